// round 1
// baseline (speedup 1.0000x reference)
#include <cuda_runtime.h>
#include <math.h>

// ---------------- problem constants ----------------
#define B_SZ   64
#define C_DIM  1536
#define N_TOK  256      // H*W = 16*16
#define HIDD   512
#define L_DIM  128
#define G_DIM  256
#define M_CL   64
#define OUT_PER_B (G_DIM + L_DIM * M_CL)   // 256 + 8192 = 8448

// -log(320), log(192)
#define NEG_LOG320 (-5.768320995793772f)
#define LOGA_LAST  (-0.510825623765991f)   // -log(320)+log(192)

// ---------------- scratch (device globals; no cudaMalloc allowed) ----------
__device__ float g_h[B_SZ * 1024 * N_TOK];   // fused hidden [b][o(1024)][n]
__device__ float g_f[B_SZ * L_DIM * N_TOK];  // cluster features
__device__ float g_s[B_SZ * M_CL * N_TOK];   // scores
__device__ float g_p[B_SZ * M_CL * N_TOK];   // matching probs

// ==========================================================================
// Kernel 1: h[b][o][n] = relu(W1cat[o][:] . x[b][:][n] + b1cat[o])
// W1cat rows 0..511 = Wc1, 512..1023 = Ws1.
// Tiled SGEMM: BM=128, BN=128, BK=16, 256 threads, 8x8 per thread.
// grid = (2 n-tiles, 8 m-tiles, 64 batches)
// ==========================================================================
__global__ __launch_bounds__(256) void k1_gemm(
    const float* __restrict__ Wc1, const float* __restrict__ bc1,
    const float* __restrict__ Ws1, const float* __restrict__ bs1,
    const float* __restrict__ x)
{
    const int b  = blockIdx.z;
    const int mt = blockIdx.y;   // 0..7
    const int nt = blockIdx.x;   // 0..1

    const float* W    = (mt < 4) ? (Wc1 + (size_t)mt * 128 * C_DIM)
                                 : (Ws1 + (size_t)(mt - 4) * 128 * C_DIM);
    const float* bias = (mt < 4) ? (bc1 + mt * 128) : (bs1 + (mt - 4) * 128);
    const float* X    = x   + (size_t)b * C_DIM * N_TOK + nt * 128;
    float*       H    = g_h + (size_t)b * 1024 * N_TOK + (size_t)mt * 128 * N_TOK + nt * 128;

    __shared__ float As[16][132];   // [k][m], padded
    __shared__ float Bs[16][128];   // [k][n]

    const int tid = threadIdx.x;
    const int tr  = tid >> 4;    // 0..15 -> rows tr*8..tr*8+7
    const int tc  = tid & 15;    // 0..15 -> cols tc*8..tc*8+7

    float acc[8][8];
#pragma unroll
    for (int i = 0; i < 8; i++)
#pragma unroll
        for (int j = 0; j < 8; j++) acc[i][j] = 0.f;

    for (int k0 = 0; k0 < C_DIM; k0 += 16) {
        // A tile: 128 rows x 16 k -> 512 float4 loads, 2 per thread (transposed store)
#pragma unroll
        for (int it = 0; it < 2; it++) {
            int idx = tid + it * 256;
            int row = idx >> 2;
            int cv  = (idx & 3) << 2;
            float4 w4 = *(const float4*)(W + (size_t)row * C_DIM + k0 + cv);
            As[cv + 0][row] = w4.x;
            As[cv + 1][row] = w4.y;
            As[cv + 2][row] = w4.z;
            As[cv + 3][row] = w4.w;
        }
        // B tile: 16 k x 128 n
#pragma unroll
        for (int it = 0; it < 2; it++) {
            int idx = tid + it * 256;
            int kr  = idx >> 5;
            int nv  = (idx & 31) << 2;
            *(float4*)(&Bs[kr][nv]) = *(const float4*)(X + (size_t)(k0 + kr) * N_TOK + nv);
        }
        __syncthreads();
#pragma unroll
        for (int kk = 0; kk < 16; kk++) {
            float a[8], bb[8];
#pragma unroll
            for (int i = 0; i < 8; i++) a[i] = As[kk][tr * 8 + i];
#pragma unroll
            for (int j = 0; j < 8; j++) bb[j] = Bs[kk][tc * 8 + j];
#pragma unroll
            for (int i = 0; i < 8; i++)
#pragma unroll
                for (int j = 0; j < 8; j++) acc[i][j] += a[i] * bb[j];
        }
        __syncthreads();
    }

#pragma unroll
    for (int i = 0; i < 8; i++) {
        float bv = bias[tr * 8 + i];
        float* Hr = H + (size_t)(tr * 8 + i) * N_TOK + tc * 8;
        float4 o0, o1;
        o0.x = fmaxf(acc[i][0] + bv, 0.f);
        o0.y = fmaxf(acc[i][1] + bv, 0.f);
        o0.z = fmaxf(acc[i][2] + bv, 0.f);
        o0.w = fmaxf(acc[i][3] + bv, 0.f);
        o1.x = fmaxf(acc[i][4] + bv, 0.f);
        o1.y = fmaxf(acc[i][5] + bv, 0.f);
        o1.z = fmaxf(acc[i][6] + bv, 0.f);
        o1.w = fmaxf(acc[i][7] + bv, 0.f);
        *(float4*)(Hr)     = o0;
        *(float4*)(Hr + 4) = o1;
    }
}

// ==========================================================================
// Kernel 2: f = Wc2 @ h[:, 0:512, :] + bc2 ;  s = Ws2 @ h[:, 512:1024, :] + bs2
// BM=64, BN=128, BK=16, 256 threads, 4x8 per thread.
// grid = (2 n-tiles, 3 m-tiles [f0,f1,s], 64 batches)
// ==========================================================================
__global__ __launch_bounds__(256) void k2_gemm(
    const float* __restrict__ Wc2, const float* __restrict__ bc2,
    const float* __restrict__ Ws2, const float* __restrict__ bs2)
{
    const int b  = blockIdx.z;
    const int mt = blockIdx.y;   // 0..2
    const int nt = blockIdx.x;   // 0..1

    const float* A; const float* bias; const float* Hb; float* O;
    if (mt < 2) {
        A    = Wc2 + (size_t)mt * 64 * HIDD;
        bias = bc2 + mt * 64;
        Hb   = g_h + (size_t)b * 1024 * N_TOK;
        O    = g_f + (size_t)b * L_DIM * N_TOK + (size_t)mt * 64 * N_TOK + nt * 128;
    } else {
        A    = Ws2;
        bias = bs2;
        Hb   = g_h + (size_t)b * 1024 * N_TOK + (size_t)512 * N_TOK;
        O    = g_s + (size_t)b * M_CL * N_TOK + nt * 128;
    }
    Hb += nt * 128;

    __shared__ float As[16][68];
    __shared__ float Bs[16][128];

    const int tid = threadIdx.x;
    const int tr  = tid >> 4;
    const int tc  = tid & 15;

    float acc[4][8];
#pragma unroll
    for (int i = 0; i < 4; i++)
#pragma unroll
        for (int j = 0; j < 8; j++) acc[i][j] = 0.f;

    for (int k0 = 0; k0 < HIDD; k0 += 16) {
        {   // A tile: 64x16 = 256 float4 -> 1 per thread
            int row = tid >> 2;
            int cv  = (tid & 3) << 2;
            float4 w4 = *(const float4*)(A + (size_t)row * HIDD + k0 + cv);
            As[cv + 0][row] = w4.x;
            As[cv + 1][row] = w4.y;
            As[cv + 2][row] = w4.z;
            As[cv + 3][row] = w4.w;
        }
#pragma unroll
        for (int it = 0; it < 2; it++) {
            int idx = tid + it * 256;
            int kr  = idx >> 5;
            int nv  = (idx & 31) << 2;
            *(float4*)(&Bs[kr][nv]) = *(const float4*)(Hb + (size_t)(k0 + kr) * N_TOK + nv);
        }
        __syncthreads();
#pragma unroll
        for (int kk = 0; kk < 16; kk++) {
            float a[4], bb[8];
#pragma unroll
            for (int i = 0; i < 4; i++) a[i] = As[kk][tr * 4 + i];
#pragma unroll
            for (int j = 0; j < 8; j++) bb[j] = Bs[kk][tc * 8 + j];
#pragma unroll
            for (int i = 0; i < 4; i++)
#pragma unroll
                for (int j = 0; j < 8; j++) acc[i][j] += a[i] * bb[j];
        }
        __syncthreads();
    }

#pragma unroll
    for (int i = 0; i < 4; i++) {
        float bv = bias[tr * 4 + i];
        float* Or = O + (size_t)(tr * 4 + i) * N_TOK + tc * 8;
        float4 o0, o1;
        o0.x = acc[i][0] + bv; o0.y = acc[i][1] + bv;
        o0.z = acc[i][2] + bv; o0.w = acc[i][3] + bv;
        o1.x = acc[i][4] + bv; o1.y = acc[i][5] + bv;
        o1.z = acc[i][6] + bv; o1.w = acc[i][7] + bv;
        *(float4*)(Or)     = o0;
        *(float4*)(Or + 4) = o1;
    }
}

// ==========================================================================
// Kernel 3: token MLP + L2 norm -> out[b][0:256]
// ==========================================================================
__global__ __launch_bounds__(256) void k3_token(
    const float* __restrict__ t,
    const float* __restrict__ Wt1, const float* __restrict__ bt1,
    const float* __restrict__ Wt2, const float* __restrict__ bt2,
    float* __restrict__ out)
{
    __shared__ float ts[C_DIM];
    __shared__ float th[HIDD];
    __shared__ float red[8];

    const int b   = blockIdx.x;
    const int tid = threadIdx.x;

    for (int i = tid; i < C_DIM; i += 256) ts[i] = t[(size_t)b * C_DIM + i];
    __syncthreads();

    for (int o = tid; o < HIDD; o += 256) {
        const float* wr = Wt1 + (size_t)o * C_DIM;
        float a0 = 0.f, a1 = 0.f, a2 = 0.f, a3 = 0.f;
        for (int c = 0; c < C_DIM; c += 4) {
            a0 += wr[c + 0] * ts[c + 0];
            a1 += wr[c + 1] * ts[c + 1];
            a2 += wr[c + 2] * ts[c + 2];
            a3 += wr[c + 3] * ts[c + 3];
        }
        th[o] = fmaxf((a0 + a1) + (a2 + a3) + bt1[o], 0.f);
    }
    __syncthreads();

    float val;
    {
        const float* wr = Wt2 + (size_t)tid * HIDD;
        float a0 = 0.f, a1 = 0.f, a2 = 0.f, a3 = 0.f;
        for (int c = 0; c < HIDD; c += 4) {
            a0 += wr[c + 0] * th[c + 0];
            a1 += wr[c + 1] * th[c + 1];
            a2 += wr[c + 2] * th[c + 2];
            a3 += wr[c + 3] * th[c + 3];
        }
        val = (a0 + a1) + (a2 + a3) + bt2[tid];
    }

    float ss = val * val;
#pragma unroll
    for (int off = 16; off; off >>= 1) ss += __shfl_xor_sync(0xffffffffu, ss, off);
    if ((tid & 31) == 0) red[tid >> 5] = ss;
    __syncthreads();
    float tot = 0.f;
#pragma unroll
    for (int i = 0; i < 8; i++) tot += red[i];
    float sc = 1.f / fmaxf(sqrtf(tot), 1e-12f);
    out[(size_t)b * OUT_PER_B + tid] = val * sc;
}

// ==========================================================================
// Kernel 4: Sinkhorn (log-domain, dustbin row, 3 iters) -> g_p = exp(log_P)
// one block per batch; Ms[65][256] in dynamic smem.
// ==========================================================================
__global__ __launch_bounds__(256) void k4_sinkhorn(const float* __restrict__ dustp)
{
    extern __shared__ float sh[];
    float* Ms = sh;                 // 65*256
    float* u  = sh + 65 * 256;      // 65
    float* v  = u + 72;             // 256

    const int b   = blockIdx.x;
    const int tid = threadIdx.x;
    const float dust = *dustp;
    const float* S = g_s + (size_t)b * M_CL * N_TOK;

    for (int i = tid; i < 64 * 256; i += 256) Ms[i] = S[i];
    {   // dustbin row + v init
        Ms[64 * 256 + tid] = dust;
        v[tid] = 0.f;
    }
    __syncthreads();

    const int w    = tid >> 5;
    const int lane = tid & 31;

    for (int it = 0; it < 3; it++) {
        // u[r] = log_a[r] - LSE_n(Ms[r][n] + v[n]);  warp per row
        for (int r = w; r < 65; r += 8) {
            float vals[8];
            float mx = -INFINITY;
#pragma unroll
            for (int q = 0; q < 8; q++) {
                float vv = Ms[r * 256 + lane + 32 * q] + v[lane + 32 * q];
                vals[q] = vv;
                mx = fmaxf(mx, vv);
            }
#pragma unroll
            for (int off = 16; off; off >>= 1)
                mx = fmaxf(mx, __shfl_xor_sync(0xffffffffu, mx, off));
            float ssum = 0.f;
#pragma unroll
            for (int q = 0; q < 8; q++) ssum += expf(vals[q] - mx);
#pragma unroll
            for (int off = 16; off; off >>= 1)
                ssum += __shfl_xor_sync(0xffffffffu, ssum, off);
            if (lane == 0) {
                float la = (r == 64) ? LOGA_LAST : NEG_LOG320;
                u[r] = la - (mx + logf(ssum));
            }
        }
        __syncthreads();
        // v[j] = log_b - LSE_m(Ms[m][j] + u[m]);  thread per column (online LSE)
        {
            float mrun = -INFINITY, srun = 0.f;
            for (int m = 0; m < 65; m++) {
                float vv = Ms[m * 256 + tid] + u[m];
                if (vv > mrun) {
                    srun = srun * expf(mrun - vv) + 1.f;
                    mrun = vv;
                } else {
                    srun += expf(vv - mrun);
                }
            }
            v[tid] = NEG_LOG320 - (mrun + logf(srun));
        }
        __syncthreads();
    }

    float* P = g_p + (size_t)b * M_CL * N_TOK;
    for (int i = tid; i < 64 * 256; i += 256) {
        int m = i >> 8, j = i & 255;
        P[i] = expf(Ms[i] + u[m] + v[j] - NEG_LOG320);
    }
}

// ==========================================================================
// Kernel 5: vlad[b][l][m] = sum_n f[b][l][n]*p[b][m][n]; intra-norm over l;
// write to out[b][256 + l*64 + m]. One block per batch.
// ==========================================================================
#define PS_LD 260   // 256 + 4 pad (keeps float4 alignment, kills bank conflicts)
__global__ __launch_bounds__(256) void k5_vlad(float* __restrict__ out)
{
    extern __shared__ float sh[];
    float* ps  = sh;                       // [64][PS_LD]
    float* vs  = sh + 64 * PS_LD;          // [128][64]
    float* inv = vs + 128 * 64;            // [64]

    const int b   = blockIdx.x;
    const int tid = threadIdx.x;
    const float* P = g_p + (size_t)b * M_CL * N_TOK;
    const float* F = g_f + (size_t)b * L_DIM * N_TOK;

    for (int i = tid; i < 64 * 256; i += 256) {
        int m = i >> 8, n = i & 255;
        ps[m * PS_LD + n] = P[i];
    }
    __syncthreads();

    const int m  = tid & 63;
    const int lg = tid >> 6;   // 0..3, handles l = lg*32 .. lg*32+31

    const float4* pr = (const float4*)(ps + m * PS_LD);

    float acc[32];
#pragma unroll
    for (int i = 0; i < 32; i++) acc[i] = 0.f;

    for (int nc = 0; nc < 64; nc += 4) {   // 16 n per chunk
        float4 pv0 = pr[nc + 0], pv1 = pr[nc + 1], pv2 = pr[nc + 2], pv3 = pr[nc + 3];
#pragma unroll
        for (int li = 0; li < 32; li++) {
            const float4* fr = (const float4*)(F + (size_t)(lg * 32 + li) * N_TOK);
            float4 f0 = fr[nc + 0], f1 = fr[nc + 1], f2 = fr[nc + 2], f3 = fr[nc + 3];
            float a = acc[li];
            a += f0.x * pv0.x + f0.y * pv0.y + f0.z * pv0.z + f0.w * pv0.w;
            a += f1.x * pv1.x + f1.y * pv1.y + f1.z * pv1.z + f1.w * pv1.w;
            a += f2.x * pv2.x + f2.y * pv2.y + f2.z * pv2.z + f2.w * pv2.w;
            a += f3.x * pv3.x + f3.y * pv3.y + f3.z * pv3.z + f3.w * pv3.w;
            acc[li] = a;
        }
    }
#pragma unroll
    for (int li = 0; li < 32; li++) vs[(lg * 32 + li) * 64 + m] = acc[li];
    __syncthreads();

    if (tid < 64) {
        float ss = 0.f;
        for (int l = 0; l < 128; l++) {
            float vv = vs[l * 64 + tid];
            ss += vv * vv;
        }
        inv[tid] = 1.f / fmaxf(sqrtf(ss), 1e-12f);
    }
    __syncthreads();

    float* Ob = out + (size_t)b * OUT_PER_B + G_DIM;
    for (int i = tid; i < L_DIM * M_CL; i += 256) Ob[i] = vs[i] * inv[i & 63];
}

// ==========================================================================
// Kernel 6: final whole-vector L2 norm per batch row.
// ==========================================================================
__global__ __launch_bounds__(256) void k6_norm(float* __restrict__ out)
{
    __shared__ float red[8];
    __shared__ float sc_s;
    const int b   = blockIdx.x;
    const int tid = threadIdx.x;
    float* O = out + (size_t)b * OUT_PER_B;

    float ss = 0.f;
    for (int i = tid; i < OUT_PER_B; i += 256) {
        float vv = O[i];
        ss += vv * vv;
    }
#pragma unroll
    for (int off = 16; off; off >>= 1) ss += __shfl_xor_sync(0xffffffffu, ss, off);
    if ((tid & 31) == 0) red[tid >> 5] = ss;
    __syncthreads();
    if (tid == 0) {
        float tot = 0.f;
#pragma unroll
        for (int i = 0; i < 8; i++) tot += red[i];
        sc_s = 1.f / fmaxf(sqrtf(tot), 1e-12f);
    }
    __syncthreads();
    float sc = sc_s;
    for (int i = tid; i < OUT_PER_B; i += 256) O[i] *= sc;
}

// ==========================================================================
// launch
// ==========================================================================
extern "C" void kernel_launch(void* const* d_in, const int* in_sizes, int n_in,
                              void* d_out, int out_size)
{
    (void)in_sizes; (void)n_in; (void)out_size;
    const float* x    = (const float*)d_in[0];
    const float* t    = (const float*)d_in[1];
    const float* Wt1  = (const float*)d_in[2];
    const float* bt1  = (const float*)d_in[3];
    const float* Wt2  = (const float*)d_in[4];
    const float* bt2  = (const float*)d_in[5];
    const float* Wc1  = (const float*)d_in[6];
    const float* bc1  = (const float*)d_in[7];
    const float* Wc2  = (const float*)d_in[8];
    const float* bc2  = (const float*)d_in[9];
    const float* Ws1  = (const float*)d_in[10];
    const float* bs1  = (const float*)d_in[11];
    const float* Ws2  = (const float*)d_in[12];
    const float* bs2  = (const float*)d_in[13];
    const float* dust = (const float*)d_in[14];
    float* out = (float*)d_out;

    const int sink_smem = (65 * 256 + 72 + 256) * (int)sizeof(float);
    const int vlad_smem = (64 * PS_LD + 128 * 64 + 64) * (int)sizeof(float);
    cudaFuncSetAttribute(k4_sinkhorn, cudaFuncAttributeMaxDynamicSharedMemorySize, sink_smem);
    cudaFuncSetAttribute(k5_vlad,     cudaFuncAttributeMaxDynamicSharedMemorySize, vlad_smem);

    k1_gemm<<<dim3(2, 8, B_SZ), 256>>>(Wc1, bc1, Ws1, bs1, x);
    k2_gemm<<<dim3(2, 3, B_SZ), 256>>>(Wc2, bc2, Ws2, bs2);
    k3_token<<<B_SZ, 256>>>(t, Wt1, bt1, Wt2, bt2, out);
    k4_sinkhorn<<<B_SZ, 256, sink_smem>>>(dust);
    k5_vlad<<<B_SZ, 256, vlad_smem>>>(out);
    k6_norm<<<B_SZ, 256>>>(out);
}

// round 2
// speedup vs baseline: 1.9756x; 1.9756x over previous
#include <cuda_runtime.h>
#include <math.h>
#include <stdint.h>

// ---------------- problem constants ----------------
#define B_SZ   64
#define C_DIM  1536
#define N_TOK  256      // H*W = 16*16
#define HIDD   512
#define L_DIM  128
#define G_DIM  256
#define M_CL   64
#define OUT_PER_B (G_DIM + L_DIM * M_CL)   // 8448

#define NEG_LOG320 (-5.768320995793772f)
#define LOGA_LAST  (-0.510825623765991f)

// ---------------- scratch ----------------
__device__ float g_h[B_SZ * 1024 * N_TOK];
__device__ float g_f[B_SZ * L_DIM * N_TOK];
__device__ float g_s[B_SZ * M_CL * N_TOK];
__device__ float g_p[B_SZ * M_CL * N_TOK];

// ---------------- helpers ----------------
#define CP_ASYNC16(smem_u32, gptr) \
    asm volatile("cp.async.cg.shared.global [%0], [%1], 16;" :: "r"(smem_u32), "l"(gptr))
#define CP_COMMIT() asm volatile("cp.async.commit_group;")
#define CP_WAIT1()  asm volatile("cp.async.wait_group 1;")

__device__ __forceinline__ uint32_t tf32u(float f) {
    uint32_t u;
    asm("cvt.rna.tf32.f32 %0, %1;" : "=r"(u) : "f"(f));
    return u;
}

__device__ __forceinline__ void mma_tf32(float* d, const uint32_t* a, const uint32_t* b) {
    asm volatile(
        "mma.sync.aligned.m16n8k8.row.col.f32.tf32.tf32.f32 "
        "{%0,%1,%2,%3}, {%4,%5,%6,%7}, {%8,%9}, {%0,%1,%2,%3};"
        : "+f"(d[0]), "+f"(d[1]), "+f"(d[2]), "+f"(d[3])
        : "r"(a[0]), "r"(a[1]), "r"(a[2]), "r"(a[3]), "r"(b[0]), "r"(b[1]));
}

// ==========================================================================
// Kernel 1 (tensor core): h = relu(W1cat @ x + b1cat)
// BM=128, BN=128, BK=32. 256 thr = 8 warps (4 M x 2 N), warp tile 32x64.
// A smem [128][36] (stride 36 -> conflict-free frags), B smem [32][136].
// 2-stage cp.async pipeline. grid = (2, 8, 64).
// ==========================================================================
#define K1_AS_STRIDE 36
#define K1_BS_STRIDE 136
#define K1_AS_ELEMS (128 * K1_AS_STRIDE)       // per stage
#define K1_BS_ELEMS (32 * K1_BS_STRIDE)
#define K1_SMEM_FLOATS (2 * K1_AS_ELEMS + 2 * K1_BS_ELEMS)

__global__ __launch_bounds__(256) void k1_mma(
    const float* __restrict__ Wc1, const float* __restrict__ bc1,
    const float* __restrict__ Ws1, const float* __restrict__ bs1,
    const float* __restrict__ x)
{
    extern __shared__ float sm[];
    float* As = sm;                       // [2][128][36]
    float* Bs = sm + 2 * K1_AS_ELEMS;     // [2][32][136]

    const int b  = blockIdx.z;
    const int mt = blockIdx.y;   // 0..7
    const int nt = blockIdx.x;   // 0..1

    const float* W    = (mt < 4) ? (Wc1 + (size_t)mt * 128 * C_DIM)
                                 : (Ws1 + (size_t)(mt - 4) * 128 * C_DIM);
    const float* bias = (mt < 4) ? (bc1 + mt * 128) : (bs1 + (mt - 4) * 128);
    const float* X    = x + (size_t)b * C_DIM * N_TOK + nt * 128;
    float*       H    = g_h + ((size_t)b * 1024 + (size_t)mt * 128) * N_TOK + nt * 128;

    const int tid  = threadIdx.x;
    const int warp = tid >> 5, lane = tid & 31;
    const int g = lane >> 2, t = lane & 3;
    const int wm = warp >> 1, wn = warp & 1;   // 4 x 2 warp grid

    const uint32_t As_u = (uint32_t)__cvta_generic_to_shared(As);
    const uint32_t Bs_u = (uint32_t)__cvta_generic_to_shared(Bs);

    float acc[2][8][4];
#pragma unroll
    for (int i = 0; i < 2; i++)
#pragma unroll
        for (int j = 0; j < 8; j++)
#pragma unroll
            for (int q = 0; q < 4; q++) acc[i][j][q] = 0.f;

    // A: 128 rows x 8 float4 = 1024 -> 4/thread. B: 32 rows x 32 float4 -> 4/thread.
    const int a_row = tid >> 3,  a_c4 = (tid & 7);     // + it*32 rows
    const int b_row = tid >> 5,  b_c4 = (tid & 31);    // + it*8 rows

#define K1_LOAD_STAGE(buf, kt)                                                      \
    do {                                                                            \
        const int k0_ = (kt) * 32;                                                  \
        _Pragma("unroll")                                                           \
        for (int it = 0; it < 4; it++) {                                            \
            int row = a_row + it * 32;                                              \
            uint32_t sa = As_u + (((buf) * 128 + row) * K1_AS_STRIDE + a_c4 * 4) * 4; \
            CP_ASYNC16(sa, W + (size_t)row * C_DIM + k0_ + a_c4 * 4);               \
        }                                                                           \
        _Pragma("unroll")                                                           \
        for (int it = 0; it < 4; it++) {                                            \
            int row = b_row + it * 8;                                               \
            uint32_t sb = Bs_u + (((buf) * 32 + row) * K1_BS_STRIDE + b_c4 * 4) * 4; \
            CP_ASYNC16(sb, X + (size_t)(k0_ + row) * N_TOK + b_c4 * 4);             \
        }                                                                           \
    } while (0)

    const int KT = C_DIM / 32;   // 48
    K1_LOAD_STAGE(0, 0);
    CP_COMMIT();

    for (int kt = 0; kt < KT; kt++) {
        if (kt + 1 < KT) K1_LOAD_STAGE((kt + 1) & 1, kt + 1);
        CP_COMMIT();
        CP_WAIT1();
        __syncthreads();

        const float* Ab = As + (kt & 1) * K1_AS_ELEMS;
        const float* Bb = Bs + (kt & 1) * K1_BS_ELEMS;

#pragma unroll
        for (int kk = 0; kk < 4; kk++) {
            uint32_t afr[2][4];
#pragma unroll
            for (int mi = 0; mi < 2; mi++) {
                int mr = wm * 32 + mi * 16 + g;
                afr[mi][0] = tf32u(Ab[(size_t)mr * K1_AS_STRIDE + kk * 8 + t]);
                afr[mi][1] = tf32u(Ab[(size_t)(mr + 8) * K1_AS_STRIDE + kk * 8 + t]);
                afr[mi][2] = tf32u(Ab[(size_t)mr * K1_AS_STRIDE + kk * 8 + t + 4]);
                afr[mi][3] = tf32u(Ab[(size_t)(mr + 8) * K1_AS_STRIDE + kk * 8 + t + 4]);
            }
            uint32_t bfr[8][2];
#pragma unroll
            for (int ni = 0; ni < 8; ni++) {
                int col = wn * 64 + ni * 8 + g;
                bfr[ni][0] = tf32u(Bb[(size_t)(kk * 8 + t) * K1_BS_STRIDE + col]);
                bfr[ni][1] = tf32u(Bb[(size_t)(kk * 8 + t + 4) * K1_BS_STRIDE + col]);
            }
#pragma unroll
            for (int mi = 0; mi < 2; mi++)
#pragma unroll
                for (int ni = 0; ni < 8; ni++)
                    mma_tf32(acc[mi][ni], afr[mi], bfr[ni]);
        }
        __syncthreads();
    }

    // epilogue: bias + relu, float2 stores
#pragma unroll
    for (int mi = 0; mi < 2; mi++) {
#pragma unroll
        for (int q2 = 0; q2 < 2; q2++) {
            int row = wm * 32 + mi * 16 + q2 * 8 + g;
            float bv = __ldg(bias + row);
#pragma unroll
            for (int ni = 0; ni < 8; ni++) {
                int col = wn * 64 + ni * 8 + t * 2;
                float2 v;
                v.x = fmaxf(acc[mi][ni][q2 * 2 + 0] + bv, 0.f);
                v.y = fmaxf(acc[mi][ni][q2 * 2 + 1] + bv, 0.f);
                *(float2*)(H + (size_t)row * N_TOK + col) = v;
            }
        }
    }
}

// ==========================================================================
// Kernel 2 (tensor core): f = Wc2 @ h[:,0:512] + bc2 ; s = Ws2 @ h[:,512:] + bs2
// BM=64, BN=128, BK=32. 8 warps (2 M x 4 N), warp tile 32x32. grid (2,3,64).
// ==========================================================================
#define K2_AS_ELEMS (64 * K1_AS_STRIDE)
#define K2_SMEM_FLOATS (2 * K2_AS_ELEMS + 2 * K1_BS_ELEMS)

__global__ __launch_bounds__(256) void k2_mma(
    const float* __restrict__ Wc2, const float* __restrict__ bc2,
    const float* __restrict__ Ws2, const float* __restrict__ bs2)
{
    extern __shared__ float sm[];
    float* As = sm;                       // [2][64][36]
    float* Bs = sm + 2 * K2_AS_ELEMS;     // [2][32][136]

    const int b  = blockIdx.z;
    const int mt = blockIdx.y;   // 0,1 -> f ; 2 -> s
    const int nt = blockIdx.x;

    const float* A; const float* bias; const float* Hb; float* O;
    if (mt < 2) {
        A    = Wc2 + (size_t)mt * 64 * HIDD;
        bias = bc2 + mt * 64;
        Hb   = g_h + (size_t)b * 1024 * N_TOK;
        O    = g_f + (size_t)b * L_DIM * N_TOK + (size_t)mt * 64 * N_TOK + nt * 128;
    } else {
        A    = Ws2;
        bias = bs2;
        Hb   = g_h + ((size_t)b * 1024 + 512) * N_TOK;
        O    = g_s + (size_t)b * M_CL * N_TOK + nt * 128;
    }
    Hb += nt * 128;

    const int tid  = threadIdx.x;
    const int warp = tid >> 5, lane = tid & 31;
    const int g = lane >> 2, t = lane & 3;
    const int wm = warp >> 2, wn = warp & 3;   // 2 x 4 warp grid

    const uint32_t As_u = (uint32_t)__cvta_generic_to_shared(As);
    const uint32_t Bs_u = (uint32_t)__cvta_generic_to_shared(Bs);

    float acc[2][4][4];
#pragma unroll
    for (int i = 0; i < 2; i++)
#pragma unroll
        for (int j = 0; j < 4; j++)
#pragma unroll
            for (int q = 0; q < 4; q++) acc[i][j][q] = 0.f;

    const int a_row = tid >> 3,  a_c4 = (tid & 7);   // + it*32, 2 iters
    const int b_row = tid >> 5,  b_c4 = (tid & 31);  // + it*8, 4 iters

#define K2_LOAD_STAGE(buf, kt)                                                      \
    do {                                                                            \
        const int k0_ = (kt) * 32;                                                  \
        _Pragma("unroll")                                                           \
        for (int it = 0; it < 2; it++) {                                            \
            int row = a_row + it * 32;                                              \
            uint32_t sa = As_u + (((buf) * 64 + row) * K1_AS_STRIDE + a_c4 * 4) * 4; \
            CP_ASYNC16(sa, A + (size_t)row * HIDD + k0_ + a_c4 * 4);                \
        }                                                                           \
        _Pragma("unroll")                                                           \
        for (int it = 0; it < 4; it++) {                                            \
            int row = b_row + it * 8;                                               \
            uint32_t sb = Bs_u + (((buf) * 32 + row) * K1_BS_STRIDE + b_c4 * 4) * 4; \
            CP_ASYNC16(sb, Hb + (size_t)(k0_ + row) * N_TOK + b_c4 * 4);            \
        }                                                                           \
    } while (0)

    const int KT = HIDD / 32;   // 16
    K2_LOAD_STAGE(0, 0);
    CP_COMMIT();

    for (int kt = 0; kt < KT; kt++) {
        if (kt + 1 < KT) K2_LOAD_STAGE((kt + 1) & 1, kt + 1);
        CP_COMMIT();
        CP_WAIT1();
        __syncthreads();

        const float* Ab = As + (kt & 1) * K2_AS_ELEMS;
        const float* Bb = Bs + (kt & 1) * K1_BS_ELEMS;

#pragma unroll
        for (int kk = 0; kk < 4; kk++) {
            uint32_t afr[2][4];
#pragma unroll
            for (int mi = 0; mi < 2; mi++) {
                int mr = wm * 32 + mi * 16 + g;
                afr[mi][0] = tf32u(Ab[(size_t)mr * K1_AS_STRIDE + kk * 8 + t]);
                afr[mi][1] = tf32u(Ab[(size_t)(mr + 8) * K1_AS_STRIDE + kk * 8 + t]);
                afr[mi][2] = tf32u(Ab[(size_t)mr * K1_AS_STRIDE + kk * 8 + t + 4]);
                afr[mi][3] = tf32u(Ab[(size_t)(mr + 8) * K1_AS_STRIDE + kk * 8 + t + 4]);
            }
            uint32_t bfr[4][2];
#pragma unroll
            for (int ni = 0; ni < 4; ni++) {
                int col = wn * 32 + ni * 8 + g;
                bfr[ni][0] = tf32u(Bb[(size_t)(kk * 8 + t) * K1_BS_STRIDE + col]);
                bfr[ni][1] = tf32u(Bb[(size_t)(kk * 8 + t + 4) * K1_BS_STRIDE + col]);
            }
#pragma unroll
            for (int mi = 0; mi < 2; mi++)
#pragma unroll
                for (int ni = 0; ni < 4; ni++)
                    mma_tf32(acc[mi][ni], afr[mi], bfr[ni]);
        }
        __syncthreads();
    }

#pragma unroll
    for (int mi = 0; mi < 2; mi++) {
#pragma unroll
        for (int q2 = 0; q2 < 2; q2++) {
            int row = wm * 32 + mi * 16 + q2 * 8 + g;
            float bv = __ldg(bias + row);
#pragma unroll
            for (int ni = 0; ni < 4; ni++) {
                int col = wn * 32 + ni * 8 + t * 2;
                float2 v;
                v.x = acc[mi][ni][q2 * 2 + 0] + bv;
                v.y = acc[mi][ni][q2 * 2 + 1] + bv;
                *(float2*)(O + (size_t)row * N_TOK + col) = v;
            }
        }
    }
}

// ==========================================================================
// Kernel 3: token MLP + L2 norm -> out[b][0:256]
// ==========================================================================
__global__ __launch_bounds__(256) void k3_token(
    const float* __restrict__ t,
    const float* __restrict__ Wt1, const float* __restrict__ bt1,
    const float* __restrict__ Wt2, const float* __restrict__ bt2,
    float* __restrict__ out)
{
    __shared__ float ts[C_DIM];
    __shared__ float th[HIDD];
    __shared__ float red[8];

    const int b   = blockIdx.x;
    const int tid = threadIdx.x;

    for (int i = tid; i < C_DIM; i += 256) ts[i] = t[(size_t)b * C_DIM + i];
    __syncthreads();

    for (int o = tid; o < HIDD; o += 256) {
        const float* wr = Wt1 + (size_t)o * C_DIM;
        float a0 = 0.f, a1 = 0.f, a2 = 0.f, a3 = 0.f;
        for (int c = 0; c < C_DIM; c += 4) {
            a0 += wr[c + 0] * ts[c + 0];
            a1 += wr[c + 1] * ts[c + 1];
            a2 += wr[c + 2] * ts[c + 2];
            a3 += wr[c + 3] * ts[c + 3];
        }
        th[o] = fmaxf((a0 + a1) + (a2 + a3) + bt1[o], 0.f);
    }
    __syncthreads();

    float val;
    {
        const float* wr = Wt2 + (size_t)tid * HIDD;
        float a0 = 0.f, a1 = 0.f, a2 = 0.f, a3 = 0.f;
        for (int c = 0; c < HIDD; c += 4) {
            a0 += wr[c + 0] * th[c + 0];
            a1 += wr[c + 1] * th[c + 1];
            a2 += wr[c + 2] * th[c + 2];
            a3 += wr[c + 3] * th[c + 3];
        }
        val = (a0 + a1) + (a2 + a3) + bt2[tid];
    }

    float ss = val * val;
#pragma unroll
    for (int off = 16; off; off >>= 1) ss += __shfl_xor_sync(0xffffffffu, ss, off);
    if ((tid & 31) == 0) red[tid >> 5] = ss;
    __syncthreads();
    float tot = 0.f;
#pragma unroll
    for (int i = 0; i < 8; i++) tot += red[i];
    float sc = 1.f / fmaxf(sqrtf(tot), 1e-12f);
    out[(size_t)b * OUT_PER_B + tid] = val * sc;
}

// ==========================================================================
// Kernel 4: Sinkhorn -> g_p
// ==========================================================================
__global__ __launch_bounds__(256) void k4_sinkhorn(const float* __restrict__ dustp)
{
    extern __shared__ float sh[];
    float* Ms = sh;
    float* u  = sh + 65 * 256;
    float* v  = u + 72;

    const int b   = blockIdx.x;
    const int tid = threadIdx.x;
    const float dust = *dustp;
    const float* S = g_s + (size_t)b * M_CL * N_TOK;

    for (int i = tid; i < 64 * 256; i += 256) Ms[i] = S[i];
    Ms[64 * 256 + tid] = dust;
    v[tid] = 0.f;
    __syncthreads();

    const int w    = tid >> 5;
    const int lane = tid & 31;

    for (int it = 0; it < 3; it++) {
        for (int r = w; r < 65; r += 8) {
            float vals[8];
            float mx = -INFINITY;
#pragma unroll
            for (int q = 0; q < 8; q++) {
                float vv = Ms[r * 256 + lane + 32 * q] + v[lane + 32 * q];
                vals[q] = vv;
                mx = fmaxf(mx, vv);
            }
#pragma unroll
            for (int off = 16; off; off >>= 1)
                mx = fmaxf(mx, __shfl_xor_sync(0xffffffffu, mx, off));
            float ssum = 0.f;
#pragma unroll
            for (int q = 0; q < 8; q++) ssum += expf(vals[q] - mx);
#pragma unroll
            for (int off = 16; off; off >>= 1)
                ssum += __shfl_xor_sync(0xffffffffu, ssum, off);
            if (lane == 0) {
                float la = (r == 64) ? LOGA_LAST : NEG_LOG320;
                u[r] = la - (mx + logf(ssum));
            }
        }
        __syncthreads();
        {
            float mrun = -INFINITY, srun = 0.f;
            for (int m = 0; m < 65; m++) {
                float vv = Ms[m * 256 + tid] + u[m];
                if (vv > mrun) {
                    srun = srun * expf(mrun - vv) + 1.f;
                    mrun = vv;
                } else {
                    srun += expf(vv - mrun);
                }
            }
            v[tid] = NEG_LOG320 - (mrun + logf(srun));
        }
        __syncthreads();
    }

    float* P = g_p + (size_t)b * M_CL * N_TOK;
    for (int i = tid; i < 64 * 256; i += 256) {
        int m = i >> 8, j = i & 255;
        P[i] = expf(Ms[i] + u[m] + v[j] - NEG_LOG320);
    }
}

// ==========================================================================
// Kernel 5: VLAD + intra-norm
// ==========================================================================
#define PS_LD 260
__global__ __launch_bounds__(256) void k5_vlad(float* __restrict__ out)
{
    extern __shared__ float sh[];
    float* ps  = sh;
    float* vs  = sh + 64 * PS_LD;
    float* inv = vs + 128 * 64;

    const int b   = blockIdx.x;
    const int tid = threadIdx.x;
    const float* P = g_p + (size_t)b * M_CL * N_TOK;
    const float* F = g_f + (size_t)b * L_DIM * N_TOK;

    for (int i = tid; i < 64 * 256; i += 256) {
        int m = i >> 8, n = i & 255;
        ps[m * PS_LD + n] = P[i];
    }
    __syncthreads();

    const int m  = tid & 63;
    const int lg = tid >> 6;

    const float4* pr = (const float4*)(ps + m * PS_LD);

    float acc[32];
#pragma unroll
    for (int i = 0; i < 32; i++) acc[i] = 0.f;

    for (int nc = 0; nc < 64; nc += 4) {
        float4 pv0 = pr[nc + 0], pv1 = pr[nc + 1], pv2 = pr[nc + 2], pv3 = pr[nc + 3];
#pragma unroll
        for (int li = 0; li < 32; li++) {
            const float4* fr = (const float4*)(F + (size_t)(lg * 32 + li) * N_TOK);
            float4 f0 = fr[nc + 0], f1 = fr[nc + 1], f2 = fr[nc + 2], f3 = fr[nc + 3];
            float a = acc[li];
            a += f0.x * pv0.x + f0.y * pv0.y + f0.z * pv0.z + f0.w * pv0.w;
            a += f1.x * pv1.x + f1.y * pv1.y + f1.z * pv1.z + f1.w * pv1.w;
            a += f2.x * pv2.x + f2.y * pv2.y + f2.z * pv2.z + f2.w * pv2.w;
            a += f3.x * pv3.x + f3.y * pv3.y + f3.z * pv3.z + f3.w * pv3.w;
            acc[li] = a;
        }
    }
#pragma unroll
    for (int li = 0; li < 32; li++) vs[(lg * 32 + li) * 64 + m] = acc[li];
    __syncthreads();

    if (tid < 64) {
        float ss = 0.f;
        for (int l = 0; l < 128; l++) {
            float vv = vs[l * 64 + tid];
            ss += vv * vv;
        }
        inv[tid] = 1.f / fmaxf(sqrtf(ss), 1e-12f);
    }
    __syncthreads();

    float* Ob = out + (size_t)b * OUT_PER_B + G_DIM;
    for (int i = tid; i < L_DIM * M_CL; i += 256) Ob[i] = vs[i] * inv[i & 63];
}

// ==========================================================================
// Kernel 6: final L2 norm
// ==========================================================================
__global__ __launch_bounds__(256) void k6_norm(float* __restrict__ out)
{
    __shared__ float red[8];
    __shared__ float sc_s;
    const int b   = blockIdx.x;
    const int tid = threadIdx.x;
    float* O = out + (size_t)b * OUT_PER_B;

    float ss = 0.f;
    for (int i = tid; i < OUT_PER_B; i += 256) {
        float vv = O[i];
        ss += vv * vv;
    }
#pragma unroll
    for (int off = 16; off; off >>= 1) ss += __shfl_xor_sync(0xffffffffu, ss, off);
    if ((tid & 31) == 0) red[tid >> 5] = ss;
    __syncthreads();
    if (tid == 0) {
        float tot = 0.f;
#pragma unroll
        for (int i = 0; i < 8; i++) tot += red[i];
        sc_s = 1.f / fmaxf(sqrtf(tot), 1e-12f);
    }
    __syncthreads();
    float sc = sc_s;
    for (int i = tid; i < OUT_PER_B; i += 256) O[i] *= sc;
}

// ==========================================================================
// launch
// ==========================================================================
extern "C" void kernel_launch(void* const* d_in, const int* in_sizes, int n_in,
                              void* d_out, int out_size)
{
    (void)in_sizes; (void)n_in; (void)out_size;
    const float* x    = (const float*)d_in[0];
    const float* t    = (const float*)d_in[1];
    const float* Wt1  = (const float*)d_in[2];
    const float* bt1  = (const float*)d_in[3];
    const float* Wt2  = (const float*)d_in[4];
    const float* bt2  = (const float*)d_in[5];
    const float* Wc1  = (const float*)d_in[6];
    const float* bc1  = (const float*)d_in[7];
    const float* Wc2  = (const float*)d_in[8];
    const float* bc2  = (const float*)d_in[9];
    const float* Ws1  = (const float*)d_in[10];
    const float* bs1  = (const float*)d_in[11];
    const float* Ws2  = (const float*)d_in[12];
    const float* bs2  = (const float*)d_in[13];
    const float* dust = (const float*)d_in[14];
    float* out = (float*)d_out;

    const int k1_smem = K1_SMEM_FLOATS * (int)sizeof(float);   // ~71.7 KB
    const int k2_smem = K2_SMEM_FLOATS * (int)sizeof(float);   // ~53.2 KB
    const int sink_smem = (65 * 256 + 72 + 256) * (int)sizeof(float);
    const int vlad_smem = (64 * PS_LD + 128 * 64 + 64) * (int)sizeof(float);
    cudaFuncSetAttribute(k1_mma,      cudaFuncAttributeMaxDynamicSharedMemorySize, k1_smem);
    cudaFuncSetAttribute(k2_mma,      cudaFuncAttributeMaxDynamicSharedMemorySize, k2_smem);
    cudaFuncSetAttribute(k4_sinkhorn, cudaFuncAttributeMaxDynamicSharedMemorySize, sink_smem);
    cudaFuncSetAttribute(k5_vlad,     cudaFuncAttributeMaxDynamicSharedMemorySize, vlad_smem);

    k1_mma<<<dim3(2, 8, B_SZ), 256, k1_smem>>>(Wc1, bc1, Ws1, bs1, x);
    k2_mma<<<dim3(2, 3, B_SZ), 256, k2_smem>>>(Wc2, bc2, Ws2, bs2);
    k3_token<<<B_SZ, 256>>>(t, Wt1, bt1, Wt2, bt2, out);
    k4_sinkhorn<<<B_SZ, 256, sink_smem>>>(dust);
    k5_vlad<<<B_SZ, 256, vlad_smem>>>(out);
    k6_norm<<<B_SZ, 256>>>(out);
}

// round 3
// speedup vs baseline: 2.0205x; 1.0227x over previous
#include <cuda_runtime.h>
#include <math.h>
#include <stdint.h>

// ---------------- problem constants ----------------
#define B_SZ   64
#define C_DIM  1536
#define N_TOK  256
#define HIDD   512
#define L_DIM  128
#define G_DIM  256
#define M_CL   64
#define OUT_PER_B (G_DIM + L_DIM * M_CL)   // 8448

#define NEG_LOG320 (-5.768320995793772f)
#define LOGA_LAST  (-0.510825623765991f)

// ---------------- scratch ----------------
__device__ float g_xt[B_SZ * N_TOK * C_DIM];   // x transposed, tf32-rounded: [b][n][k]
__device__ float g_ht[B_SZ * N_TOK * 1024];    // hidden transposed, tf32-rounded: [b][n][o]
__device__ float g_w1[1024 * C_DIM];           // [Wc1;Ws1] tf32-rounded
__device__ float g_w2[256 * HIDD];             // rows 0-127 Wc2, 128-191 Ws2, 192-255 zero
__device__ float g_f[B_SZ * L_DIM * N_TOK];
__device__ float g_s[B_SZ * M_CL * N_TOK];
__device__ float g_p[B_SZ * M_CL * N_TOK];

// ---------------- helpers ----------------
#define CP_ASYNC16(smem_u32, gptr) \
    asm volatile("cp.async.cg.shared.global [%0], [%1], 16;" :: "r"(smem_u32), "l"(gptr))
#define CP_COMMIT() asm volatile("cp.async.commit_group;")
#define CP_WAIT1()  asm volatile("cp.async.wait_group 1;")

__device__ __forceinline__ float tf32r(float f) {
    uint32_t u;
    asm("cvt.rna.tf32.f32 %0, %1;" : "=r"(u) : "f"(f));
    return __uint_as_float(u);
}

__device__ __forceinline__ void ldsm_x4(uint32_t& r0, uint32_t& r1, uint32_t& r2, uint32_t& r3,
                                        uint32_t addr) {
    asm volatile("ldmatrix.sync.aligned.m8n8.x4.shared.b16 {%0,%1,%2,%3}, [%4];"
        : "=r"(r0), "=r"(r1), "=r"(r2), "=r"(r3) : "r"(addr));
}

__device__ __forceinline__ void mma_tf32(float* d, const uint32_t* a, const uint32_t* b) {
    asm volatile(
        "mma.sync.aligned.m16n8k8.row.col.f32.tf32.tf32.f32 "
        "{%0,%1,%2,%3}, {%4,%5,%6,%7}, {%8,%9}, {%0,%1,%2,%3};"
        : "+f"(d[0]), "+f"(d[1]), "+f"(d[2]), "+f"(d[3])
        : "r"(a[0]), "r"(a[1]), "r"(a[2]), "r"(a[3]), "r"(b[0]), "r"(b[1]));
}

// smem tile geometry (shared by k1/k2): rows of 32 fp32 + pad 4 -> stride 36 floats (144B)
#define TS        36
#define ROW_BYTES 144
#define STAGE_BYTES (128 * ROW_BYTES)              // 18432 per operand per stage
#define GEMM_SMEM  (4 * STAGE_BYTES)               // A(2 stages) + B(2 stages) = 73728 B

// ==========================================================================
// Prepass A: weights -> tf32-rounded device copies
// ==========================================================================
__global__ __launch_bounds__(256) void p_weights(
    const float* __restrict__ Wc1, const float* __restrict__ Ws1,
    const float* __restrict__ Wc2, const float* __restrict__ Ws2)
{
    const int total1 = 1024 * C_DIM;
    const int total2 = 256 * HIDD;
    for (int idx = blockIdx.x * 256 + threadIdx.x; idx < total1 + total2;
         idx += gridDim.x * 256) {
        if (idx < total1) {
            float v = (idx < 512 * C_DIM) ? Wc1[idx] : Ws1[idx - 512 * C_DIM];
            g_w1[idx] = tf32r(v);
        } else {
            int j = idx - total1;
            int row = j / HIDD;
            float v = (row < 128) ? Wc2[j]
                    : (row < 192) ? Ws2[j - 128 * HIDD] : 0.f;
            g_w2[j] = tf32r(v);
        }
    }
}

// ==========================================================================
// Prepass B: x[b][c][n] -> g_xt[b][n][c], tf32-rounded (32x32 smem transpose)
// grid (48 c-tiles, 8 n-tiles, 64)
// ==========================================================================
__global__ __launch_bounds__(256) void p_xt(const float* __restrict__ x)
{
    __shared__ float sm[32][33];
    const int b  = blockIdx.z;
    const int ct = blockIdx.x * 32;
    const int nt = blockIdx.y * 32;
    const int tx = threadIdx.x & 31;
    const int ty = threadIdx.x >> 5;

#pragma unroll
    for (int i = 0; i < 4; i++) {
        int c = ct + ty + i * 8;
        sm[ty + i * 8][tx] = tf32r(x[((size_t)b * C_DIM + c) * N_TOK + nt + tx]);
    }
    __syncthreads();
#pragma unroll
    for (int i = 0; i < 4; i++) {
        int n = nt + ty + i * 8;
        g_xt[((size_t)b * N_TOK + n) * C_DIM + ct + tx] = sm[tx][ty + i * 8];
    }
}

// ==========================================================================
// Kernel 1: h^T = relu(W1 @ x + b1)^T, tf32-rounded, written as g_ht[b][n][o]
// BM=128 BN=128 BK=32; 8 warps (2m x 4n), warp tile 64x32; ldmatrix frags.
// grid (2 nt, 8 mt, 64 b)
// ==========================================================================
__global__ __launch_bounds__(256, 2) void k1_mma(
    const float* __restrict__ bc1, const float* __restrict__ bs1)
{
    extern __shared__ float smf[];
    const uint32_t As_u = (uint32_t)__cvta_generic_to_shared(smf);
    const uint32_t Bs_u = As_u + 2 * STAGE_BYTES;

    const int b  = blockIdx.z;
    const int mt = blockIdx.y;
    const int nt = blockIdx.x;

    const float* A    = g_w1 + (size_t)mt * 128 * C_DIM;
    const float* bias = (mt < 4) ? (bc1 + mt * 128) : (bs1 + (mt - 4) * 128);
    const float* Bsrc = g_xt + ((size_t)b * N_TOK + nt * 128) * C_DIM;

    const int tid  = threadIdx.x;
    const int warp = tid >> 5, lane = tid & 31;
    const int g = lane >> 2, t = lane & 3;
    const int wm = warp >> 2, wn = warp & 3;   // 2 x 4

    // ldmatrix lane address components
    const int rowA = lane & 15;
    const int kcA  = (lane >> 4) * 4;
    const int rowB = lane & 7;
    const int kcB  = ((lane >> 3) & 1) * 4;
    const int nio  = (lane >> 4) * 8;

    const uint32_t a_base = As_u + (uint32_t)((wm * 64 + rowA) * TS + kcA) * 4u;
    const uint32_t b_base = Bs_u + (uint32_t)((wn * 32 + nio + rowB) * TS + kcB) * 4u;

    // cp.async thread mapping: 128 rows x 8 float4 -> 4 per thread
    const int ld_row = tid >> 3;
    const int ld_c4  = tid & 7;

    float acc[4][4][4];
#pragma unroll
    for (int i = 0; i < 4; i++)
#pragma unroll
        for (int j = 0; j < 4; j++)
#pragma unroll
            for (int q = 0; q < 4; q++) acc[i][j][q] = 0.f;

#define K1_LOAD(buf, kt)                                                           \
    do {                                                                           \
        const int k0_ = (kt) * 32;                                                 \
        _Pragma("unroll")                                                          \
        for (int it = 0; it < 4; it++) {                                           \
            int row = ld_row + it * 32;                                            \
            uint32_t sa = As_u + (buf) * STAGE_BYTES + (uint32_t)(row * TS + ld_c4 * 4) * 4u; \
            CP_ASYNC16(sa, A + (size_t)row * C_DIM + k0_ + ld_c4 * 4);             \
            uint32_t sb = Bs_u + (buf) * STAGE_BYTES + (uint32_t)(row * TS + ld_c4 * 4) * 4u; \
            CP_ASYNC16(sb, Bsrc + (size_t)row * C_DIM + k0_ + ld_c4 * 4);          \
        }                                                                          \
    } while (0)

    const int KT = C_DIM / 32;   // 48
    K1_LOAD(0, 0);
    CP_COMMIT();

    for (int kt = 0; kt < KT; kt++) {
        if (kt + 1 < KT) K1_LOAD((kt + 1) & 1, kt + 1);
        CP_COMMIT();
        CP_WAIT1();
        __syncthreads();

        const uint32_t abuf = a_base + (kt & 1) * STAGE_BYTES;
        const uint32_t bbuf = b_base + (kt & 1) * STAGE_BYTES;

#pragma unroll
        for (int kk = 0; kk < 4; kk++) {
            uint32_t af[4][4];
#pragma unroll
            for (int mi = 0; mi < 4; mi++)
                ldsm_x4(af[mi][0], af[mi][1], af[mi][2], af[mi][3],
                        abuf + mi * (16 * ROW_BYTES) + kk * 32);
            uint32_t bf[4][2];
#pragma unroll
            for (int nip = 0; nip < 2; nip++) {
                uint32_t r0, r1, r2, r3;
                ldsm_x4(r0, r1, r2, r3, bbuf + nip * (16 * ROW_BYTES) + kk * 32);
                bf[2 * nip + 0][0] = r0; bf[2 * nip + 0][1] = r1;
                bf[2 * nip + 1][0] = r2; bf[2 * nip + 1][1] = r3;
            }
#pragma unroll
            for (int mi = 0; mi < 4; mi++)
#pragma unroll
                for (int ni = 0; ni < 4; ni++)
                    mma_tf32(acc[mi][ni], af[mi], bf[ni]);
        }
        __syncthreads();
    }

    // epilogue: bias + relu + tf32 round, store transposed to g_ht[b][n][o]
#pragma unroll
    for (int mi = 0; mi < 4; mi++) {
#pragma unroll
        for (int q2 = 0; q2 < 2; q2++) {
            int row = wm * 64 + mi * 16 + q2 * 8 + g;
            float bv = __ldg(bias + row);
#pragma unroll
            for (int ni = 0; ni < 4; ni++) {
                int col = nt * 128 + wn * 32 + ni * 8 + t * 2;
                size_t base = ((size_t)b * N_TOK + col) * 1024 + mt * 128 + row;
                g_ht[base]        = tf32r(fmaxf(acc[mi][ni][q2 * 2 + 0] + bv, 0.f));
                g_ht[base + 1024] = tf32r(fmaxf(acc[mi][ni][q2 * 2 + 1] + bv, 0.f));
            }
        }
    }
}

// ==========================================================================
// Kernel 2: f = Wc2 @ h1 + bc2 (mt=0);  s = Ws2 @ h2 + bs2 (mt=1, rows<64)
// same tile geometry; A = g_w2 (128 rows per mt), B = g_ht (+ koff), KT=16.
// grid (2 nt, 2 mt, 64 b)
// ==========================================================================
__global__ __launch_bounds__(256, 2) void k2_mma(
    const float* __restrict__ bc2, const float* __restrict__ bs2)
{
    extern __shared__ float smf[];
    const uint32_t As_u = (uint32_t)__cvta_generic_to_shared(smf);
    const uint32_t Bs_u = As_u + 2 * STAGE_BYTES;

    const int b  = blockIdx.z;
    const int mt = blockIdx.y;   // 0 -> f, 1 -> s
    const int nt = blockIdx.x;

    const float* A    = g_w2 + (size_t)mt * 128 * HIDD;
    const float* Bsrc = g_ht + ((size_t)b * N_TOK + nt * 128) * 1024 + mt * 512;

    const int tid  = threadIdx.x;
    const int warp = tid >> 5, lane = tid & 31;
    const int g = lane >> 2, t = lane & 3;
    const int wm = warp >> 2, wn = warp & 3;

    const int rowA = lane & 15;
    const int kcA  = (lane >> 4) * 4;
    const int rowB = lane & 7;
    const int kcB  = ((lane >> 3) & 1) * 4;
    const int nio  = (lane >> 4) * 8;

    const uint32_t a_base = As_u + (uint32_t)((wm * 64 + rowA) * TS + kcA) * 4u;
    const uint32_t b_base = Bs_u + (uint32_t)((wn * 32 + nio + rowB) * TS + kcB) * 4u;

    const int ld_row = tid >> 3;
    const int ld_c4  = tid & 7;

    float acc[4][4][4];
#pragma unroll
    for (int i = 0; i < 4; i++)
#pragma unroll
        for (int j = 0; j < 4; j++)
#pragma unroll
            for (int q = 0; q < 4; q++) acc[i][j][q] = 0.f;

#define K2_LOAD(buf, kt)                                                           \
    do {                                                                           \
        const int k0_ = (kt) * 32;                                                 \
        _Pragma("unroll")                                                          \
        for (int it = 0; it < 4; it++) {                                           \
            int row = ld_row + it * 32;                                            \
            uint32_t sa = As_u + (buf) * STAGE_BYTES + (uint32_t)(row * TS + ld_c4 * 4) * 4u; \
            CP_ASYNC16(sa, A + (size_t)row * HIDD + k0_ + ld_c4 * 4);              \
            uint32_t sb = Bs_u + (buf) * STAGE_BYTES + (uint32_t)(row * TS + ld_c4 * 4) * 4u; \
            CP_ASYNC16(sb, Bsrc + (size_t)row * 1024 + k0_ + ld_c4 * 4);           \
        }                                                                          \
    } while (0)

    const int KT = HIDD / 32;   // 16
    K2_LOAD(0, 0);
    CP_COMMIT();

    for (int kt = 0; kt < KT; kt++) {
        if (kt + 1 < KT) K2_LOAD((kt + 1) & 1, kt + 1);
        CP_COMMIT();
        CP_WAIT1();
        __syncthreads();

        const uint32_t abuf = a_base + (kt & 1) * STAGE_BYTES;
        const uint32_t bbuf = b_base + (kt & 1) * STAGE_BYTES;

#pragma unroll
        for (int kk = 0; kk < 4; kk++) {
            uint32_t af[4][4];
#pragma unroll
            for (int mi = 0; mi < 4; mi++)
                ldsm_x4(af[mi][0], af[mi][1], af[mi][2], af[mi][3],
                        abuf + mi * (16 * ROW_BYTES) + kk * 32);
            uint32_t bf[4][2];
#pragma unroll
            for (int nip = 0; nip < 2; nip++) {
                uint32_t r0, r1, r2, r3;
                ldsm_x4(r0, r1, r2, r3, bbuf + nip * (16 * ROW_BYTES) + kk * 32);
                bf[2 * nip + 0][0] = r0; bf[2 * nip + 0][1] = r1;
                bf[2 * nip + 1][0] = r2; bf[2 * nip + 1][1] = r3;
            }
#pragma unroll
            for (int mi = 0; mi < 4; mi++)
#pragma unroll
                for (int ni = 0; ni < 4; ni++)
                    mma_tf32(acc[mi][ni], af[mi], bf[ni]);
        }
        __syncthreads();
    }

    // epilogue: +bias, store row-major to g_f / g_s
#pragma unroll
    for (int mi = 0; mi < 4; mi++) {
#pragma unroll
        for (int q2 = 0; q2 < 2; q2++) {
            int row = wm * 64 + mi * 16 + q2 * 8 + g;
            if (mt == 0) {
                float bv = __ldg(bc2 + row);
#pragma unroll
                for (int ni = 0; ni < 4; ni++) {
                    int col = nt * 128 + wn * 32 + ni * 8 + t * 2;
                    float2 v;
                    v.x = acc[mi][ni][q2 * 2 + 0] + bv;
                    v.y = acc[mi][ni][q2 * 2 + 1] + bv;
                    *(float2*)(g_f + ((size_t)b * L_DIM + row) * N_TOK + col) = v;
                }
            } else if (row < 64) {
                float bv = __ldg(bs2 + row);
#pragma unroll
                for (int ni = 0; ni < 4; ni++) {
                    int col = nt * 128 + wn * 32 + ni * 8 + t * 2;
                    float2 v;
                    v.x = acc[mi][ni][q2 * 2 + 0] + bv;
                    v.y = acc[mi][ni][q2 * 2 + 1] + bv;
                    *(float2*)(g_s + ((size_t)b * M_CL + row) * N_TOK + col) = v;
                }
            }
        }
    }
}

// ==========================================================================
// Kernel 3: token MLP + L2 norm -> out[b][0:256]
// ==========================================================================
__global__ __launch_bounds__(256) void k3_token(
    const float* __restrict__ t,
    const float* __restrict__ Wt1, const float* __restrict__ bt1,
    const float* __restrict__ Wt2, const float* __restrict__ bt2,
    float* __restrict__ out)
{
    __shared__ float ts[C_DIM];
    __shared__ float th[HIDD];
    __shared__ float red[8];

    const int b   = blockIdx.x;
    const int tid = threadIdx.x;

    for (int i = tid; i < C_DIM; i += 256) ts[i] = t[(size_t)b * C_DIM + i];
    __syncthreads();

    for (int o = tid; o < HIDD; o += 256) {
        const float* wr = Wt1 + (size_t)o * C_DIM;
        float a0 = 0.f, a1 = 0.f, a2 = 0.f, a3 = 0.f;
        for (int c = 0; c < C_DIM; c += 4) {
            a0 += wr[c + 0] * ts[c + 0];
            a1 += wr[c + 1] * ts[c + 1];
            a2 += wr[c + 2] * ts[c + 2];
            a3 += wr[c + 3] * ts[c + 3];
        }
        th[o] = fmaxf((a0 + a1) + (a2 + a3) + bt1[o], 0.f);
    }
    __syncthreads();

    float val;
    {
        const float* wr = Wt2 + (size_t)tid * HIDD;
        float a0 = 0.f, a1 = 0.f, a2 = 0.f, a3 = 0.f;
        for (int c = 0; c < HIDD; c += 4) {
            a0 += wr[c + 0] * th[c + 0];
            a1 += wr[c + 1] * th[c + 1];
            a2 += wr[c + 2] * th[c + 2];
            a3 += wr[c + 3] * th[c + 3];
        }
        val = (a0 + a1) + (a2 + a3) + bt2[tid];
    }

    float ss = val * val;
#pragma unroll
    for (int off = 16; off; off >>= 1) ss += __shfl_xor_sync(0xffffffffu, ss, off);
    if ((tid & 31) == 0) red[tid >> 5] = ss;
    __syncthreads();
    float tot = 0.f;
#pragma unroll
    for (int i = 0; i < 8; i++) tot += red[i];
    float sc = 1.f / fmaxf(sqrtf(tot), 1e-12f);
    out[(size_t)b * OUT_PER_B + tid] = val * sc;
}

// ==========================================================================
// Kernel 4: Sinkhorn -> g_p
// ==========================================================================
__global__ __launch_bounds__(256) void k4_sinkhorn(const float* __restrict__ dustp)
{
    extern __shared__ float sh[];
    float* Ms = sh;
    float* u  = sh + 65 * 256;
    float* v  = u + 72;

    const int b   = blockIdx.x;
    const int tid = threadIdx.x;
    const float dust = *dustp;
    const float* S = g_s + (size_t)b * M_CL * N_TOK;

    for (int i = tid; i < 64 * 256; i += 256) Ms[i] = S[i];
    Ms[64 * 256 + tid] = dust;
    v[tid] = 0.f;
    __syncthreads();

    const int w    = tid >> 5;
    const int lane = tid & 31;

    for (int it = 0; it < 3; it++) {
        for (int r = w; r < 65; r += 8) {
            float vals[8];
            float mx = -INFINITY;
#pragma unroll
            for (int q = 0; q < 8; q++) {
                float vv = Ms[r * 256 + lane + 32 * q] + v[lane + 32 * q];
                vals[q] = vv;
                mx = fmaxf(mx, vv);
            }
#pragma unroll
            for (int off = 16; off; off >>= 1)
                mx = fmaxf(mx, __shfl_xor_sync(0xffffffffu, mx, off));
            float ssum = 0.f;
#pragma unroll
            for (int q = 0; q < 8; q++) ssum += expf(vals[q] - mx);
#pragma unroll
            for (int off = 16; off; off >>= 1)
                ssum += __shfl_xor_sync(0xffffffffu, ssum, off);
            if (lane == 0) {
                float la = (r == 64) ? LOGA_LAST : NEG_LOG320;
                u[r] = la - (mx + logf(ssum));
            }
        }
        __syncthreads();
        {
            float mrun = -INFINITY, srun = 0.f;
            for (int m = 0; m < 65; m++) {
                float vv = Ms[m * 256 + tid] + u[m];
                if (vv > mrun) {
                    srun = srun * expf(mrun - vv) + 1.f;
                    mrun = vv;
                } else {
                    srun += expf(vv - mrun);
                }
            }
            v[tid] = NEG_LOG320 - (mrun + logf(srun));
        }
        __syncthreads();
    }

    float* P = g_p + (size_t)b * M_CL * N_TOK;
    for (int i = tid; i < 64 * 256; i += 256) {
        int m = i >> 8, j = i & 255;
        P[i] = expf(Ms[i] + u[m] + v[j] - NEG_LOG320);
    }
}

// ==========================================================================
// Kernel 5: VLAD + intra-norm
// ==========================================================================
#define PS_LD 260
__global__ __launch_bounds__(256) void k5_vlad(float* __restrict__ out)
{
    extern __shared__ float sh[];
    float* ps  = sh;
    float* vs  = sh + 64 * PS_LD;
    float* inv = vs + 128 * 64;

    const int b   = blockIdx.x;
    const int tid = threadIdx.x;
    const float* P = g_p + (size_t)b * M_CL * N_TOK;
    const float* F = g_f + (size_t)b * L_DIM * N_TOK;

    for (int i = tid; i < 64 * 256; i += 256) {
        int m = i >> 8, n = i & 255;
        ps[m * PS_LD + n] = P[i];
    }
    __syncthreads();

    const int m  = tid & 63;
    const int lg = tid >> 6;

    const float4* pr = (const float4*)(ps + m * PS_LD);

    float acc[32];
#pragma unroll
    for (int i = 0; i < 32; i++) acc[i] = 0.f;

    for (int nc = 0; nc < 64; nc += 4) {
        float4 pv0 = pr[nc + 0], pv1 = pr[nc + 1], pv2 = pr[nc + 2], pv3 = pr[nc + 3];
#pragma unroll
        for (int li = 0; li < 32; li++) {
            const float4* fr = (const float4*)(F + (size_t)(lg * 32 + li) * N_TOK);
            float4 f0 = fr[nc + 0], f1 = fr[nc + 1], f2 = fr[nc + 2], f3 = fr[nc + 3];
            float a = acc[li];
            a += f0.x * pv0.x + f0.y * pv0.y + f0.z * pv0.z + f0.w * pv0.w;
            a += f1.x * pv1.x + f1.y * pv1.y + f1.z * pv1.z + f1.w * pv1.w;
            a += f2.x * pv2.x + f2.y * pv2.y + f2.z * pv2.z + f2.w * pv2.w;
            a += f3.x * pv3.x + f3.y * pv3.y + f3.z * pv3.z + f3.w * pv3.w;
            acc[li] = a;
        }
    }
#pragma unroll
    for (int li = 0; li < 32; li++) vs[(lg * 32 + li) * 64 + m] = acc[li];
    __syncthreads();

    if (tid < 64) {
        float ss = 0.f;
        for (int l = 0; l < 128; l++) {
            float vv = vs[l * 64 + tid];
            ss += vv * vv;
        }
        inv[tid] = 1.f / fmaxf(sqrtf(ss), 1e-12f);
    }
    __syncthreads();

    float* Ob = out + (size_t)b * OUT_PER_B + G_DIM;
    for (int i = tid; i < L_DIM * M_CL; i += 256) Ob[i] = vs[i] * inv[i & 63];
}

// ==========================================================================
// Kernel 6: final L2 norm
// ==========================================================================
__global__ __launch_bounds__(256) void k6_norm(float* __restrict__ out)
{
    __shared__ float red[8];
    __shared__ float sc_s;
    const int b   = blockIdx.x;
    const int tid = threadIdx.x;
    float* O = out + (size_t)b * OUT_PER_B;

    float ss = 0.f;
    for (int i = tid; i < OUT_PER_B; i += 256) {
        float vv = O[i];
        ss += vv * vv;
    }
#pragma unroll
    for (int off = 16; off; off >>= 1) ss += __shfl_xor_sync(0xffffffffu, ss, off);
    if ((tid & 31) == 0) red[tid >> 5] = ss;
    __syncthreads();
    if (tid == 0) {
        float tot = 0.f;
#pragma unroll
        for (int i = 0; i < 8; i++) tot += red[i];
        sc_s = 1.f / fmaxf(sqrtf(tot), 1e-12f);
    }
    __syncthreads();
    float sc = sc_s;
    for (int i = tid; i < OUT_PER_B; i += 256) O[i] *= sc;
}

// ==========================================================================
// launch
// ==========================================================================
extern "C" void kernel_launch(void* const* d_in, const int* in_sizes, int n_in,
                              void* d_out, int out_size)
{
    (void)in_sizes; (void)n_in; (void)out_size;
    const float* x    = (const float*)d_in[0];
    const float* t    = (const float*)d_in[1];
    const float* Wt1  = (const float*)d_in[2];
    const float* bt1  = (const float*)d_in[3];
    const float* Wt2  = (const float*)d_in[4];
    const float* bt2  = (const float*)d_in[5];
    const float* Wc1  = (const float*)d_in[6];
    const float* bc1  = (const float*)d_in[7];
    const float* Wc2  = (const float*)d_in[8];
    const float* bc2  = (const float*)d_in[9];
    const float* Ws1  = (const float*)d_in[10];
    const float* bs1  = (const float*)d_in[11];
    const float* Ws2  = (const float*)d_in[12];
    const float* bs2  = (const float*)d_in[13];
    const float* dust = (const float*)d_in[14];
    float* out = (float*)d_out;

    const int sink_smem = (65 * 256 + 72 + 256) * (int)sizeof(float);
    const int vlad_smem = (64 * PS_LD + 128 * 64 + 64) * (int)sizeof(float);
    cudaFuncSetAttribute(k1_mma,      cudaFuncAttributeMaxDynamicSharedMemorySize, GEMM_SMEM);
    cudaFuncSetAttribute(k2_mma,      cudaFuncAttributeMaxDynamicSharedMemorySize, GEMM_SMEM);
    cudaFuncSetAttribute(k4_sinkhorn, cudaFuncAttributeMaxDynamicSharedMemorySize, sink_smem);
    cudaFuncSetAttribute(k5_vlad,     cudaFuncAttributeMaxDynamicSharedMemorySize, vlad_smem);

    p_weights<<<512, 256>>>(Wc1, Ws1, Wc2, Ws2);
    p_xt<<<dim3(48, 8, B_SZ), 256>>>(x);
    k1_mma<<<dim3(2, 8, B_SZ), 256, GEMM_SMEM>>>(bc1, bs1);
    k2_mma<<<dim3(2, 2, B_SZ), 256, GEMM_SMEM>>>(bc2, bs2);
    k3_token<<<B_SZ, 256>>>(t, Wt1, bt1, Wt2, bt2, out);
    k4_sinkhorn<<<B_SZ, 256, sink_smem>>>(dust);
    k5_vlad<<<B_SZ, 256, vlad_smem>>>(out);
    k6_norm<<<B_SZ, 256>>>(out);
}

// round 5
// speedup vs baseline: 2.3037x; 1.1402x over previous
#include <cuda_runtime.h>
#include <cuda_fp16.h>
#include <math.h>
#include <stdint.h>

// ---------------- problem constants ----------------
#define B_SZ   64
#define C_DIM  1536
#define N_TOK  256
#define HIDD   512
#define L_DIM  128
#define G_DIM  256
#define M_CL   64
#define OUT_PER_B (G_DIM + L_DIM * M_CL)   // 8448

#define NEG_LOG320 (-5.768320995793772f)
#define LOGA_LAST  (-0.510825623765991f)

// ---------------- scratch ----------------
__device__ __half g_xth[B_SZ * N_TOK * C_DIM];   // x^T fp16: [b][n][k]
__device__ __half g_hth[B_SZ * N_TOK * 1024];    // hidden^T fp16: [b][n][o]
__device__ __half g_w1h[1024 * C_DIM];           // [Wc1;Ws1] fp16
__device__ __half g_w2h[256 * HIDD];             // rows 0-127 Wc2, 128-191 Ws2, rest 0
__device__ float  g_f[B_SZ * L_DIM * N_TOK];
__device__ float  g_s[B_SZ * M_CL * N_TOK];
__device__ float  g_p[B_SZ * M_CL * N_TOK];

// ---------------- helpers ----------------
#define CP_ASYNC16(smem_u32, gptr) \
    asm volatile("cp.async.cg.shared.global [%0], [%1], 16;" :: "r"(smem_u32), "l"(gptr))
#define CP_COMMIT() asm volatile("cp.async.commit_group;")
#define CP_WAIT1()  asm volatile("cp.async.wait_group 1;")

__device__ __forceinline__ void ldsm_x4(uint32_t& r0, uint32_t& r1, uint32_t& r2, uint32_t& r3,
                                        uint32_t addr) {
    asm volatile("ldmatrix.sync.aligned.m8n8.x4.shared.b16 {%0,%1,%2,%3}, [%4];"
        : "=r"(r0), "=r"(r1), "=r"(r2), "=r"(r3) : "r"(addr));
}

__device__ __forceinline__ void mma_f16(float* d, const uint32_t* a, const uint32_t* b) {
    asm volatile(
        "mma.sync.aligned.m16n8k16.row.col.f32.f16.f16.f32 "
        "{%0,%1,%2,%3}, {%4,%5,%6,%7}, {%8,%9}, {%0,%1,%2,%3};"
        : "+f"(d[0]), "+f"(d[1]), "+f"(d[2]), "+f"(d[3])
        : "r"(a[0]), "r"(a[1]), "r"(a[2]), "r"(a[3]), "r"(b[0]), "r"(b[1]));
}

// smem geometry: rows of 32 halves + 8 pad -> stride 40 halves (80 B), conflict-free ldsm
#define HTS          40
#define HROW_BYTES   80
#define HSTAGE_BYTES (128 * HROW_BYTES)           // 10240 per operand per stage
#define HGEMM_SMEM   (4 * HSTAGE_BYTES)           // 40960 B

// ==========================================================================
// Prepass A: weights -> fp16 copies
// ==========================================================================
__global__ __launch_bounds__(256) void p_weights(
    const float* __restrict__ Wc1, const float* __restrict__ Ws1,
    const float* __restrict__ Wc2, const float* __restrict__ Ws2)
{
    const int total1 = 1024 * C_DIM;
    const int total2 = 256 * HIDD;
    for (int idx = blockIdx.x * 256 + threadIdx.x; idx < total1 + total2;
         idx += gridDim.x * 256) {
        if (idx < total1) {
            float v = (idx < 512 * C_DIM) ? Wc1[idx] : Ws1[idx - 512 * C_DIM];
            g_w1h[idx] = __float2half_rn(v);
        } else {
            int j = idx - total1;
            int row = j / HIDD;
            float v = (row < 128) ? Wc2[j]
                    : (row < 192) ? Ws2[j - 128 * HIDD] : 0.f;
            g_w2h[j] = __float2half_rn(v);
        }
    }
}

// ==========================================================================
// Prepass B: x[b][c][n] -> g_xth[b][n][c] fp16 (32x32 smem transpose)
// grid (48 c-tiles, 8 n-tiles, 64)
// ==========================================================================
__global__ __launch_bounds__(256) void p_xt(const float* __restrict__ x)
{
    __shared__ float sm[32][33];
    const int b  = blockIdx.z;
    const int ct = blockIdx.x * 32;
    const int nt = blockIdx.y * 32;
    const int tx = threadIdx.x & 31;
    const int ty = threadIdx.x >> 5;

#pragma unroll
    for (int i = 0; i < 4; i++) {
        int c = ct + ty + i * 8;
        sm[ty + i * 8][tx] = x[((size_t)b * C_DIM + c) * N_TOK + nt + tx];
    }
    __syncthreads();
#pragma unroll
    for (int i = 0; i < 4; i++) {
        int n = nt + ty + i * 8;
        g_xth[((size_t)b * N_TOK + n) * C_DIM + ct + tx] = __float2half_rn(sm[tx][ty + i * 8]);
    }
}

// ==========================================================================
// Kernel 1 (fp16 mma.sync): h^T = relu(W1 @ x + b1)^T -> g_hth[b][n][o]
// BM=128 BN=128 BK=32; 8 warps (2m x 4n), warp tile 64x32; m16n8k16.
// grid (2 nt, 8 mt, 64 b)
// ==========================================================================
__global__ __launch_bounds__(256, 2) void k1_mma(
    const float* __restrict__ bc1, const float* __restrict__ bs1)
{
    extern __shared__ __half smh[];
    const uint32_t As_u = (uint32_t)__cvta_generic_to_shared(smh);
    const uint32_t Bs_u = As_u + 2 * HSTAGE_BYTES;

    const int b  = blockIdx.z;
    const int mt = blockIdx.y;
    const int nt = blockIdx.x;

    const __half* A    = g_w1h + (size_t)mt * 128 * C_DIM;
    const float*  bias = (mt < 4) ? (bc1 + mt * 128) : (bs1 + (mt - 4) * 128);
    const __half* Bsrc = g_xth + ((size_t)b * N_TOK + nt * 128) * C_DIM;

    const int tid  = threadIdx.x;
    const int warp = tid >> 5, lane = tid & 31;
    const int g = lane >> 2, t = lane & 3;
    const int wm = warp >> 2, wn = warp & 3;   // 2 x 4

    // ldmatrix lane address: row = lane&15, col = (lane>>4)*8 halves
    const int lrow = lane & 15;
    const int lcol = (lane >> 4) * 8;

    const uint32_t a_base = As_u + (uint32_t)((wm * 64 + lrow) * HTS + lcol) * 2u;
    const uint32_t b_base = Bs_u + (uint32_t)((wn * 32 + lrow) * HTS + lcol) * 2u;

    // cp.async: 128 rows x 4 chunks(16B = 8 halves) per operand -> 2 per thread
    const int ld_row = tid >> 2;   // 0..63, +64 on second iter
    const int ld_c   = tid & 3;

    float acc[4][4][4];
#pragma unroll
    for (int i = 0; i < 4; i++)
#pragma unroll
        for (int j = 0; j < 4; j++)
#pragma unroll
            for (int q = 0; q < 4; q++) acc[i][j][q] = 0.f;

#define K1_LOAD(buf, kt)                                                             \
    do {                                                                             \
        const int k0_ = (kt) * 32;                                                   \
        _Pragma("unroll")                                                            \
        for (int it = 0; it < 2; it++) {                                             \
            int row = ld_row + it * 64;                                              \
            uint32_t so = (uint32_t)(row * HTS + ld_c * 8) * 2u + (buf) * HSTAGE_BYTES; \
            CP_ASYNC16(As_u + so, A + (size_t)row * C_DIM + k0_ + ld_c * 8);         \
            CP_ASYNC16(Bs_u + so, Bsrc + (size_t)row * C_DIM + k0_ + ld_c * 8);      \
        }                                                                            \
    } while (0)

    const int KT = C_DIM / 32;   // 48
    K1_LOAD(0, 0);
    CP_COMMIT();

    for (int kt = 0; kt < KT; kt++) {
        if (kt + 1 < KT) K1_LOAD((kt + 1) & 1, kt + 1);
        CP_COMMIT();
        CP_WAIT1();
        __syncthreads();

        const uint32_t abuf = a_base + (kt & 1) * HSTAGE_BYTES;
        const uint32_t bbuf = b_base + (kt & 1) * HSTAGE_BYTES;

#pragma unroll
        for (int kk = 0; kk < 2; kk++) {   // two k16 steps per BK=32
            uint32_t af[4][4];
#pragma unroll
            for (int mi = 0; mi < 4; mi++)
                ldsm_x4(af[mi][0], af[mi][1], af[mi][2], af[mi][3],
                        abuf + mi * (16 * HROW_BYTES) + kk * 32);
            uint32_t bf[4][2];
#pragma unroll
            for (int nip = 0; nip < 2; nip++) {
                uint32_t r0, r1, r2, r3;
                ldsm_x4(r0, r1, r2, r3, bbuf + nip * (16 * HROW_BYTES) + kk * 32);
                bf[2 * nip + 0][0] = r0; bf[2 * nip + 0][1] = r2;
                bf[2 * nip + 1][0] = r1; bf[2 * nip + 1][1] = r3;
            }
#pragma unroll
            for (int mi = 0; mi < 4; mi++)
#pragma unroll
                for (int ni = 0; ni < 4; ni++)
                    mma_f16(acc[mi][ni], af[mi], bf[ni]);
        }
        __syncthreads();
    }

    // epilogue: bias + relu -> fp16, store transposed to g_hth[b][n][o]
#pragma unroll
    for (int mi = 0; mi < 4; mi++) {
#pragma unroll
        for (int q2 = 0; q2 < 2; q2++) {
            int row = wm * 64 + mi * 16 + q2 * 8 + g;
            float bv = __ldg(bias + row);
#pragma unroll
            for (int ni = 0; ni < 4; ni++) {
                int col = nt * 128 + wn * 32 + ni * 8 + t * 2;
                size_t base = ((size_t)b * N_TOK + col) * 1024 + mt * 128 + row;
                g_hth[base]        = __float2half_rn(fmaxf(acc[mi][ni][q2 * 2 + 0] + bv, 0.f));
                g_hth[base + 1024] = __float2half_rn(fmaxf(acc[mi][ni][q2 * 2 + 1] + bv, 0.f));
            }
        }
    }
}

// ==========================================================================
// Kernel 2 (fp16 mma.sync): f = Wc2 @ h1 + bc2 ; s = Ws2 @ h2 + bs2
// grid (2 nt, 2 mt, 64 b); KT=16.
// ==========================================================================
__global__ __launch_bounds__(256, 2) void k2_mma(
    const float* __restrict__ bc2, const float* __restrict__ bs2)
{
    extern __shared__ __half smh[];
    const uint32_t As_u = (uint32_t)__cvta_generic_to_shared(smh);
    const uint32_t Bs_u = As_u + 2 * HSTAGE_BYTES;

    const int b  = blockIdx.z;
    const int mt = blockIdx.y;
    const int nt = blockIdx.x;

    const __half* A    = g_w2h + (size_t)mt * 128 * HIDD;
    const __half* Bsrc = g_hth + ((size_t)b * N_TOK + nt * 128) * 1024 + mt * 512;

    const int tid  = threadIdx.x;
    const int warp = tid >> 5, lane = tid & 31;
    const int g = lane >> 2, t = lane & 3;
    const int wm = warp >> 2, wn = warp & 3;

    const int lrow = lane & 15;
    const int lcol = (lane >> 4) * 8;

    const uint32_t a_base = As_u + (uint32_t)((wm * 64 + lrow) * HTS + lcol) * 2u;
    const uint32_t b_base = Bs_u + (uint32_t)((wn * 32 + lrow) * HTS + lcol) * 2u;

    const int ld_row = tid >> 2;
    const int ld_c   = tid & 3;

    float acc[4][4][4];
#pragma unroll
    for (int i = 0; i < 4; i++)
#pragma unroll
        for (int j = 0; j < 4; j++)
#pragma unroll
            for (int q = 0; q < 4; q++) acc[i][j][q] = 0.f;

#define K2_LOAD(buf, kt)                                                             \
    do {                                                                             \
        const int k0_ = (kt) * 32;                                                   \
        _Pragma("unroll")                                                            \
        for (int it = 0; it < 2; it++) {                                             \
            int row = ld_row + it * 64;                                              \
            uint32_t so = (uint32_t)(row * HTS + ld_c * 8) * 2u + (buf) * HSTAGE_BYTES; \
            CP_ASYNC16(As_u + so, A + (size_t)row * HIDD + k0_ + ld_c * 8);          \
            CP_ASYNC16(Bs_u + so, Bsrc + (size_t)row * 1024 + k0_ + ld_c * 8);       \
        }                                                                            \
    } while (0)

    const int KT = HIDD / 32;   // 16
    K2_LOAD(0, 0);
    CP_COMMIT();

    for (int kt = 0; kt < KT; kt++) {
        if (kt + 1 < KT) K2_LOAD((kt + 1) & 1, kt + 1);
        CP_COMMIT();
        CP_WAIT1();
        __syncthreads();

        const uint32_t abuf = a_base + (kt & 1) * HSTAGE_BYTES;
        const uint32_t bbuf = b_base + (kt & 1) * HSTAGE_BYTES;

#pragma unroll
        for (int kk = 0; kk < 2; kk++) {
            uint32_t af[4][4];
#pragma unroll
            for (int mi = 0; mi < 4; mi++)
                ldsm_x4(af[mi][0], af[mi][1], af[mi][2], af[mi][3],
                        abuf + mi * (16 * HROW_BYTES) + kk * 32);
            uint32_t bf[4][2];
#pragma unroll
            for (int nip = 0; nip < 2; nip++) {
                uint32_t r0, r1, r2, r3;
                ldsm_x4(r0, r1, r2, r3, bbuf + nip * (16 * HROW_BYTES) + kk * 32);
                bf[2 * nip + 0][0] = r0; bf[2 * nip + 0][1] = r2;
                bf[2 * nip + 1][0] = r1; bf[2 * nip + 1][1] = r3;
            }
#pragma unroll
            for (int mi = 0; mi < 4; mi++)
#pragma unroll
                for (int ni = 0; ni < 4; ni++)
                    mma_f16(acc[mi][ni], af[mi], bf[ni]);
        }
        __syncthreads();
    }

#pragma unroll
    for (int mi = 0; mi < 4; mi++) {
#pragma unroll
        for (int q2 = 0; q2 < 2; q2++) {
            int row = wm * 64 + mi * 16 + q2 * 8 + g;
            if (mt == 0) {
                float bv = __ldg(bc2 + row);
#pragma unroll
                for (int ni = 0; ni < 4; ni++) {
                    int col = nt * 128 + wn * 32 + ni * 8 + t * 2;
                    float2 v;
                    v.x = acc[mi][ni][q2 * 2 + 0] + bv;
                    v.y = acc[mi][ni][q2 * 2 + 1] + bv;
                    *(float2*)(g_f + ((size_t)b * L_DIM + row) * N_TOK + col) = v;
                }
            } else if (row < 64) {
                float bv = __ldg(bs2 + row);
#pragma unroll
                for (int ni = 0; ni < 4; ni++) {
                    int col = nt * 128 + wn * 32 + ni * 8 + t * 2;
                    float2 v;
                    v.x = acc[mi][ni][q2 * 2 + 0] + bv;
                    v.y = acc[mi][ni][q2 * 2 + 1] + bv;
                    *(float2*)(g_s + ((size_t)b * M_CL + row) * N_TOK + col) = v;
                }
            }
        }
    }
}

// ==========================================================================
// Kernel 3: token MLP + L2 norm -> out[b][0:256]
// ==========================================================================
__global__ __launch_bounds__(256) void k3_token(
    const float* __restrict__ t,
    const float* __restrict__ Wt1, const float* __restrict__ bt1,
    const float* __restrict__ Wt2, const float* __restrict__ bt2,
    float* __restrict__ out)
{
    __shared__ float ts[C_DIM];
    __shared__ float th[HIDD];
    __shared__ float red[8];

    const int b   = blockIdx.x;
    const int tid = threadIdx.x;

    for (int i = tid; i < C_DIM; i += 256) ts[i] = t[(size_t)b * C_DIM + i];
    __syncthreads();

    for (int o = tid; o < HIDD; o += 256) {
        const float* wr = Wt1 + (size_t)o * C_DIM;
        float a0 = 0.f, a1 = 0.f, a2 = 0.f, a3 = 0.f;
        for (int c = 0; c < C_DIM; c += 4) {
            a0 += wr[c + 0] * ts[c + 0];
            a1 += wr[c + 1] * ts[c + 1];
            a2 += wr[c + 2] * ts[c + 2];
            a3 += wr[c + 3] * ts[c + 3];
        }
        th[o] = fmaxf((a0 + a1) + (a2 + a3) + bt1[o], 0.f);
    }
    __syncthreads();

    float val;
    {
        const float* wr = Wt2 + (size_t)tid * HIDD;
        float a0 = 0.f, a1 = 0.f, a2 = 0.f, a3 = 0.f;
        for (int c = 0; c < HIDD; c += 4) {
            a0 += wr[c + 0] * th[c + 0];
            a1 += wr[c + 1] * th[c + 1];
            a2 += wr[c + 2] * th[c + 2];
            a3 += wr[c + 3] * th[c + 3];
        }
        val = (a0 + a1) + (a2 + a3) + bt2[tid];
    }

    float ss = val * val;
#pragma unroll
    for (int off = 16; off; off >>= 1) ss += __shfl_xor_sync(0xffffffffu, ss, off);
    if ((tid & 31) == 0) red[tid >> 5] = ss;
    __syncthreads();
    float tot = 0.f;
#pragma unroll
    for (int i = 0; i < 8; i++) tot += red[i];
    float sc = 1.f / fmaxf(sqrtf(tot), 1e-12f);
    out[(size_t)b * OUT_PER_B + tid] = val * sc;
}

// ==========================================================================
// Kernel 4: Sinkhorn -> g_p
// ==========================================================================
__global__ __launch_bounds__(256) void k4_sinkhorn(const float* __restrict__ dustp)
{
    extern __shared__ float sh[];
    float* Ms = sh;
    float* u  = sh + 65 * 256;
    float* v  = u + 72;

    const int b   = blockIdx.x;
    const int tid = threadIdx.x;
    const float dust = *dustp;
    const float* S = g_s + (size_t)b * M_CL * N_TOK;

    for (int i = tid; i < 64 * 256; i += 256) Ms[i] = S[i];
    Ms[64 * 256 + tid] = dust;
    v[tid] = 0.f;
    __syncthreads();

    const int w    = tid >> 5;
    const int lane = tid & 31;

    for (int it = 0; it < 3; it++) {
        for (int r = w; r < 65; r += 8) {
            float vals[8];
            float mx = -INFINITY;
#pragma unroll
            for (int q = 0; q < 8; q++) {
                float vv = Ms[r * 256 + lane + 32 * q] + v[lane + 32 * q];
                vals[q] = vv;
                mx = fmaxf(mx, vv);
            }
#pragma unroll
            for (int off = 16; off; off >>= 1)
                mx = fmaxf(mx, __shfl_xor_sync(0xffffffffu, mx, off));
            float ssum = 0.f;
#pragma unroll
            for (int q = 0; q < 8; q++) ssum += expf(vals[q] - mx);
#pragma unroll
            for (int off = 16; off; off >>= 1)
                ssum += __shfl_xor_sync(0xffffffffu, ssum, off);
            if (lane == 0) {
                float la = (r == 64) ? LOGA_LAST : NEG_LOG320;
                u[r] = la - (mx + logf(ssum));
            }
        }
        __syncthreads();
        {
            float mrun = -INFINITY, srun = 0.f;
            for (int m = 0; m < 65; m++) {
                float vv = Ms[m * 256 + tid] + u[m];
                if (vv > mrun) {
                    srun = srun * expf(mrun - vv) + 1.f;
                    mrun = vv;
                } else {
                    srun += expf(vv - mrun);
                }
            }
            v[tid] = NEG_LOG320 - (mrun + logf(srun));
        }
        __syncthreads();
    }

    float* P = g_p + (size_t)b * M_CL * N_TOK;
    for (int i = tid; i < 64 * 256; i += 256) {
        int m = i >> 8, j = i & 255;
        P[i] = expf(Ms[i] + u[m] + v[j] - NEG_LOG320);
    }
}

// ==========================================================================
// Kernel 5: VLAD + intra-norm
// ==========================================================================
#define PS_LD 260
__global__ __launch_bounds__(256) void k5_vlad(float* __restrict__ out)
{
    extern __shared__ float sh[];
    float* ps  = sh;
    float* vs  = sh + 64 * PS_LD;
    float* inv = vs + 128 * 64;

    const int b   = blockIdx.x;
    const int tid = threadIdx.x;
    const float* P = g_p + (size_t)b * M_CL * N_TOK;
    const float* F = g_f + (size_t)b * L_DIM * N_TOK;

    for (int i = tid; i < 64 * 256; i += 256) {
        int m = i >> 8, n = i & 255;
        ps[m * PS_LD + n] = P[i];
    }
    __syncthreads();

    const int m  = tid & 63;
    const int lg = tid >> 6;

    const float4* pr = (const float4*)(ps + m * PS_LD);

    float acc[32];
#pragma unroll
    for (int i = 0; i < 32; i++) acc[i] = 0.f;

    for (int nc = 0; nc < 64; nc += 4) {
        float4 pv0 = pr[nc + 0], pv1 = pr[nc + 1], pv2 = pr[nc + 2], pv3 = pr[nc + 3];
#pragma unroll
        for (int li = 0; li < 32; li++) {
            const float4* fr = (const float4*)(F + (size_t)(lg * 32 + li) * N_TOK);
            float4 f0 = fr[nc + 0], f1 = fr[nc + 1], f2 = fr[nc + 2], f3 = fr[nc + 3];
            float a = acc[li];
            a += f0.x * pv0.x + f0.y * pv0.y + f0.z * pv0.z + f0.w * pv0.w;
            a += f1.x * pv1.x + f1.y * pv1.y + f1.z * pv1.z + f1.w * pv1.w;
            a += f2.x * pv2.x + f2.y * pv2.y + f2.z * pv2.z + f2.w * pv2.w;
            a += f3.x * pv3.x + f3.y * pv3.y + f3.z * pv3.z + f3.w * pv3.w;
            acc[li] = a;
        }
    }
#pragma unroll
    for (int li = 0; li < 32; li++) vs[(lg * 32 + li) * 64 + m] = acc[li];
    __syncthreads();

    if (tid < 64) {
        float ss = 0.f;
        for (int l = 0; l < 128; l++) {
            float vv = vs[l * 64 + tid];
            ss += vv * vv;
        }
        inv[tid] = 1.f / fmaxf(sqrtf(ss), 1e-12f);
    }
    __syncthreads();

    float* Ob = out + (size_t)b * OUT_PER_B + G_DIM;
    for (int i = tid; i < L_DIM * M_CL; i += 256) Ob[i] = vs[i] * inv[i & 63];
}

// ==========================================================================
// Kernel 6: final L2 norm
// ==========================================================================
__global__ __launch_bounds__(256) void k6_norm(float* __restrict__ out)
{
    __shared__ float red[8];
    __shared__ float sc_s;
    const int b   = blockIdx.x;
    const int tid = threadIdx.x;
    float* O = out + (size_t)b * OUT_PER_B;

    float ss = 0.f;
    for (int i = tid; i < OUT_PER_B; i += 256) {
        float vv = O[i];
        ss += vv * vv;
    }
#pragma unroll
    for (int off = 16; off; off >>= 1) ss += __shfl_xor_sync(0xffffffffu, ss, off);
    if ((tid & 31) == 0) red[tid >> 5] = ss;
    __syncthreads();
    if (tid == 0) {
        float tot = 0.f;
#pragma unroll
        for (int i = 0; i < 8; i++) tot += red[i];
        sc_s = 1.f / fmaxf(sqrtf(tot), 1e-12f);
    }
    __syncthreads();
    float sc = sc_s;
    for (int i = tid; i < OUT_PER_B; i += 256) O[i] *= sc;
}

// ==========================================================================
// launch
// ==========================================================================
extern "C" void kernel_launch(void* const* d_in, const int* in_sizes, int n_in,
                              void* d_out, int out_size)
{
    (void)in_sizes; (void)n_in; (void)out_size;
    const float* x    = (const float*)d_in[0];
    const float* t    = (const float*)d_in[1];
    const float* Wt1  = (const float*)d_in[2];
    const float* bt1  = (const float*)d_in[3];
    const float* Wt2  = (const float*)d_in[4];
    const float* bt2  = (const float*)d_in[5];
    const float* Wc1  = (const float*)d_in[6];
    const float* bc1  = (const float*)d_in[7];
    const float* Wc2  = (const float*)d_in[8];
    const float* bc2  = (const float*)d_in[9];
    const float* Ws1  = (const float*)d_in[10];
    const float* bs1  = (const float*)d_in[11];
    const float* Ws2  = (const float*)d_in[12];
    const float* bs2  = (const float*)d_in[13];
    const float* dust = (const float*)d_in[14];
    float* out = (float*)d_out;

    const int sink_smem = (65 * 256 + 72 + 256) * (int)sizeof(float);
    const int vlad_smem = (64 * PS_LD + 128 * 64 + 64) * (int)sizeof(float);
    cudaFuncSetAttribute(k1_mma,      cudaFuncAttributeMaxDynamicSharedMemorySize, HGEMM_SMEM);
    cudaFuncSetAttribute(k2_mma,      cudaFuncAttributeMaxDynamicSharedMemorySize, HGEMM_SMEM);
    cudaFuncSetAttribute(k4_sinkhorn, cudaFuncAttributeMaxDynamicSharedMemorySize, sink_smem);
    cudaFuncSetAttribute(k5_vlad,     cudaFuncAttributeMaxDynamicSharedMemorySize, vlad_smem);

    p_weights<<<512, 256>>>(Wc1, Ws1, Wc2, Ws2);
    p_xt<<<dim3(48, 8, B_SZ), 256>>>(x);
    k1_mma<<<dim3(2, 8, B_SZ), 256, HGEMM_SMEM>>>(bc1, bs1);
    k2_mma<<<dim3(2, 2, B_SZ), 256, HGEMM_SMEM>>>(bc2, bs2);
    k3_token<<<B_SZ, 256>>>(t, Wt1, bt1, Wt2, bt2, out);
    k4_sinkhorn<<<B_SZ, 256, sink_smem>>>(dust);
    k5_vlad<<<B_SZ, 256, vlad_smem>>>(out);
    k6_norm<<<B_SZ, 256>>>(out);
}

// round 6
// speedup vs baseline: 2.3145x; 1.0047x over previous
#include <cuda_runtime.h>
#include <cuda_fp16.h>
#include <math.h>
#include <stdint.h>

// ---------------- problem constants ----------------
#define B_SZ   64
#define C_DIM  1536
#define N_TOK  256
#define HIDD   512
#define L_DIM  128
#define G_DIM  256
#define M_CL   64
#define OUT_PER_B (G_DIM + L_DIM * M_CL)   // 8448

#define NEG_LOG320 (-5.768320995793772f)
#define LOGA_LAST  (-0.510825623765991f)

// ---------------- scratch ----------------
__device__ __half g_xth[B_SZ * N_TOK * C_DIM];   // x^T fp16: [b][n][k]
__device__ __half g_hth[B_SZ * N_TOK * 1024];    // hidden^T fp16: [b][n][o]
__device__ __half g_w1h[1024 * C_DIM];           // [Wc1;Ws1] fp16
__device__ __half g_w2h[256 * HIDD];             // rows 0-127 Wc2, 128-191 Ws2, rest 0
__device__ float  g_f[B_SZ * L_DIM * N_TOK];
__device__ float  g_s[B_SZ * M_CL * N_TOK];
__device__ float  g_p[B_SZ * M_CL * N_TOK];

// ---------------- helpers ----------------
#define CP_ASYNC16(smem_u32, gptr) \
    asm volatile("cp.async.cg.shared.global [%0], [%1], 16;" :: "r"(smem_u32), "l"(gptr))
#define CP_COMMIT() asm volatile("cp.async.commit_group;")
#define CP_WAIT1()  asm volatile("cp.async.wait_group 1;")

__device__ __forceinline__ void ldsm_x4(uint32_t& r0, uint32_t& r1, uint32_t& r2, uint32_t& r3,
                                        uint32_t addr) {
    asm volatile("ldmatrix.sync.aligned.m8n8.x4.shared.b16 {%0,%1,%2,%3}, [%4];"
        : "=r"(r0), "=r"(r1), "=r"(r2), "=r"(r3) : "r"(addr));
}

__device__ __forceinline__ void mma_f16(float* d, const uint32_t* a, const uint32_t* b) {
    asm volatile(
        "mma.sync.aligned.m16n8k16.row.col.f32.f16.f16.f32 "
        "{%0,%1,%2,%3}, {%4,%5,%6,%7}, {%8,%9}, {%0,%1,%2,%3};"
        : "+f"(d[0]), "+f"(d[1]), "+f"(d[2]), "+f"(d[3])
        : "r"(a[0]), "r"(a[1]), "r"(a[2]), "r"(a[3]), "r"(b[0]), "r"(b[1]));
}

// smem geometry: rows of 32 halves + 8 pad -> stride 40 halves (80 B), conflict-free ldsm
#define HTS          40
#define HROW_BYTES   80
#define HSTAGE_BYTES (128 * HROW_BYTES)           // 10240 per operand per stage
#define HGEMM_SMEM   (4 * HSTAGE_BYTES)           // 40960 B

// ==========================================================================
// Prepass A: weights -> fp16 copies
// ==========================================================================
__global__ __launch_bounds__(256) void p_weights(
    const float* __restrict__ Wc1, const float* __restrict__ Ws1,
    const float* __restrict__ Wc2, const float* __restrict__ Ws2)
{
    const int total1 = 1024 * C_DIM;
    const int total2 = 256 * HIDD;
    for (int idx = blockIdx.x * 256 + threadIdx.x; idx < total1 + total2;
         idx += gridDim.x * 256) {
        if (idx < total1) {
            float v = (idx < 512 * C_DIM) ? Wc1[idx] : Ws1[idx - 512 * C_DIM];
            g_w1h[idx] = __float2half_rn(v);
        } else {
            int j = idx - total1;
            int row = j / HIDD;
            float v = (row < 128) ? Wc2[j]
                    : (row < 192) ? Ws2[j - 128 * HIDD] : 0.f;
            g_w2h[j] = __float2half_rn(v);
        }
    }
}

// ==========================================================================
// Prepass B: x[b][c][n] -> g_xth[b][n][c] fp16 (32x32 smem transpose)
// grid (48 c-tiles, 8 n-tiles, 64)
// ==========================================================================
__global__ __launch_bounds__(256) void p_xt(const float* __restrict__ x)
{
    __shared__ float sm[32][33];
    const int b  = blockIdx.z;
    const int ct = blockIdx.x * 32;
    const int nt = blockIdx.y * 32;
    const int tx = threadIdx.x & 31;
    const int ty = threadIdx.x >> 5;

#pragma unroll
    for (int i = 0; i < 4; i++) {
        int c = ct + ty + i * 8;
        sm[ty + i * 8][tx] = x[((size_t)b * C_DIM + c) * N_TOK + nt + tx];
    }
    __syncthreads();
#pragma unroll
    for (int i = 0; i < 4; i++) {
        int n = nt + ty + i * 8;
        g_xth[((size_t)b * N_TOK + n) * C_DIM + ct + tx] = __float2half_rn(sm[tx][ty + i * 8]);
    }
}

// ==========================================================================
// Kernel 1 (fp16 mma.sync, M<->N swapped): h^T[n][o] = relu(x^T @ W1^T + b1)
// A = tokens (M=128), B = weight rows (N=128), BK=32; 8 warps (2m x 4n),
// warp tile 64x32; m16n8k16.  Output is naturally [token][o] -> coalesced
// half2 stores into g_hth[b][n][o].
// grid (2 nt_tok, 8 mt, 64 b)
// ==========================================================================
__global__ __launch_bounds__(256, 2) void k1_mma(
    const float* __restrict__ bc1, const float* __restrict__ bs1)
{
    extern __shared__ __half smh[];
    const uint32_t As_u = (uint32_t)__cvta_generic_to_shared(smh);
    const uint32_t Bs_u = As_u + 2 * HSTAGE_BYTES;

    const int b  = blockIdx.z;
    const int mt = blockIdx.y;   // weight-row tile 0..7
    const int nt = blockIdx.x;   // token tile 0..1

    const __half* Atok = g_xth + ((size_t)b * N_TOK + nt * 128) * C_DIM;   // tokens (M)
    const __half* Bw   = g_w1h + (size_t)mt * 128 * C_DIM;                 // weights (N)
    const float*  bias = (mt < 4) ? (bc1 + mt * 128) : (bs1 + (mt - 4) * 128);

    const int tid  = threadIdx.x;
    const int warp = tid >> 5, lane = tid & 31;
    const int g = lane >> 2, t = lane & 3;
    const int wm = warp >> 2, wn = warp & 3;   // 2 (token) x 4 (channel)

    const int lrow = lane & 15;
    const int lcol = (lane >> 4) * 8;

    const uint32_t a_base = As_u + (uint32_t)((wm * 64 + lrow) * HTS + lcol) * 2u;
    const uint32_t b_base = Bs_u + (uint32_t)((wn * 32 + lrow) * HTS + lcol) * 2u;

    const int ld_row = tid >> 2;   // 0..63, +64 on second iter
    const int ld_c   = tid & 3;

    float acc[4][4][4];
#pragma unroll
    for (int i = 0; i < 4; i++)
#pragma unroll
        for (int j = 0; j < 4; j++)
#pragma unroll
            for (int q = 0; q < 4; q++) acc[i][j][q] = 0.f;

#define K1_LOAD(buf, kt)                                                             \
    do {                                                                             \
        const int k0_ = (kt) * 32;                                                   \
        _Pragma("unroll")                                                            \
        for (int it = 0; it < 2; it++) {                                             \
            int row = ld_row + it * 64;                                              \
            uint32_t so = (uint32_t)(row * HTS + ld_c * 8) * 2u + (buf) * HSTAGE_BYTES; \
            CP_ASYNC16(As_u + so, Atok + (size_t)row * C_DIM + k0_ + ld_c * 8);      \
            CP_ASYNC16(Bs_u + so, Bw   + (size_t)row * C_DIM + k0_ + ld_c * 8);      \
        }                                                                            \
    } while (0)

    const int KT = C_DIM / 32;   // 48
    K1_LOAD(0, 0);
    CP_COMMIT();

    for (int kt = 0; kt < KT; kt++) {
        if (kt + 1 < KT) K1_LOAD((kt + 1) & 1, kt + 1);
        CP_COMMIT();
        CP_WAIT1();
        __syncthreads();

        const uint32_t abuf = a_base + (kt & 1) * HSTAGE_BYTES;
        const uint32_t bbuf = b_base + (kt & 1) * HSTAGE_BYTES;

#pragma unroll
        for (int kk = 0; kk < 2; kk++) {   // two k16 steps per BK=32
            uint32_t af[4][4];
#pragma unroll
            for (int mi = 0; mi < 4; mi++)
                ldsm_x4(af[mi][0], af[mi][1], af[mi][2], af[mi][3],
                        abuf + mi * (16 * HROW_BYTES) + kk * 32);
            uint32_t bf[4][2];
#pragma unroll
            for (int nip = 0; nip < 2; nip++) {
                uint32_t r0, r1, r2, r3;
                ldsm_x4(r0, r1, r2, r3, bbuf + nip * (16 * HROW_BYTES) + kk * 32);
                bf[2 * nip + 0][0] = r0; bf[2 * nip + 0][1] = r2;
                bf[2 * nip + 1][0] = r1; bf[2 * nip + 1][1] = r3;
            }
#pragma unroll
            for (int mi = 0; mi < 4; mi++)
#pragma unroll
                for (int ni = 0; ni < 4; ni++)
                    mma_f16(acc[mi][ni], af[mi], bf[ni]);
        }
        __syncthreads();
    }

    // epilogue: bias (per channel col) + relu -> half2, coalesced stores along o
    float bvv[4][2];
#pragma unroll
    for (int ni = 0; ni < 4; ni++) {
        int col = wn * 32 + ni * 8 + t * 2;
        bvv[ni][0] = __ldg(bias + col);
        bvv[ni][1] = __ldg(bias + col + 1);
    }
    __half* Ob = g_hth + ((size_t)b * N_TOK + nt * 128) * 1024 + mt * 128;
#pragma unroll
    for (int mi = 0; mi < 4; mi++) {
#pragma unroll
        for (int q2 = 0; q2 < 2; q2++) {
            int row = wm * 64 + mi * 16 + q2 * 8 + g;   // token within tile
            __half* Orow = Ob + (size_t)row * 1024;
#pragma unroll
            for (int ni = 0; ni < 4; ni++) {
                int col = wn * 32 + ni * 8 + t * 2;
                __half2 hv = __floats2half2_rn(
                    fmaxf(acc[mi][ni][q2 * 2 + 0] + bvv[ni][0], 0.f),
                    fmaxf(acc[mi][ni][q2 * 2 + 1] + bvv[ni][1], 0.f));
                *(__half2*)(Orow + col) = hv;
            }
        }
    }
}

// ==========================================================================
// Kernel 2 (fp16 mma.sync): f = Wc2 @ h1 + bc2 ; s = Ws2 @ h2 + bs2
// grid (2 nt, 2 mt, 64 b); KT=16.  (unchanged — consumes g_hth[b][n][o])
// ==========================================================================
__global__ __launch_bounds__(256, 2) void k2_mma(
    const float* __restrict__ bc2, const float* __restrict__ bs2)
{
    extern __shared__ __half smh[];
    const uint32_t As_u = (uint32_t)__cvta_generic_to_shared(smh);
    const uint32_t Bs_u = As_u + 2 * HSTAGE_BYTES;

    const int b  = blockIdx.z;
    const int mt = blockIdx.y;
    const int nt = blockIdx.x;

    const __half* A    = g_w2h + (size_t)mt * 128 * HIDD;
    const __half* Bsrc = g_hth + ((size_t)b * N_TOK + nt * 128) * 1024 + mt * 512;

    const int tid  = threadIdx.x;
    const int warp = tid >> 5, lane = tid & 31;
    const int g = lane >> 2, t = lane & 3;
    const int wm = warp >> 2, wn = warp & 3;

    const int lrow = lane & 15;
    const int lcol = (lane >> 4) * 8;

    const uint32_t a_base = As_u + (uint32_t)((wm * 64 + lrow) * HTS + lcol) * 2u;
    const uint32_t b_base = Bs_u + (uint32_t)((wn * 32 + lrow) * HTS + lcol) * 2u;

    const int ld_row = tid >> 2;
    const int ld_c   = tid & 3;

    float acc[4][4][4];
#pragma unroll
    for (int i = 0; i < 4; i++)
#pragma unroll
        for (int j = 0; j < 4; j++)
#pragma unroll
            for (int q = 0; q < 4; q++) acc[i][j][q] = 0.f;

#define K2_LOAD(buf, kt)                                                             \
    do {                                                                             \
        const int k0_ = (kt) * 32;                                                   \
        _Pragma("unroll")                                                            \
        for (int it = 0; it < 2; it++) {                                             \
            int row = ld_row + it * 64;                                              \
            uint32_t so = (uint32_t)(row * HTS + ld_c * 8) * 2u + (buf) * HSTAGE_BYTES; \
            CP_ASYNC16(As_u + so, A + (size_t)row * HIDD + k0_ + ld_c * 8);          \
            CP_ASYNC16(Bs_u + so, Bsrc + (size_t)row * 1024 + k0_ + ld_c * 8);       \
        }                                                                            \
    } while (0)

    const int KT = HIDD / 32;   // 16
    K2_LOAD(0, 0);
    CP_COMMIT();

    for (int kt = 0; kt < KT; kt++) {
        if (kt + 1 < KT) K2_LOAD((kt + 1) & 1, kt + 1);
        CP_COMMIT();
        CP_WAIT1();
        __syncthreads();

        const uint32_t abuf = a_base + (kt & 1) * HSTAGE_BYTES;
        const uint32_t bbuf = b_base + (kt & 1) * HSTAGE_BYTES;

#pragma unroll
        for (int kk = 0; kk < 2; kk++) {
            uint32_t af[4][4];
#pragma unroll
            for (int mi = 0; mi < 4; mi++)
                ldsm_x4(af[mi][0], af[mi][1], af[mi][2], af[mi][3],
                        abuf + mi * (16 * HROW_BYTES) + kk * 32);
            uint32_t bf[4][2];
#pragma unroll
            for (int nip = 0; nip < 2; nip++) {
                uint32_t r0, r1, r2, r3;
                ldsm_x4(r0, r1, r2, r3, bbuf + nip * (16 * HROW_BYTES) + kk * 32);
                bf[2 * nip + 0][0] = r0; bf[2 * nip + 0][1] = r2;
                bf[2 * nip + 1][0] = r1; bf[2 * nip + 1][1] = r3;
            }
#pragma unroll
            for (int mi = 0; mi < 4; mi++)
#pragma unroll
                for (int ni = 0; ni < 4; ni++)
                    mma_f16(acc[mi][ni], af[mi], bf[ni]);
        }
        __syncthreads();
    }

#pragma unroll
    for (int mi = 0; mi < 4; mi++) {
#pragma unroll
        for (int q2 = 0; q2 < 2; q2++) {
            int row = wm * 64 + mi * 16 + q2 * 8 + g;
            if (mt == 0) {
                float bv = __ldg(bc2 + row);
#pragma unroll
                for (int ni = 0; ni < 4; ni++) {
                    int col = nt * 128 + wn * 32 + ni * 8 + t * 2;
                    float2 v;
                    v.x = acc[mi][ni][q2 * 2 + 0] + bv;
                    v.y = acc[mi][ni][q2 * 2 + 1] + bv;
                    *(float2*)(g_f + ((size_t)b * L_DIM + row) * N_TOK + col) = v;
                }
            } else if (row < 64) {
                float bv = __ldg(bs2 + row);
#pragma unroll
                for (int ni = 0; ni < 4; ni++) {
                    int col = nt * 128 + wn * 32 + ni * 8 + t * 2;
                    float2 v;
                    v.x = acc[mi][ni][q2 * 2 + 0] + bv;
                    v.y = acc[mi][ni][q2 * 2 + 1] + bv;
                    *(float2*)(g_s + ((size_t)b * M_CL + row) * N_TOK + col) = v;
                }
            }
        }
    }
}

// ==========================================================================
// Kernel 3: token MLP + L2 norm -> out[b][0:256]
// ==========================================================================
__global__ __launch_bounds__(256) void k3_token(
    const float* __restrict__ t,
    const float* __restrict__ Wt1, const float* __restrict__ bt1,
    const float* __restrict__ Wt2, const float* __restrict__ bt2,
    float* __restrict__ out)
{
    __shared__ float ts[C_DIM];
    __shared__ float th[HIDD];
    __shared__ float red[8];

    const int b   = blockIdx.x;
    const int tid = threadIdx.x;

    for (int i = tid; i < C_DIM; i += 256) ts[i] = t[(size_t)b * C_DIM + i];
    __syncthreads();

    for (int o = tid; o < HIDD; o += 256) {
        const float* wr = Wt1 + (size_t)o * C_DIM;
        float a0 = 0.f, a1 = 0.f, a2 = 0.f, a3 = 0.f;
        for (int c = 0; c < C_DIM; c += 4) {
            a0 += wr[c + 0] * ts[c + 0];
            a1 += wr[c + 1] * ts[c + 1];
            a2 += wr[c + 2] * ts[c + 2];
            a3 += wr[c + 3] * ts[c + 3];
        }
        th[o] = fmaxf((a0 + a1) + (a2 + a3) + bt1[o], 0.f);
    }
    __syncthreads();

    float val;
    {
        const float* wr = Wt2 + (size_t)tid * HIDD;
        float a0 = 0.f, a1 = 0.f, a2 = 0.f, a3 = 0.f;
        for (int c = 0; c < HIDD; c += 4) {
            a0 += wr[c + 0] * th[c + 0];
            a1 += wr[c + 1] * th[c + 1];
            a2 += wr[c + 2] * th[c + 2];
            a3 += wr[c + 3] * th[c + 3];
        }
        val = (a0 + a1) + (a2 + a3) + bt2[tid];
    }

    float ss = val * val;
#pragma unroll
    for (int off = 16; off; off >>= 1) ss += __shfl_xor_sync(0xffffffffu, ss, off);
    if ((tid & 31) == 0) red[tid >> 5] = ss;
    __syncthreads();
    float tot = 0.f;
#pragma unroll
    for (int i = 0; i < 8; i++) tot += red[i];
    float sc = 1.f / fmaxf(sqrtf(tot), 1e-12f);
    out[(size_t)b * OUT_PER_B + tid] = val * sc;
}

// ==========================================================================
// Kernel 4: Sinkhorn -> g_p
// ==========================================================================
__global__ __launch_bounds__(256) void k4_sinkhorn(const float* __restrict__ dustp)
{
    extern __shared__ float sh[];
    float* Ms = sh;
    float* u  = sh + 65 * 256;
    float* v  = u + 72;

    const int b   = blockIdx.x;
    const int tid = threadIdx.x;
    const float dust = *dustp;
    const float* S = g_s + (size_t)b * M_CL * N_TOK;

    for (int i = tid; i < 64 * 256; i += 256) Ms[i] = S[i];
    Ms[64 * 256 + tid] = dust;
    v[tid] = 0.f;
    __syncthreads();

    const int w    = tid >> 5;
    const int lane = tid & 31;

    for (int it = 0; it < 3; it++) {
        for (int r = w; r < 65; r += 8) {
            float vals[8];
            float mx = -INFINITY;
#pragma unroll
            for (int q = 0; q < 8; q++) {
                float vv = Ms[r * 256 + lane + 32 * q] + v[lane + 32 * q];
                vals[q] = vv;
                mx = fmaxf(mx, vv);
            }
#pragma unroll
            for (int off = 16; off; off >>= 1)
                mx = fmaxf(mx, __shfl_xor_sync(0xffffffffu, mx, off));
            float ssum = 0.f;
#pragma unroll
            for (int q = 0; q < 8; q++) ssum += expf(vals[q] - mx);
#pragma unroll
            for (int off = 16; off; off >>= 1)
                ssum += __shfl_xor_sync(0xffffffffu, ssum, off);
            if (lane == 0) {
                float la = (r == 64) ? LOGA_LAST : NEG_LOG320;
                u[r] = la - (mx + logf(ssum));
            }
        }
        __syncthreads();
        {
            float mrun = -INFINITY, srun = 0.f;
            for (int m = 0; m < 65; m++) {
                float vv = Ms[m * 256 + tid] + u[m];
                if (vv > mrun) {
                    srun = srun * expf(mrun - vv) + 1.f;
                    mrun = vv;
                } else {
                    srun += expf(vv - mrun);
                }
            }
            v[tid] = NEG_LOG320 - (mrun + logf(srun));
        }
        __syncthreads();
    }

    float* P = g_p + (size_t)b * M_CL * N_TOK;
    for (int i = tid; i < 64 * 256; i += 256) {
        int m = i >> 8, j = i & 255;
        P[i] = expf(Ms[i] + u[m] + v[j] - NEG_LOG320);
    }
}

// ==========================================================================
// Kernel 5: VLAD + intra-norm
// ==========================================================================
#define PS_LD 260
__global__ __launch_bounds__(256) void k5_vlad(float* __restrict__ out)
{
    extern __shared__ float sh[];
    float* ps  = sh;
    float* vs  = sh + 64 * PS_LD;
    float* inv = vs + 128 * 64;

    const int b   = blockIdx.x;
    const int tid = threadIdx.x;
    const float* P = g_p + (size_t)b * M_CL * N_TOK;
    const float* F = g_f + (size_t)b * L_DIM * N_TOK;

    for (int i = tid; i < 64 * 256; i += 256) {
        int m = i >> 8, n = i & 255;
        ps[m * PS_LD + n] = P[i];
    }
    __syncthreads();

    const int m  = tid & 63;
    const int lg = tid >> 6;

    const float4* pr = (const float4*)(ps + m * PS_LD);

    float acc[32];
#pragma unroll
    for (int i = 0; i < 32; i++) acc[i] = 0.f;

    for (int nc = 0; nc < 64; nc += 4) {
        float4 pv0 = pr[nc + 0], pv1 = pr[nc + 1], pv2 = pr[nc + 2], pv3 = pr[nc + 3];
#pragma unroll
        for (int li = 0; li < 32; li++) {
            const float4* fr = (const float4*)(F + (size_t)(lg * 32 + li) * N_TOK);
            float4 f0 = fr[nc + 0], f1 = fr[nc + 1], f2 = fr[nc + 2], f3 = fr[nc + 3];
            float a = acc[li];
            a += f0.x * pv0.x + f0.y * pv0.y + f0.z * pv0.z + f0.w * pv0.w;
            a += f1.x * pv1.x + f1.y * pv1.y + f1.z * pv1.z + f1.w * pv1.w;
            a += f2.x * pv2.x + f2.y * pv2.y + f2.z * pv2.z + f2.w * pv2.w;
            a += f3.x * pv3.x + f3.y * pv3.y + f3.z * pv3.z + f3.w * pv3.w;
            acc[li] = a;
        }
    }
#pragma unroll
    for (int li = 0; li < 32; li++) vs[(lg * 32 + li) * 64 + m] = acc[li];
    __syncthreads();

    if (tid < 64) {
        float ss = 0.f;
        for (int l = 0; l < 128; l++) {
            float vv = vs[l * 64 + tid];
            ss += vv * vv;
        }
        inv[tid] = 1.f / fmaxf(sqrtf(ss), 1e-12f);
    }
    __syncthreads();

    float* Ob = out + (size_t)b * OUT_PER_B + G_DIM;
    for (int i = tid; i < L_DIM * M_CL; i += 256) Ob[i] = vs[i] * inv[i & 63];
}

// ==========================================================================
// Kernel 6: final L2 norm
// ==========================================================================
__global__ __launch_bounds__(256) void k6_norm(float* __restrict__ out)
{
    __shared__ float red[8];
    __shared__ float sc_s;
    const int b   = blockIdx.x;
    const int tid = threadIdx.x;
    float* O = out + (size_t)b * OUT_PER_B;

    float ss = 0.f;
    for (int i = tid; i < OUT_PER_B; i += 256) {
        float vv = O[i];
        ss += vv * vv;
    }
#pragma unroll
    for (int off = 16; off; off >>= 1) ss += __shfl_xor_sync(0xffffffffu, ss, off);
    if ((tid & 31) == 0) red[tid >> 5] = ss;
    __syncthreads();
    if (tid == 0) {
        float tot = 0.f;
#pragma unroll
        for (int i = 0; i < 8; i++) tot += red[i];
        sc_s = 1.f / fmaxf(sqrtf(tot), 1e-12f);
    }
    __syncthreads();
    float sc = sc_s;
    for (int i = tid; i < OUT_PER_B; i += 256) O[i] *= sc;
}

// ==========================================================================
// launch
// ==========================================================================
extern "C" void kernel_launch(void* const* d_in, const int* in_sizes, int n_in,
                              void* d_out, int out_size)
{
    (void)in_sizes; (void)n_in; (void)out_size;
    const float* x    = (const float*)d_in[0];
    const float* t    = (const float*)d_in[1];
    const float* Wt1  = (const float*)d_in[2];
    const float* bt1  = (const float*)d_in[3];
    const float* Wt2  = (const float*)d_in[4];
    const float* bt2  = (const float*)d_in[5];
    const float* Wc1  = (const float*)d_in[6];
    const float* bc1  = (const float*)d_in[7];
    const float* Wc2  = (const float*)d_in[8];
    const float* bc2  = (const float*)d_in[9];
    const float* Ws1  = (const float*)d_in[10];
    const float* bs1  = (const float*)d_in[11];
    const float* Ws2  = (const float*)d_in[12];
    const float* bs2  = (const float*)d_in[13];
    const float* dust = (const float*)d_in[14];
    float* out = (float*)d_out;

    const int sink_smem = (65 * 256 + 72 + 256) * (int)sizeof(float);
    const int vlad_smem = (64 * PS_LD + 128 * 64 + 64) * (int)sizeof(float);
    cudaFuncSetAttribute(k1_mma,      cudaFuncAttributeMaxDynamicSharedMemorySize, HGEMM_SMEM);
    cudaFuncSetAttribute(k2_mma,      cudaFuncAttributeMaxDynamicSharedMemorySize, HGEMM_SMEM);
    cudaFuncSetAttribute(k4_sinkhorn, cudaFuncAttributeMaxDynamicSharedMemorySize, sink_smem);
    cudaFuncSetAttribute(k5_vlad,     cudaFuncAttributeMaxDynamicSharedMemorySize, vlad_smem);

    p_weights<<<512, 256>>>(Wc1, Ws1, Wc2, Ws2);
    p_xt<<<dim3(48, 8, B_SZ), 256>>>(x);
    k1_mma<<<dim3(2, 8, B_SZ), 256, HGEMM_SMEM>>>(bc1, bs1);
    k2_mma<<<dim3(2, 2, B_SZ), 256, HGEMM_SMEM>>>(bc2, bs2);
    k3_token<<<B_SZ, 256>>>(t, Wt1, bt1, Wt2, bt2, out);
    k4_sinkhorn<<<B_SZ, 256, sink_smem>>>(dust);
    k5_vlad<<<B_SZ, 256, vlad_smem>>>(out);
    k6_norm<<<B_SZ, 256>>>(out);
}

// round 7
// speedup vs baseline: 2.4917x; 1.0766x over previous
#include <cuda_runtime.h>
#include <cuda_fp16.h>
#include <math.h>
#include <stdint.h>

// ---------------- problem constants ----------------
#define B_SZ   64
#define C_DIM  1536
#define N_TOK  256
#define HIDD   512
#define L_DIM  128
#define G_DIM  256
#define M_CL   64
#define OUT_PER_B (G_DIM + L_DIM * M_CL)   // 8448

#define NEG_LOG320 (-5.768320995793772f)
#define LOGA_LAST  (-0.510825623765991f)

// blocked tile: 128 rows x 40 halves (32 data + 8 pad) = 5120 halves = 10240 B
#define BLK_H   5120
#define BLK_B   10240

// ---------------- scratch (blocked, pre-padded layouts) ----------------
__device__ __half g_xb [B_SZ * 2 * 48 * BLK_H];   // x^T blocked: [(b*2+nt)*48+kt]
__device__ __half g_hb [B_SZ * 2 * 32 * BLK_H];   // hidden blocked: [(b*2+nt)*32+oblk]
__device__ __half g_w1b[8 * 48 * BLK_H];          // [Wc1;Ws1] blocked: [mt*48+kt]
__device__ __half g_w2b[2 * 16 * BLK_H];          // [Wc2;Ws2pad] blocked: [mt*16+kt]
__device__ float  g_f[B_SZ * L_DIM * N_TOK];
__device__ float  g_s[B_SZ * M_CL * N_TOK];
__device__ float  g_p[B_SZ * M_CL * N_TOK];

// ---------------- helpers ----------------
__device__ __forceinline__ void ldsm_x4(uint32_t& r0, uint32_t& r1, uint32_t& r2, uint32_t& r3,
                                        uint32_t addr) {
    asm volatile("ldmatrix.sync.aligned.m8n8.x4.shared.b16 {%0,%1,%2,%3}, [%4];"
        : "=r"(r0), "=r"(r1), "=r"(r2), "=r"(r3) : "r"(addr));
}

__device__ __forceinline__ void mma_f16(float* d, const uint32_t* a, const uint32_t* b) {
    asm volatile(
        "mma.sync.aligned.m16n8k16.row.col.f32.f16.f16.f32 "
        "{%0,%1,%2,%3}, {%4,%5,%6,%7}, {%8,%9}, {%0,%1,%2,%3};"
        : "+f"(d[0]), "+f"(d[1]), "+f"(d[2]), "+f"(d[3])
        : "r"(a[0]), "r"(a[1]), "r"(a[2]), "r"(a[3]), "r"(b[0]), "r"(b[1]));
}

#define MBAR_INIT(mbar, cnt) \
    asm volatile("mbarrier.init.shared.b64 [%0], %1;" :: "r"(mbar), "r"((uint32_t)(cnt)) : "memory")
#define MBAR_EXPECT_TX(mbar, bytes) \
    asm volatile("mbarrier.arrive.expect_tx.shared.b64 _, [%0], %1;" \
                 :: "r"(mbar), "r"((uint32_t)(bytes)) : "memory")
#define BULK_G2S(dst_smem, gsrc, bytes, mbar) \
    asm volatile("cp.async.bulk.shared::cta.global.mbarrier::complete_tx::bytes [%0], [%1], %2, [%3];" \
                 :: "r"(dst_smem), "l"(gsrc), "r"((uint32_t)(bytes)), "r"(mbar) : "memory")

__device__ __forceinline__ void mbar_wait(uint32_t mbar, uint32_t parity) {
    asm volatile(
        "{\n\t.reg .pred P1;\n\t"
        "WAIT_LOOP_%=:\n\t"
        "mbarrier.try_wait.parity.acquire.cta.shared::cta.b64 P1, [%0], %1, 0x989680;\n\t"
        "@P1 bra.uni WAIT_DONE_%=;\n\t"
        "bra.uni WAIT_LOOP_%=;\n\t"
        "WAIT_DONE_%=:\n\t}"
        :: "r"(mbar), "r"(parity) : "memory");
}

// smem geometry: rows of 32 halves + 8 pad -> stride 40 halves, conflict-free ldsm
#define HTS       40
#define NS        4                  // pipeline stages
#define STG_BYTES (2 * BLK_B)        // A + B per stage = 20480
#define GEMM_SMEM (1024 + NS * STG_BYTES)   // barriers @0, stages @1024 -> 82944 B

// ==========================================================================
// Prepass A: weights -> fp16 blocked layouts
// ==========================================================================
__global__ __launch_bounds__(256) void p_weights(
    const float* __restrict__ Wc1, const float* __restrict__ Ws1,
    const float* __restrict__ Wc2, const float* __restrict__ Ws2)
{
    const int total1 = 1024 * C_DIM;
    const int total2 = 256 * HIDD;
    for (int idx = blockIdx.x * 256 + threadIdx.x; idx < total1 + total2;
         idx += gridDim.x * 256) {
        if (idx < total1) {
            int o = idx / C_DIM, k = idx - o * C_DIM;
            float v = (o < 512) ? Wc1[idx] : Ws1[idx - 512 * C_DIM];
            g_w1b[(size_t)((o >> 7) * 48 + (k >> 5)) * BLK_H + (o & 127) * HTS + (k & 31)]
                = __float2half_rn(v);
        } else {
            int j = idx - total1;
            int o = j >> 9, k = j & 511;
            float v = (o < 128) ? Wc2[j]
                    : (o < 192) ? Ws2[j - 128 * HIDD] : 0.f;
            g_w2b[(size_t)((o >> 7) * 16 + (k >> 5)) * BLK_H + (o & 127) * HTS + (k & 31)]
                = __float2half_rn(v);
        }
    }
}

// ==========================================================================
// Prepass B: x[b][c][n] -> blocked g_xb (transpose + fp16)
// grid (48 c-tiles, 8 n-tiles, 64)
// ==========================================================================
__global__ __launch_bounds__(256) void p_xt(const float* __restrict__ x)
{
    __shared__ float sm[32][33];
    const int b  = blockIdx.z;
    const int ct = blockIdx.x * 32;
    const int nt = blockIdx.y * 32;
    const int tx = threadIdx.x & 31;
    const int ty = threadIdx.x >> 5;

#pragma unroll
    for (int i = 0; i < 4; i++) {
        int c = ct + ty + i * 8;
        sm[ty + i * 8][tx] = x[((size_t)b * C_DIM + c) * N_TOK + nt + tx];
    }
    __syncthreads();
    // write: row n = nt+ty+i*8, channel cg = ct+tx
    const int kt = ct >> 5;   // ct is 32-aligned, tx<32 -> block col fixed
#pragma unroll
    for (int i = 0; i < 4; i++) {
        int n = nt + ty + i * 8;
        size_t dst = (size_t)(((b * 2) + (n >> 7)) * 48 + kt) * BLK_H
                   + (n & 127) * HTS + tx;
        g_xb[dst] = __float2half_rn(sm[tx][ty + i * 8]);
    }
}

// ==========================================================================
// Kernel 1 (fp16 mma.sync + bulk-copy pipeline): h[n][o] = relu(x^T W1^T + b1)
// A = tokens (M=128), B = weight rows (N=128), BK=32, NS=4 stages.
// Output blocked into g_hb. grid (2 nt, 8 mt, 64 b), 256 thr, 2 CTA/SM.
// ==========================================================================
__global__ __launch_bounds__(256, 2) void k1_mma(
    const float* __restrict__ bc1, const float* __restrict__ bs1)
{
    extern __shared__ __half smh[];
    const uint32_t sbase = (uint32_t)__cvta_generic_to_shared(smh);
    const uint32_t mb    = sbase;          // full[s] @ sbase + 8*s
    const uint32_t st0   = sbase + 1024;

    const int b  = blockIdx.z;
    const int mt = blockIdx.y;   // weight-row tile 0..7
    const int nt = blockIdx.x;   // token tile 0..1

    const __half* Asrc = g_xb  + (size_t)((b * 2 + nt) * 48) * BLK_H;   // +kt*BLK_H
    const __half* Bsrc = g_w1b + (size_t)(mt * 48) * BLK_H;
    const float*  bias = (mt < 4) ? (bc1 + mt * 128) : (bs1 + (mt - 4) * 128);

    const int tid  = threadIdx.x;
    const int warp = tid >> 5, lane = tid & 31;
    const int g = lane >> 2, t = lane & 3;
    const int wm = warp >> 2, wn = warp & 3;   // 2 (token) x 4 (channel)

    const int lrow = lane & 15;
    const int lcol = (lane >> 4) * 8;

    const uint32_t a_base = st0 + (uint32_t)((wm * 64 + lrow) * HTS + lcol) * 2u;
    const uint32_t b_base = st0 + BLK_B + (uint32_t)((wn * 32 + lrow) * HTS + lcol) * 2u;

    if (tid == 0) {
#pragma unroll
        for (int s = 0; s < NS; s++) MBAR_INIT(mb + 8 * s, 1);
    }
    __syncthreads();
    if (tid == 0) {
#pragma unroll
        for (int s = 0; s < NS; s++) {
            MBAR_EXPECT_TX(mb + 8 * s, STG_BYTES);
            BULK_G2S(st0 + s * STG_BYTES,         Asrc + (size_t)s * BLK_H, BLK_B, mb + 8 * s);
            BULK_G2S(st0 + s * STG_BYTES + BLK_B, Bsrc + (size_t)s * BLK_H, BLK_B, mb + 8 * s);
        }
    }

    float acc[4][4][4];
#pragma unroll
    for (int i = 0; i < 4; i++)
#pragma unroll
        for (int j = 0; j < 4; j++)
#pragma unroll
            for (int q = 0; q < 4; q++) acc[i][j][q] = 0.f;

    const int KT = C_DIM / 32;   // 48
    for (int kt = 0; kt < KT; kt++) {
        const int s = kt & (NS - 1);
        const uint32_t parity = (kt >> 2) & 1;
        mbar_wait(mb + 8 * s, parity);

        const uint32_t abuf = a_base + s * STG_BYTES;
        const uint32_t bbuf = b_base + s * STG_BYTES;

#pragma unroll
        for (int kk = 0; kk < 2; kk++) {   // two k16 steps per BK=32
            uint32_t af[4][4];
#pragma unroll
            for (int mi = 0; mi < 4; mi++)
                ldsm_x4(af[mi][0], af[mi][1], af[mi][2], af[mi][3],
                        abuf + mi * (16 * HTS * 2) + kk * 32);
            uint32_t bf[4][2];
#pragma unroll
            for (int nip = 0; nip < 2; nip++) {
                uint32_t r0, r1, r2, r3;
                ldsm_x4(r0, r1, r2, r3, bbuf + nip * (16 * HTS * 2) + kk * 32);
                bf[2 * nip + 0][0] = r0; bf[2 * nip + 0][1] = r2;
                bf[2 * nip + 1][0] = r1; bf[2 * nip + 1][1] = r3;
            }
#pragma unroll
            for (int mi = 0; mi < 4; mi++)
#pragma unroll
                for (int ni = 0; ni < 4; ni++)
                    mma_f16(acc[mi][ni], af[mi], bf[ni]);
        }
        __syncthreads();   // all warps done reading stage s
        if (tid == 0 && kt + NS < KT) {
            const int kn = kt + NS;
            MBAR_EXPECT_TX(mb + 8 * s, STG_BYTES);
            BULK_G2S(st0 + s * STG_BYTES,         Asrc + (size_t)kn * BLK_H, BLK_B, mb + 8 * s);
            BULK_G2S(st0 + s * STG_BYTES + BLK_B, Bsrc + (size_t)kn * BLK_H, BLK_B, mb + 8 * s);
        }
    }

    // epilogue: bias (per channel col) + relu -> half2, blocked store into g_hb
    float bvv[4][2];
#pragma unroll
    for (int ni = 0; ni < 4; ni++) {
        int col = wn * 32 + ni * 8 + t * 2;
        bvv[ni][0] = __ldg(bias + col);
        bvv[ni][1] = __ldg(bias + col + 1);
    }
    // block index: (b*2+nt)*32 + (mt*4 + wn)
    __half* Ob = g_hb + (size_t)((b * 2 + nt) * 32 + mt * 4 + wn) * BLK_H;
#pragma unroll
    for (int mi = 0; mi < 4; mi++) {
#pragma unroll
        for (int q2 = 0; q2 < 2; q2++) {
            int row = wm * 64 + mi * 16 + q2 * 8 + g;   // token within tile
#pragma unroll
            for (int ni = 0; ni < 4; ni++) {
                int c = ni * 8 + t * 2;
                __half2 hv = __floats2half2_rn(
                    fmaxf(acc[mi][ni][q2 * 2 + 0] + bvv[ni][0], 0.f),
                    fmaxf(acc[mi][ni][q2 * 2 + 1] + bvv[ni][1], 0.f));
                *(__half2*)(Ob + row * HTS + c) = hv;
            }
        }
    }
}

// ==========================================================================
// Kernel 2 (fp16 mma.sync + bulk pipeline): f = Wc2 h1 + bc2 ; s = Ws2 h2 + bs2
// A = weights (M=128), B = tokens from g_hb (N=128), KT=16.
// grid (2 nt, 2 mt, 64 b)
// ==========================================================================
__global__ __launch_bounds__(256, 2) void k2_mma(
    const float* __restrict__ bc2, const float* __restrict__ bs2)
{
    extern __shared__ __half smh[];
    const uint32_t sbase = (uint32_t)__cvta_generic_to_shared(smh);
    const uint32_t mb    = sbase;
    const uint32_t st0   = sbase + 1024;

    const int b  = blockIdx.z;
    const int mt = blockIdx.y;   // 0 -> f, 1 -> s
    const int nt = blockIdx.x;

    const __half* Asrc = g_w2b + (size_t)(mt * 16) * BLK_H;
    const __half* Bsrc = g_hb  + (size_t)((b * 2 + nt) * 32 + mt * 16) * BLK_H;

    const int tid  = threadIdx.x;
    const int warp = tid >> 5, lane = tid & 31;
    const int g = lane >> 2, t = lane & 3;
    const int wm = warp >> 2, wn = warp & 3;

    const int lrow = lane & 15;
    const int lcol = (lane >> 4) * 8;

    const uint32_t a_base = st0 + (uint32_t)((wm * 64 + lrow) * HTS + lcol) * 2u;
    const uint32_t b_base = st0 + BLK_B + (uint32_t)((wn * 32 + lrow) * HTS + lcol) * 2u;

    if (tid == 0) {
#pragma unroll
        for (int s = 0; s < NS; s++) MBAR_INIT(mb + 8 * s, 1);
    }
    __syncthreads();
    if (tid == 0) {
#pragma unroll
        for (int s = 0; s < NS; s++) {
            MBAR_EXPECT_TX(mb + 8 * s, STG_BYTES);
            BULK_G2S(st0 + s * STG_BYTES,         Asrc + (size_t)s * BLK_H, BLK_B, mb + 8 * s);
            BULK_G2S(st0 + s * STG_BYTES + BLK_B, Bsrc + (size_t)s * BLK_H, BLK_B, mb + 8 * s);
        }
    }

    float acc[4][4][4];
#pragma unroll
    for (int i = 0; i < 4; i++)
#pragma unroll
        for (int j = 0; j < 4; j++)
#pragma unroll
            for (int q = 0; q < 4; q++) acc[i][j][q] = 0.f;

    const int KT = HIDD / 32;   // 16
    for (int kt = 0; kt < KT; kt++) {
        const int s = kt & (NS - 1);
        const uint32_t parity = (kt >> 2) & 1;
        mbar_wait(mb + 8 * s, parity);

        const uint32_t abuf = a_base + s * STG_BYTES;
        const uint32_t bbuf = b_base + s * STG_BYTES;

#pragma unroll
        for (int kk = 0; kk < 2; kk++) {
            uint32_t af[4][4];
#pragma unroll
            for (int mi = 0; mi < 4; mi++)
                ldsm_x4(af[mi][0], af[mi][1], af[mi][2], af[mi][3],
                        abuf + mi * (16 * HTS * 2) + kk * 32);
            uint32_t bf[4][2];
#pragma unroll
            for (int nip = 0; nip < 2; nip++) {
                uint32_t r0, r1, r2, r3;
                ldsm_x4(r0, r1, r2, r3, bbuf + nip * (16 * HTS * 2) + kk * 32);
                bf[2 * nip + 0][0] = r0; bf[2 * nip + 0][1] = r2;
                bf[2 * nip + 1][0] = r1; bf[2 * nip + 1][1] = r3;
            }
#pragma unroll
            for (int mi = 0; mi < 4; mi++)
#pragma unroll
                for (int ni = 0; ni < 4; ni++)
                    mma_f16(acc[mi][ni], af[mi], bf[ni]);
        }
        __syncthreads();
        if (tid == 0 && kt + NS < KT) {
            const int kn = kt + NS;
            MBAR_EXPECT_TX(mb + 8 * s, STG_BYTES);
            BULK_G2S(st0 + s * STG_BYTES,         Asrc + (size_t)kn * BLK_H, BLK_B, mb + 8 * s);
            BULK_G2S(st0 + s * STG_BYTES + BLK_B, Bsrc + (size_t)kn * BLK_H, BLK_B, mb + 8 * s);
        }
    }

#pragma unroll
    for (int mi = 0; mi < 4; mi++) {
#pragma unroll
        for (int q2 = 0; q2 < 2; q2++) {
            int row = wm * 64 + mi * 16 + q2 * 8 + g;
            if (mt == 0) {
                float bv = __ldg(bc2 + row);
#pragma unroll
                for (int ni = 0; ni < 4; ni++) {
                    int col = nt * 128 + wn * 32 + ni * 8 + t * 2;
                    float2 v;
                    v.x = acc[mi][ni][q2 * 2 + 0] + bv;
                    v.y = acc[mi][ni][q2 * 2 + 1] + bv;
                    *(float2*)(g_f + ((size_t)b * L_DIM + row) * N_TOK + col) = v;
                }
            } else if (row < 64) {
                float bv = __ldg(bs2 + row);
#pragma unroll
                for (int ni = 0; ni < 4; ni++) {
                    int col = nt * 128 + wn * 32 + ni * 8 + t * 2;
                    float2 v;
                    v.x = acc[mi][ni][q2 * 2 + 0] + bv;
                    v.y = acc[mi][ni][q2 * 2 + 1] + bv;
                    *(float2*)(g_s + ((size_t)b * M_CL + row) * N_TOK + col) = v;
                }
            }
        }
    }
}

// ==========================================================================
// Kernel 3: token MLP + L2 norm -> out[b][0:256]
// ==========================================================================
__global__ __launch_bounds__(256) void k3_token(
    const float* __restrict__ t,
    const float* __restrict__ Wt1, const float* __restrict__ bt1,
    const float* __restrict__ Wt2, const float* __restrict__ bt2,
    float* __restrict__ out)
{
    __shared__ float ts[C_DIM];
    __shared__ float th[HIDD];
    __shared__ float red[8];

    const int b   = blockIdx.x;
    const int tid = threadIdx.x;

    for (int i = tid; i < C_DIM; i += 256) ts[i] = t[(size_t)b * C_DIM + i];
    __syncthreads();

    for (int o = tid; o < HIDD; o += 256) {
        const float* wr = Wt1 + (size_t)o * C_DIM;
        float a0 = 0.f, a1 = 0.f, a2 = 0.f, a3 = 0.f;
        for (int c = 0; c < C_DIM; c += 4) {
            a0 += wr[c + 0] * ts[c + 0];
            a1 += wr[c + 1] * ts[c + 1];
            a2 += wr[c + 2] * ts[c + 2];
            a3 += wr[c + 3] * ts[c + 3];
        }
        th[o] = fmaxf((a0 + a1) + (a2 + a3) + bt1[o], 0.f);
    }
    __syncthreads();

    float val;
    {
        const float* wr = Wt2 + (size_t)tid * HIDD;
        float a0 = 0.f, a1 = 0.f, a2 = 0.f, a3 = 0.f;
        for (int c = 0; c < HIDD; c += 4) {
            a0 += wr[c + 0] * th[c + 0];
            a1 += wr[c + 1] * th[c + 1];
            a2 += wr[c + 2] * th[c + 2];
            a3 += wr[c + 3] * th[c + 3];
        }
        val = (a0 + a1) + (a2 + a3) + bt2[tid];
    }

    float ss = val * val;
#pragma unroll
    for (int off = 16; off; off >>= 1) ss += __shfl_xor_sync(0xffffffffu, ss, off);
    if ((tid & 31) == 0) red[tid >> 5] = ss;
    __syncthreads();
    float tot = 0.f;
#pragma unroll
    for (int i = 0; i < 8; i++) tot += red[i];
    float sc = 1.f / fmaxf(sqrtf(tot), 1e-12f);
    out[(size_t)b * OUT_PER_B + tid] = val * sc;
}

// ==========================================================================
// Kernel 4: Sinkhorn -> g_p
// ==========================================================================
__global__ __launch_bounds__(256) void k4_sinkhorn(const float* __restrict__ dustp)
{
    extern __shared__ float sh[];
    float* Ms = sh;
    float* u  = sh + 65 * 256;
    float* v  = u + 72;

    const int b   = blockIdx.x;
    const int tid = threadIdx.x;
    const float dust = *dustp;
    const float* S = g_s + (size_t)b * M_CL * N_TOK;

    for (int i = tid; i < 64 * 256; i += 256) Ms[i] = S[i];
    Ms[64 * 256 + tid] = dust;
    v[tid] = 0.f;
    __syncthreads();

    const int w    = tid >> 5;
    const int lane = tid & 31;

    for (int it = 0; it < 3; it++) {
        for (int r = w; r < 65; r += 8) {
            float vals[8];
            float mx = -INFINITY;
#pragma unroll
            for (int q = 0; q < 8; q++) {
                float vv = Ms[r * 256 + lane + 32 * q] + v[lane + 32 * q];
                vals[q] = vv;
                mx = fmaxf(mx, vv);
            }
#pragma unroll
            for (int off = 16; off; off >>= 1)
                mx = fmaxf(mx, __shfl_xor_sync(0xffffffffu, mx, off));
            float ssum = 0.f;
#pragma unroll
            for (int q = 0; q < 8; q++) ssum += expf(vals[q] - mx);
#pragma unroll
            for (int off = 16; off; off >>= 1)
                ssum += __shfl_xor_sync(0xffffffffu, ssum, off);
            if (lane == 0) {
                float la = (r == 64) ? LOGA_LAST : NEG_LOG320;
                u[r] = la - (mx + logf(ssum));
            }
        }
        __syncthreads();
        {
            float mrun = -INFINITY, srun = 0.f;
            for (int m = 0; m < 65; m++) {
                float vv = Ms[m * 256 + tid] + u[m];
                if (vv > mrun) {
                    srun = srun * expf(mrun - vv) + 1.f;
                    mrun = vv;
                } else {
                    srun += expf(vv - mrun);
                }
            }
            v[tid] = NEG_LOG320 - (mrun + logf(srun));
        }
        __syncthreads();
    }

    float* P = g_p + (size_t)b * M_CL * N_TOK;
    for (int i = tid; i < 64 * 256; i += 256) {
        int m = i >> 8, j = i & 255;
        P[i] = expf(Ms[i] + u[m] + v[j] - NEG_LOG320);
    }
}

// ==========================================================================
// Kernel 5: VLAD + intra-norm
// ==========================================================================
#define PS_LD 260
__global__ __launch_bounds__(256) void k5_vlad(float* __restrict__ out)
{
    extern __shared__ float sh[];
    float* ps  = sh;
    float* vs  = sh + 64 * PS_LD;
    float* inv = vs + 128 * 64;

    const int b   = blockIdx.x;
    const int tid = threadIdx.x;
    const float* P = g_p + (size_t)b * M_CL * N_TOK;
    const float* F = g_f + (size_t)b * L_DIM * N_TOK;

    for (int i = tid; i < 64 * 256; i += 256) {
        int m = i >> 8, n = i & 255;
        ps[m * PS_LD + n] = P[i];
    }
    __syncthreads();

    const int m  = tid & 63;
    const int lg = tid >> 6;

    const float4* pr = (const float4*)(ps + m * PS_LD);

    float acc[32];
#pragma unroll
    for (int i = 0; i < 32; i++) acc[i] = 0.f;

    for (int nc = 0; nc < 64; nc += 4) {
        float4 pv0 = pr[nc + 0], pv1 = pr[nc + 1], pv2 = pr[nc + 2], pv3 = pr[nc + 3];
#pragma unroll
        for (int li = 0; li < 32; li++) {
            const float4* fr = (const float4*)(F + (size_t)(lg * 32 + li) * N_TOK);
            float4 f0 = fr[nc + 0], f1 = fr[nc + 1], f2 = fr[nc + 2], f3 = fr[nc + 3];
            float a = acc[li];
            a += f0.x * pv0.x + f0.y * pv0.y + f0.z * pv0.z + f0.w * pv0.w;
            a += f1.x * pv1.x + f1.y * pv1.y + f1.z * pv1.z + f1.w * pv1.w;
            a += f2.x * pv2.x + f2.y * pv2.y + f2.z * pv2.z + f2.w * pv2.w;
            a += f3.x * pv3.x + f3.y * pv3.y + f3.z * pv3.z + f3.w * pv3.w;
            acc[li] = a;
        }
    }
#pragma unroll
    for (int li = 0; li < 32; li++) vs[(lg * 32 + li) * 64 + m] = acc[li];
    __syncthreads();

    if (tid < 64) {
        float ss = 0.f;
        for (int l = 0; l < 128; l++) {
            float vv = vs[l * 64 + tid];
            ss += vv * vv;
        }
        inv[tid] = 1.f / fmaxf(sqrtf(ss), 1e-12f);
    }
    __syncthreads();

    float* Ob = out + (size_t)b * OUT_PER_B + G_DIM;
    for (int i = tid; i < L_DIM * M_CL; i += 256) Ob[i] = vs[i] * inv[i & 63];
}

// ==========================================================================
// Kernel 6: final L2 norm
// ==========================================================================
__global__ __launch_bounds__(256) void k6_norm(float* __restrict__ out)
{
    __shared__ float red[8];
    __shared__ float sc_s;
    const int b   = blockIdx.x;
    const int tid = threadIdx.x;
    float* O = out + (size_t)b * OUT_PER_B;

    float ss = 0.f;
    for (int i = tid; i < OUT_PER_B; i += 256) {
        float vv = O[i];
        ss += vv * vv;
    }
#pragma unroll
    for (int off = 16; off; off >>= 1) ss += __shfl_xor_sync(0xffffffffu, ss, off);
    if ((tid & 31) == 0) red[tid >> 5] = ss;
    __syncthreads();
    if (tid == 0) {
        float tot = 0.f;
#pragma unroll
        for (int i = 0; i < 8; i++) tot += red[i];
        sc_s = 1.f / fmaxf(sqrtf(tot), 1e-12f);
    }
    __syncthreads();
    float sc = sc_s;
    for (int i = tid; i < OUT_PER_B; i += 256) O[i] *= sc;
}

// ==========================================================================
// launch  (k1 placed at launch index 3 so ncu captures it)
// ==========================================================================
extern "C" void kernel_launch(void* const* d_in, const int* in_sizes, int n_in,
                              void* d_out, int out_size)
{
    (void)in_sizes; (void)n_in; (void)out_size;
    const float* x    = (const float*)d_in[0];
    const float* t    = (const float*)d_in[1];
    const float* Wt1  = (const float*)d_in[2];
    const float* bt1  = (const float*)d_in[3];
    const float* Wt2  = (const float*)d_in[4];
    const float* bt2  = (const float*)d_in[5];
    const float* Wc1  = (const float*)d_in[6];
    const float* bc1  = (const float*)d_in[7];
    const float* Wc2  = (const float*)d_in[8];
    const float* bc2  = (const float*)d_in[9];
    const float* Ws1  = (const float*)d_in[10];
    const float* bs1  = (const float*)d_in[11];
    const float* Ws2  = (const float*)d_in[12];
    const float* bs2  = (const float*)d_in[13];
    const float* dust = (const float*)d_in[14];
    float* out = (float*)d_out;

    const int sink_smem = (65 * 256 + 72 + 256) * (int)sizeof(float);
    const int vlad_smem = (64 * PS_LD + 128 * 64 + 64) * (int)sizeof(float);
    cudaFuncSetAttribute(k1_mma,      cudaFuncAttributeMaxDynamicSharedMemorySize, GEMM_SMEM);
    cudaFuncSetAttribute(k2_mma,      cudaFuncAttributeMaxDynamicSharedMemorySize, GEMM_SMEM);
    cudaFuncSetAttribute(k4_sinkhorn, cudaFuncAttributeMaxDynamicSharedMemorySize, sink_smem);
    cudaFuncSetAttribute(k5_vlad,     cudaFuncAttributeMaxDynamicSharedMemorySize, vlad_smem);

    p_weights<<<512, 256>>>(Wc1, Ws1, Wc2, Ws2);                 // idx 0
    p_xt<<<dim3(48, 8, B_SZ), 256>>>(x);                         // idx 1
    k3_token<<<B_SZ, 256>>>(t, Wt1, bt1, Wt2, bt2, out);         // idx 2
    k1_mma<<<dim3(2, 8, B_SZ), 256, GEMM_SMEM>>>(bc1, bs1);      // idx 3 (ncu target)
    k2_mma<<<dim3(2, 2, B_SZ), 256, GEMM_SMEM>>>(bc2, bs2);      // idx 4
    k4_sinkhorn<<<B_SZ, 256, sink_smem>>>(dust);                 // idx 5
    k5_vlad<<<B_SZ, 256, vlad_smem>>>(out);                      // idx 6
    k6_norm<<<B_SZ, 256>>>(out);                                 // idx 7
}

// round 8
// speedup vs baseline: 4.2686x; 1.7131x over previous
#include <cuda_runtime.h>
#include <cuda_fp16.h>
#include <math.h>
#include <stdint.h>

// ---------------- problem constants ----------------
#define B_SZ   64
#define C_DIM  1536
#define N_TOK  256
#define HIDD   512
#define L_DIM  128
#define G_DIM  256
#define M_CL   64
#define OUT_PER_B (G_DIM + L_DIM * M_CL)   // 8448

#define NEG_LOG320 (-5.768320995793772f)
#define LOGA_LAST  (-0.510825623765991f)

// blocked tile: 128 rows x 40 halves (32 data + 8 pad) = 5120 halves = 10240 B
#define BLK_H   5120
#define BLK_B   10240

// ---------------- scratch (blocked, pre-padded layouts) ----------------
__device__ __half g_xb [B_SZ * 2 * 48 * BLK_H];   // x^T blocked: [(b*2+nt)*48+kt]
__device__ __half g_hb [B_SZ * 2 * 32 * BLK_H];   // hidden blocked: [(b*2+nt)*32+oblk]
__device__ __half g_w1b[8 * 48 * BLK_H];          // [Wc1;Ws1] blocked: [mt*48+kt]
__device__ __half g_w2b[2 * 16 * BLK_H];          // [Wc2;Ws2pad] blocked: [mt*16+kt]
__device__ float  g_f[B_SZ * L_DIM * N_TOK];
__device__ float  g_s[B_SZ * M_CL * N_TOK];
__device__ float  g_p[B_SZ * M_CL * N_TOK];

// ---------------- helpers ----------------
__device__ __forceinline__ void ldsm_x4(uint32_t& r0, uint32_t& r1, uint32_t& r2, uint32_t& r3,
                                        uint32_t addr) {
    asm volatile("ldmatrix.sync.aligned.m8n8.x4.shared.b16 {%0,%1,%2,%3}, [%4];"
        : "=r"(r0), "=r"(r1), "=r"(r2), "=r"(r3) : "r"(addr));
}

__device__ __forceinline__ void mma_f16(float* d, const uint32_t* a, const uint32_t* b) {
    asm volatile(
        "mma.sync.aligned.m16n8k16.row.col.f32.f16.f16.f32 "
        "{%0,%1,%2,%3}, {%4,%5,%6,%7}, {%8,%9}, {%0,%1,%2,%3};"
        : "+f"(d[0]), "+f"(d[1]), "+f"(d[2]), "+f"(d[3])
        : "r"(a[0]), "r"(a[1]), "r"(a[2]), "r"(a[3]), "r"(b[0]), "r"(b[1]));
}

#define MBAR_INIT(mbar, cnt) \
    asm volatile("mbarrier.init.shared.b64 [%0], %1;" :: "r"(mbar), "r"((uint32_t)(cnt)) : "memory")
#define MBAR_EXPECT_TX(mbar, bytes) \
    asm volatile("mbarrier.arrive.expect_tx.shared.b64 _, [%0], %1;" \
                 :: "r"(mbar), "r"((uint32_t)(bytes)) : "memory")
#define BULK_G2S(dst_smem, gsrc, bytes, mbar) \
    asm volatile("cp.async.bulk.shared::cta.global.mbarrier::complete_tx::bytes [%0], [%1], %2, [%3];" \
                 :: "r"(dst_smem), "l"(gsrc), "r"((uint32_t)(bytes)), "r"(mbar) : "memory")

__device__ __forceinline__ void mbar_wait(uint32_t mbar, uint32_t parity) {
    asm volatile(
        "{\n\t.reg .pred P1;\n\t"
        "WAIT_LOOP_%=:\n\t"
        "mbarrier.try_wait.parity.acquire.cta.shared::cta.b64 P1, [%0], %1, 0x989680;\n\t"
        "@P1 bra.uni WAIT_DONE_%=;\n\t"
        "bra.uni WAIT_LOOP_%=;\n\t"
        "WAIT_DONE_%=:\n\t}"
        :: "r"(mbar), "r"(parity) : "memory");
}

// smem geometry: rows of 32 halves + 8 pad -> stride 40 halves, conflict-free ldsm
#define HTS       40
#define NS        4                  // pipeline stages
#define STG_BYTES (2 * BLK_B)        // A + B per stage = 20480
#define GEMM_SMEM (1024 + NS * STG_BYTES)   // 82944 B

// ==========================================================================
// Prepass A: weights -> fp16 blocked layouts
// ==========================================================================
__global__ __launch_bounds__(256) void p_weights(
    const float* __restrict__ Wc1, const float* __restrict__ Ws1,
    const float* __restrict__ Wc2, const float* __restrict__ Ws2)
{
    const int total1 = 1024 * C_DIM;
    const int total2 = 256 * HIDD;
    for (int idx = blockIdx.x * 256 + threadIdx.x; idx < total1 + total2;
         idx += gridDim.x * 256) {
        if (idx < total1) {
            int o = idx / C_DIM, k = idx - o * C_DIM;
            float v = (o < 512) ? Wc1[idx] : Ws1[idx - 512 * C_DIM];
            g_w1b[(size_t)((o >> 7) * 48 + (k >> 5)) * BLK_H + (o & 127) * HTS + (k & 31)]
                = __float2half_rn(v);
        } else {
            int j = idx - total1;
            int o = j >> 9, k = j & 511;
            float v = (o < 128) ? Wc2[j]
                    : (o < 192) ? Ws2[j - 128 * HIDD] : 0.f;
            g_w2b[(size_t)((o >> 7) * 16 + (k >> 5)) * BLK_H + (o & 127) * HTS + (k & 31)]
                = __float2half_rn(v);
        }
    }
}

// ==========================================================================
// Prepass B: x[b][c][n] -> blocked g_xb (transpose + fp16)
// ==========================================================================
__global__ __launch_bounds__(256) void p_xt(const float* __restrict__ x)
{
    __shared__ float sm[32][33];
    const int b  = blockIdx.z;
    const int ct = blockIdx.x * 32;
    const int nt = blockIdx.y * 32;
    const int tx = threadIdx.x & 31;
    const int ty = threadIdx.x >> 5;

#pragma unroll
    for (int i = 0; i < 4; i++) {
        int c = ct + ty + i * 8;
        sm[ty + i * 8][tx] = x[((size_t)b * C_DIM + c) * N_TOK + nt + tx];
    }
    __syncthreads();
    const int kt = ct >> 5;
#pragma unroll
    for (int i = 0; i < 4; i++) {
        int n = nt + ty + i * 8;
        size_t dst = (size_t)(((b * 2) + (n >> 7)) * 48 + kt) * BLK_H
                   + (n & 127) * HTS + tx;
        g_xb[dst] = __float2half_rn(sm[tx][ty + i * 8]);
    }
}

// ==========================================================================
// Kernel 1 (fp16 mma.sync + bulk-copy pipeline): h[n][o] = relu(x^T W1^T + b1)
// ==========================================================================
__global__ __launch_bounds__(256, 2) void k1_mma(
    const float* __restrict__ bc1, const float* __restrict__ bs1)
{
    extern __shared__ __half smh[];
    const uint32_t sbase = (uint32_t)__cvta_generic_to_shared(smh);
    const uint32_t mb    = sbase;
    const uint32_t st0   = sbase + 1024;

    const int b  = blockIdx.z;
    const int mt = blockIdx.y;
    const int nt = blockIdx.x;

    const __half* Asrc = g_xb  + (size_t)((b * 2 + nt) * 48) * BLK_H;
    const __half* Bsrc = g_w1b + (size_t)(mt * 48) * BLK_H;
    const float*  bias = (mt < 4) ? (bc1 + mt * 128) : (bs1 + (mt - 4) * 128);

    const int tid  = threadIdx.x;
    const int warp = tid >> 5, lane = tid & 31;
    const int g = lane >> 2, t = lane & 3;
    const int wm = warp >> 2, wn = warp & 3;

    const int lrow = lane & 15;
    const int lcol = (lane >> 4) * 8;

    const uint32_t a_base = st0 + (uint32_t)((wm * 64 + lrow) * HTS + lcol) * 2u;
    const uint32_t b_base = st0 + BLK_B + (uint32_t)((wn * 32 + lrow) * HTS + lcol) * 2u;

    if (tid == 0) {
#pragma unroll
        for (int s = 0; s < NS; s++) MBAR_INIT(mb + 8 * s, 1);
    }
    __syncthreads();
    if (tid == 0) {
#pragma unroll
        for (int s = 0; s < NS; s++) {
            MBAR_EXPECT_TX(mb + 8 * s, STG_BYTES);
            BULK_G2S(st0 + s * STG_BYTES,         Asrc + (size_t)s * BLK_H, BLK_B, mb + 8 * s);
            BULK_G2S(st0 + s * STG_BYTES + BLK_B, Bsrc + (size_t)s * BLK_H, BLK_B, mb + 8 * s);
        }
    }

    float acc[4][4][4];
#pragma unroll
    for (int i = 0; i < 4; i++)
#pragma unroll
        for (int j = 0; j < 4; j++)
#pragma unroll
            for (int q = 0; q < 4; q++) acc[i][j][q] = 0.f;

    const int KT = C_DIM / 32;   // 48
    for (int kt = 0; kt < KT; kt++) {
        const int s = kt & (NS - 1);
        const uint32_t parity = (kt >> 2) & 1;
        mbar_wait(mb + 8 * s, parity);

        const uint32_t abuf = a_base + s * STG_BYTES;
        const uint32_t bbuf = b_base + s * STG_BYTES;

#pragma unroll
        for (int kk = 0; kk < 2; kk++) {
            uint32_t af[4][4];
#pragma unroll
            for (int mi = 0; mi < 4; mi++)
                ldsm_x4(af[mi][0], af[mi][1], af[mi][2], af[mi][3],
                        abuf + mi * (16 * HTS * 2) + kk * 32);
            uint32_t bf[4][2];
#pragma unroll
            for (int nip = 0; nip < 2; nip++) {
                uint32_t r0, r1, r2, r3;
                ldsm_x4(r0, r1, r2, r3, bbuf + nip * (16 * HTS * 2) + kk * 32);
                bf[2 * nip + 0][0] = r0; bf[2 * nip + 0][1] = r2;
                bf[2 * nip + 1][0] = r1; bf[2 * nip + 1][1] = r3;
            }
#pragma unroll
            for (int mi = 0; mi < 4; mi++)
#pragma unroll
                for (int ni = 0; ni < 4; ni++)
                    mma_f16(acc[mi][ni], af[mi], bf[ni]);
        }
        __syncthreads();
        if (tid == 0 && kt + NS < KT) {
            const int kn = kt + NS;
            MBAR_EXPECT_TX(mb + 8 * s, STG_BYTES);
            BULK_G2S(st0 + s * STG_BYTES,         Asrc + (size_t)kn * BLK_H, BLK_B, mb + 8 * s);
            BULK_G2S(st0 + s * STG_BYTES + BLK_B, Bsrc + (size_t)kn * BLK_H, BLK_B, mb + 8 * s);
        }
    }

    float bvv[4][2];
#pragma unroll
    for (int ni = 0; ni < 4; ni++) {
        int col = wn * 32 + ni * 8 + t * 2;
        bvv[ni][0] = __ldg(bias + col);
        bvv[ni][1] = __ldg(bias + col + 1);
    }
    __half* Ob = g_hb + (size_t)((b * 2 + nt) * 32 + mt * 4 + wn) * BLK_H;
#pragma unroll
    for (int mi = 0; mi < 4; mi++) {
#pragma unroll
        for (int q2 = 0; q2 < 2; q2++) {
            int row = wm * 64 + mi * 16 + q2 * 8 + g;
#pragma unroll
            for (int ni = 0; ni < 4; ni++) {
                int c = ni * 8 + t * 2;
                __half2 hv = __floats2half2_rn(
                    fmaxf(acc[mi][ni][q2 * 2 + 0] + bvv[ni][0], 0.f),
                    fmaxf(acc[mi][ni][q2 * 2 + 1] + bvv[ni][1], 0.f));
                *(__half2*)(Ob + row * HTS + c) = hv;
            }
        }
    }
}

// ==========================================================================
// Kernel 2 (fp16 mma.sync + bulk pipeline): f = Wc2 h1 + bc2 ; s = Ws2 h2 + bs2
// ==========================================================================
__global__ __launch_bounds__(256, 2) void k2_mma(
    const float* __restrict__ bc2, const float* __restrict__ bs2)
{
    extern __shared__ __half smh[];
    const uint32_t sbase = (uint32_t)__cvta_generic_to_shared(smh);
    const uint32_t mb    = sbase;
    const uint32_t st0   = sbase + 1024;

    const int b  = blockIdx.z;
    const int mt = blockIdx.y;
    const int nt = blockIdx.x;

    const __half* Asrc = g_w2b + (size_t)(mt * 16) * BLK_H;
    const __half* Bsrc = g_hb  + (size_t)((b * 2 + nt) * 32 + mt * 16) * BLK_H;

    const int tid  = threadIdx.x;
    const int warp = tid >> 5, lane = tid & 31;
    const int g = lane >> 2, t = lane & 3;
    const int wm = warp >> 2, wn = warp & 3;

    const int lrow = lane & 15;
    const int lcol = (lane >> 4) * 8;

    const uint32_t a_base = st0 + (uint32_t)((wm * 64 + lrow) * HTS + lcol) * 2u;
    const uint32_t b_base = st0 + BLK_B + (uint32_t)((wn * 32 + lrow) * HTS + lcol) * 2u;

    if (tid == 0) {
#pragma unroll
        for (int s = 0; s < NS; s++) MBAR_INIT(mb + 8 * s, 1);
    }
    __syncthreads();
    if (tid == 0) {
#pragma unroll
        for (int s = 0; s < NS; s++) {
            MBAR_EXPECT_TX(mb + 8 * s, STG_BYTES);
            BULK_G2S(st0 + s * STG_BYTES,         Asrc + (size_t)s * BLK_H, BLK_B, mb + 8 * s);
            BULK_G2S(st0 + s * STG_BYTES + BLK_B, Bsrc + (size_t)s * BLK_H, BLK_B, mb + 8 * s);
        }
    }

    float acc[4][4][4];
#pragma unroll
    for (int i = 0; i < 4; i++)
#pragma unroll
        for (int j = 0; j < 4; j++)
#pragma unroll
            for (int q = 0; q < 4; q++) acc[i][j][q] = 0.f;

    const int KT = HIDD / 32;   // 16
    for (int kt = 0; kt < KT; kt++) {
        const int s = kt & (NS - 1);
        const uint32_t parity = (kt >> 2) & 1;
        mbar_wait(mb + 8 * s, parity);

        const uint32_t abuf = a_base + s * STG_BYTES;
        const uint32_t bbuf = b_base + s * STG_BYTES;

#pragma unroll
        for (int kk = 0; kk < 2; kk++) {
            uint32_t af[4][4];
#pragma unroll
            for (int mi = 0; mi < 4; mi++)
                ldsm_x4(af[mi][0], af[mi][1], af[mi][2], af[mi][3],
                        abuf + mi * (16 * HTS * 2) + kk * 32);
            uint32_t bf[4][2];
#pragma unroll
            for (int nip = 0; nip < 2; nip++) {
                uint32_t r0, r1, r2, r3;
                ldsm_x4(r0, r1, r2, r3, bbuf + nip * (16 * HTS * 2) + kk * 32);
                bf[2 * nip + 0][0] = r0; bf[2 * nip + 0][1] = r2;
                bf[2 * nip + 1][0] = r1; bf[2 * nip + 1][1] = r3;
            }
#pragma unroll
            for (int mi = 0; mi < 4; mi++)
#pragma unroll
                for (int ni = 0; ni < 4; ni++)
                    mma_f16(acc[mi][ni], af[mi], bf[ni]);
        }
        __syncthreads();
        if (tid == 0 && kt + NS < KT) {
            const int kn = kt + NS;
            MBAR_EXPECT_TX(mb + 8 * s, STG_BYTES);
            BULK_G2S(st0 + s * STG_BYTES,         Asrc + (size_t)kn * BLK_H, BLK_B, mb + 8 * s);
            BULK_G2S(st0 + s * STG_BYTES + BLK_B, Bsrc + (size_t)kn * BLK_H, BLK_B, mb + 8 * s);
        }
    }

#pragma unroll
    for (int mi = 0; mi < 4; mi++) {
#pragma unroll
        for (int q2 = 0; q2 < 2; q2++) {
            int row = wm * 64 + mi * 16 + q2 * 8 + g;
            if (mt == 0) {
                float bv = __ldg(bc2 + row);
#pragma unroll
                for (int ni = 0; ni < 4; ni++) {
                    int col = nt * 128 + wn * 32 + ni * 8 + t * 2;
                    float2 v;
                    v.x = acc[mi][ni][q2 * 2 + 0] + bv;
                    v.y = acc[mi][ni][q2 * 2 + 1] + bv;
                    *(float2*)(g_f + ((size_t)b * L_DIM + row) * N_TOK + col) = v;
                }
            } else if (row < 64) {
                float bv = __ldg(bs2 + row);
#pragma unroll
                for (int ni = 0; ni < 4; ni++) {
                    int col = nt * 128 + wn * 32 + ni * 8 + t * 2;
                    float2 v;
                    v.x = acc[mi][ni][q2 * 2 + 0] + bv;
                    v.y = acc[mi][ni][q2 * 2 + 1] + bv;
                    *(float2*)(g_s + ((size_t)b * M_CL + row) * N_TOK + col) = v;
                }
            }
        }
    }
}

// ==========================================================================
// Kernel 3 (v2, coalesced): token MLP + L2 norm -> out[b][0:256]
// Warp-cooperative dots: lanes split the k-dimension, float4 loads, butterfly
// reduction. 2 outputs per iteration for ILP.
// ==========================================================================
__global__ __launch_bounds__(256) void k3_token(
    const float* __restrict__ t,
    const float* __restrict__ Wt1, const float* __restrict__ bt1,
    const float* __restrict__ Wt2, const float* __restrict__ bt2,
    float* __restrict__ out)
{
    __shared__ float ts[C_DIM];
    __shared__ float th[HIDD];
    __shared__ float tg[G_DIM];
    __shared__ float red[8];

    const int b    = blockIdx.x;
    const int tid  = threadIdx.x;
    const int warp = tid >> 5;
    const int lane = tid & 31;

    for (int i = tid; i < C_DIM / 4; i += 256)
        ((float4*)ts)[i] = ((const float4*)(t + (size_t)b * C_DIM))[i];
    __syncthreads();

    // layer 1: 512 outputs, warp computes 64 (2 at a time)
    for (int o0 = warp * 64; o0 < warp * 64 + 64; o0 += 2) {
        const float4* w0 = (const float4*)(Wt1 + (size_t)o0 * C_DIM);
        const float4* w1 = (const float4*)(Wt1 + (size_t)(o0 + 1) * C_DIM);
        const float4* tv4 = (const float4*)ts;
        float a0 = 0.f, a1 = 0.f;
#pragma unroll
        for (int j = 0; j < C_DIM / 128; j++) {   // 12
            float4 tv = tv4[j * 32 + lane];
            float4 v0 = __ldg(w0 + j * 32 + lane);
            float4 v1 = __ldg(w1 + j * 32 + lane);
            a0 += v0.x * tv.x + v0.y * tv.y + v0.z * tv.z + v0.w * tv.w;
            a1 += v1.x * tv.x + v1.y * tv.y + v1.z * tv.z + v1.w * tv.w;
        }
#pragma unroll
        for (int off = 16; off; off >>= 1) {
            a0 += __shfl_xor_sync(0xffffffffu, a0, off);
            a1 += __shfl_xor_sync(0xffffffffu, a1, off);
        }
        if (lane == 0) {
            th[o0]     = fmaxf(a0 + __ldg(bt1 + o0), 0.f);
            th[o0 + 1] = fmaxf(a1 + __ldg(bt1 + o0 + 1), 0.f);
        }
    }
    __syncthreads();

    // layer 2: 256 outputs, warp computes 32 (2 at a time)
    for (int o0 = warp * 32; o0 < warp * 32 + 32; o0 += 2) {
        const float4* w0 = (const float4*)(Wt2 + (size_t)o0 * HIDD);
        const float4* w1 = (const float4*)(Wt2 + (size_t)(o0 + 1) * HIDD);
        const float4* hv4 = (const float4*)th;
        float a0 = 0.f, a1 = 0.f;
#pragma unroll
        for (int j = 0; j < HIDD / 128; j++) {    // 4
            float4 hv = hv4[j * 32 + lane];
            float4 v0 = __ldg(w0 + j * 32 + lane);
            float4 v1 = __ldg(w1 + j * 32 + lane);
            a0 += v0.x * hv.x + v0.y * hv.y + v0.z * hv.z + v0.w * hv.w;
            a1 += v1.x * hv.x + v1.y * hv.y + v1.z * hv.z + v1.w * hv.w;
        }
#pragma unroll
        for (int off = 16; off; off >>= 1) {
            a0 += __shfl_xor_sync(0xffffffffu, a0, off);
            a1 += __shfl_xor_sync(0xffffffffu, a1, off);
        }
        if (lane == 0) {
            tg[o0]     = a0 + __ldg(bt2 + o0);
            tg[o0 + 1] = a1 + __ldg(bt2 + o0 + 1);
        }
    }
    __syncthreads();

    // L2 norm over the 256 token features
    float val = tg[tid];
    float ss = val * val;
#pragma unroll
    for (int off = 16; off; off >>= 1) ss += __shfl_xor_sync(0xffffffffu, ss, off);
    if (lane == 0) red[warp] = ss;
    __syncthreads();
    float tot = 0.f;
#pragma unroll
    for (int i = 0; i < 8; i++) tot += red[i];
    float sc = 1.f / fmaxf(sqrtf(tot), 1e-12f);
    out[(size_t)b * OUT_PER_B + tid] = val * sc;
}

// ==========================================================================
// Kernel 4: Sinkhorn -> g_p
// ==========================================================================
__global__ __launch_bounds__(256) void k4_sinkhorn(const float* __restrict__ dustp)
{
    extern __shared__ float sh[];
    float* Ms = sh;
    float* u  = sh + 65 * 256;
    float* v  = u + 72;

    const int b   = blockIdx.x;
    const int tid = threadIdx.x;
    const float dust = *dustp;
    const float* S = g_s + (size_t)b * M_CL * N_TOK;

    for (int i = tid; i < 64 * 256; i += 256) Ms[i] = S[i];
    Ms[64 * 256 + tid] = dust;
    v[tid] = 0.f;
    __syncthreads();

    const int w    = tid >> 5;
    const int lane = tid & 31;

    for (int it = 0; it < 3; it++) {
        for (int r = w; r < 65; r += 8) {
            float vals[8];
            float mx = -INFINITY;
#pragma unroll
            for (int q = 0; q < 8; q++) {
                float vv = Ms[r * 256 + lane + 32 * q] + v[lane + 32 * q];
                vals[q] = vv;
                mx = fmaxf(mx, vv);
            }
#pragma unroll
            for (int off = 16; off; off >>= 1)
                mx = fmaxf(mx, __shfl_xor_sync(0xffffffffu, mx, off));
            float ssum = 0.f;
#pragma unroll
            for (int q = 0; q < 8; q++) ssum += expf(vals[q] - mx);
#pragma unroll
            for (int off = 16; off; off >>= 1)
                ssum += __shfl_xor_sync(0xffffffffu, ssum, off);
            if (lane == 0) {
                float la = (r == 64) ? LOGA_LAST : NEG_LOG320;
                u[r] = la - (mx + logf(ssum));
            }
        }
        __syncthreads();
        {
            float mrun = -INFINITY, srun = 0.f;
            for (int m = 0; m < 65; m++) {
                float vv = Ms[m * 256 + tid] + u[m];
                if (vv > mrun) {
                    srun = srun * expf(mrun - vv) + 1.f;
                    mrun = vv;
                } else {
                    srun += expf(vv - mrun);
                }
            }
            v[tid] = NEG_LOG320 - (mrun + logf(srun));
        }
        __syncthreads();
    }

    float* P = g_p + (size_t)b * M_CL * N_TOK;
    for (int i = tid; i < 64 * 256; i += 256) {
        int m = i >> 8, j = i & 255;
        P[i] = expf(Ms[i] + u[m] + v[j] - NEG_LOG320);
    }
}

// ==========================================================================
// Kernel 5: VLAD + intra-norm
// ==========================================================================
#define PS_LD 260
__global__ __launch_bounds__(256) void k5_vlad(float* __restrict__ out)
{
    extern __shared__ float sh[];
    float* ps  = sh;
    float* vs  = sh + 64 * PS_LD;
    float* inv = vs + 128 * 64;

    const int b   = blockIdx.x;
    const int tid = threadIdx.x;
    const float* P = g_p + (size_t)b * M_CL * N_TOK;
    const float* F = g_f + (size_t)b * L_DIM * N_TOK;

    for (int i = tid; i < 64 * 256; i += 256) {
        int m = i >> 8, n = i & 255;
        ps[m * PS_LD + n] = P[i];
    }
    __syncthreads();

    const int m  = tid & 63;
    const int lg = tid >> 6;

    const float4* pr = (const float4*)(ps + m * PS_LD);

    float acc[32];
#pragma unroll
    for (int i = 0; i < 32; i++) acc[i] = 0.f;

    for (int nc = 0; nc < 64; nc += 4) {
        float4 pv0 = pr[nc + 0], pv1 = pr[nc + 1], pv2 = pr[nc + 2], pv3 = pr[nc + 3];
#pragma unroll
        for (int li = 0; li < 32; li++) {
            const float4* fr = (const float4*)(F + (size_t)(lg * 32 + li) * N_TOK);
            float4 f0 = fr[nc + 0], f1 = fr[nc + 1], f2 = fr[nc + 2], f3 = fr[nc + 3];
            float a = acc[li];
            a += f0.x * pv0.x + f0.y * pv0.y + f0.z * pv0.z + f0.w * pv0.w;
            a += f1.x * pv1.x + f1.y * pv1.y + f1.z * pv1.z + f1.w * pv1.w;
            a += f2.x * pv2.x + f2.y * pv2.y + f2.z * pv2.z + f2.w * pv2.w;
            a += f3.x * pv3.x + f3.y * pv3.y + f3.z * pv3.z + f3.w * pv3.w;
            acc[li] = a;
        }
    }
#pragma unroll
    for (int li = 0; li < 32; li++) vs[(lg * 32 + li) * 64 + m] = acc[li];
    __syncthreads();

    if (tid < 64) {
        float ss = 0.f;
        for (int l = 0; l < 128; l++) {
            float vv = vs[l * 64 + tid];
            ss += vv * vv;
        }
        inv[tid] = 1.f / fmaxf(sqrtf(ss), 1e-12f);
    }
    __syncthreads();

    float* Ob = out + (size_t)b * OUT_PER_B + G_DIM;
    for (int i = tid; i < L_DIM * M_CL; i += 256) Ob[i] = vs[i] * inv[i & 63];
}

// ==========================================================================
// Kernel 6: final L2 norm
// ==========================================================================
__global__ __launch_bounds__(256) void k6_norm(float* __restrict__ out)
{
    __shared__ float red[8];
    __shared__ float sc_s;
    const int b   = blockIdx.x;
    const int tid = threadIdx.x;
    float* O = out + (size_t)b * OUT_PER_B;

    float ss = 0.f;
    for (int i = tid; i < OUT_PER_B; i += 256) {
        float vv = O[i];
        ss += vv * vv;
    }
#pragma unroll
    for (int off = 16; off; off >>= 1) ss += __shfl_xor_sync(0xffffffffu, ss, off);
    if ((tid & 31) == 0) red[tid >> 5] = ss;
    __syncthreads();
    if (tid == 0) {
        float tot = 0.f;
#pragma unroll
        for (int i = 0; i < 8; i++) tot += red[i];
        sc_s = 1.f / fmaxf(sqrtf(tot), 1e-12f);
    }
    __syncthreads();
    float sc = sc_s;
    for (int i = tid; i < OUT_PER_B; i += 256) O[i] *= sc;
}

// ==========================================================================
// launch  (k3 at launch index 3 so ncu captures the rewrite)
// ==========================================================================
extern "C" void kernel_launch(void* const* d_in, const int* in_sizes, int n_in,
                              void* d_out, int out_size)
{
    (void)in_sizes; (void)n_in; (void)out_size;
    const float* x    = (const float*)d_in[0];
    const float* t    = (const float*)d_in[1];
    const float* Wt1  = (const float*)d_in[2];
    const float* bt1  = (const float*)d_in[3];
    const float* Wt2  = (const float*)d_in[4];
    const float* bt2  = (const float*)d_in[5];
    const float* Wc1  = (const float*)d_in[6];
    const float* bc1  = (const float*)d_in[7];
    const float* Wc2  = (const float*)d_in[8];
    const float* bc2  = (const float*)d_in[9];
    const float* Ws1  = (const float*)d_in[10];
    const float* bs1  = (const float*)d_in[11];
    const float* Ws2  = (const float*)d_in[12];
    const float* bs2  = (const float*)d_in[13];
    const float* dust = (const float*)d_in[14];
    float* out = (float*)d_out;

    const int sink_smem = (65 * 256 + 72 + 256) * (int)sizeof(float);
    const int vlad_smem = (64 * PS_LD + 128 * 64 + 64) * (int)sizeof(float);
    cudaFuncSetAttribute(k1_mma,      cudaFuncAttributeMaxDynamicSharedMemorySize, GEMM_SMEM);
    cudaFuncSetAttribute(k2_mma,      cudaFuncAttributeMaxDynamicSharedMemorySize, GEMM_SMEM);
    cudaFuncSetAttribute(k4_sinkhorn, cudaFuncAttributeMaxDynamicSharedMemorySize, sink_smem);
    cudaFuncSetAttribute(k5_vlad,     cudaFuncAttributeMaxDynamicSharedMemorySize, vlad_smem);

    p_weights<<<512, 256>>>(Wc1, Ws1, Wc2, Ws2);                 // idx 0
    p_xt<<<dim3(48, 8, B_SZ), 256>>>(x);                         // idx 1
    k1_mma<<<dim3(2, 8, B_SZ), 256, GEMM_SMEM>>>(bc1, bs1);      // idx 2
    k3_token<<<B_SZ, 256>>>(t, Wt1, bt1, Wt2, bt2, out);         // idx 3 (ncu target)
    k2_mma<<<dim3(2, 2, B_SZ), 256, GEMM_SMEM>>>(bc2, bs2);      // idx 4
    k4_sinkhorn<<<B_SZ, 256, sink_smem>>>(dust);                 // idx 5
    k5_vlad<<<B_SZ, 256, vlad_smem>>>(out);                      // idx 6
    k6_norm<<<B_SZ, 256>>>(out);                                 // idx 7
}

// round 9
// speedup vs baseline: 4.4470x; 1.0418x over previous
#include <cuda_runtime.h>
#include <cuda_fp16.h>
#include <math.h>
#include <stdint.h>

// ---------------- problem constants ----------------
#define B_SZ   64
#define C_DIM  1536
#define N_TOK  256
#define HIDD   512
#define L_DIM  128
#define G_DIM  256
#define M_CL   64
#define OUT_PER_B (G_DIM + L_DIM * M_CL)   // 8448

#define NEG_LOG320 (-5.768320995793772f)
#define LOGA_LAST  (-0.510825623765991f)

// blocked tile: 128 rows x 40 halves (32 data + 8 pad) = 5120 halves = 10240 B
#define BLK_H   5120
#define BLK_B   10240

// ---------------- scratch (blocked, pre-padded layouts) ----------------
__device__ __half g_xb [B_SZ * 2 * 48 * BLK_H];   // x^T blocked: [(b*2+nt)*48+kt]
__device__ __half g_hb [B_SZ * 2 * 32 * BLK_H];   // hidden blocked: [(b*2+nt)*32+oblk]
__device__ __half g_w1b[8 * 48 * BLK_H];          // [Wc1;Ws1] blocked: [mt*48+kt]
__device__ __half g_w2b[2 * 16 * BLK_H];          // [Wc2;Ws2pad] blocked: [mt*16+kt]
__device__ float  g_f[B_SZ * L_DIM * N_TOK];
__device__ float  g_s[B_SZ * M_CL * N_TOK];
__device__ float  g_p[B_SZ * M_CL * N_TOK];

// ---------------- helpers ----------------
__device__ __forceinline__ void ldsm_x4(uint32_t& r0, uint32_t& r1, uint32_t& r2, uint32_t& r3,
                                        uint32_t addr) {
    asm volatile("ldmatrix.sync.aligned.m8n8.x4.shared.b16 {%0,%1,%2,%3}, [%4];"
        : "=r"(r0), "=r"(r1), "=r"(r2), "=r"(r3) : "r"(addr));
}

__device__ __forceinline__ void mma_f16(float* d, const uint32_t* a, const uint32_t* b) {
    asm volatile(
        "mma.sync.aligned.m16n8k16.row.col.f32.f16.f16.f32 "
        "{%0,%1,%2,%3}, {%4,%5,%6,%7}, {%8,%9}, {%0,%1,%2,%3};"
        : "+f"(d[0]), "+f"(d[1]), "+f"(d[2]), "+f"(d[3])
        : "r"(a[0]), "r"(a[1]), "r"(a[2]), "r"(a[3]), "r"(b[0]), "r"(b[1]));
}

#define MBAR_INIT(mbar, cnt) \
    asm volatile("mbarrier.init.shared.b64 [%0], %1;" :: "r"(mbar), "r"((uint32_t)(cnt)) : "memory")
#define MBAR_EXPECT_TX(mbar, bytes) \
    asm volatile("mbarrier.arrive.expect_tx.shared.b64 _, [%0], %1;" \
                 :: "r"(mbar), "r"((uint32_t)(bytes)) : "memory")
#define BULK_G2S(dst_smem, gsrc, bytes, mbar) \
    asm volatile("cp.async.bulk.shared::cta.global.mbarrier::complete_tx::bytes [%0], [%1], %2, [%3];" \
                 :: "r"(dst_smem), "l"(gsrc), "r"((uint32_t)(bytes)), "r"(mbar) : "memory")

__device__ __forceinline__ void mbar_wait(uint32_t mbar, uint32_t parity) {
    asm volatile(
        "{\n\t.reg .pred P1;\n\t"
        "WAIT_LOOP_%=:\n\t"
        "mbarrier.try_wait.parity.acquire.cta.shared::cta.b64 P1, [%0], %1, 0x989680;\n\t"
        "@P1 bra.uni WAIT_DONE_%=;\n\t"
        "bra.uni WAIT_LOOP_%=;\n\t"
        "WAIT_DONE_%=:\n\t}"
        :: "r"(mbar), "r"(parity) : "memory");
}

// smem geometry: rows of 32 halves + 8 pad -> stride 40 halves, conflict-free ldsm
#define HTS       40
#define NS        4
#define STG_BYTES (2 * BLK_B)               // 20480
#define GEMM_SMEM (1024 + NS * STG_BYTES)   // 82944 B

// ==========================================================================
// Prepass A: weights -> fp16 blocked layouts
// ==========================================================================
__global__ __launch_bounds__(256) void p_weights(
    const float* __restrict__ Wc1, const float* __restrict__ Ws1,
    const float* __restrict__ Wc2, const float* __restrict__ Ws2)
{
    const int total1 = 1024 * C_DIM;
    const int total2 = 256 * HIDD;
    for (int idx = blockIdx.x * 256 + threadIdx.x; idx < total1 + total2;
         idx += gridDim.x * 256) {
        if (idx < total1) {
            int o = idx / C_DIM, k = idx - o * C_DIM;
            float v = (o < 512) ? Wc1[idx] : Ws1[idx - 512 * C_DIM];
            g_w1b[(size_t)((o >> 7) * 48 + (k >> 5)) * BLK_H + (o & 127) * HTS + (k & 31)]
                = __float2half_rn(v);
        } else {
            int j = idx - total1;
            int o = j >> 9, k = j & 511;
            float v = (o < 128) ? Wc2[j]
                    : (o < 192) ? Ws2[j - 128 * HIDD] : 0.f;
            g_w2b[(size_t)((o >> 7) * 16 + (k >> 5)) * BLK_H + (o & 127) * HTS + (k & 31)]
                = __float2half_rn(v);
        }
    }
}

// ==========================================================================
// Prepass B: x[b][c][n] -> blocked g_xb (transpose + fp16)
// ==========================================================================
__global__ __launch_bounds__(256) void p_xt(const float* __restrict__ x)
{
    __shared__ float sm[32][33];
    const int b  = blockIdx.z;
    const int ct = blockIdx.x * 32;
    const int nt = blockIdx.y * 32;
    const int tx = threadIdx.x & 31;
    const int ty = threadIdx.x >> 5;

#pragma unroll
    for (int i = 0; i < 4; i++) {
        int c = ct + ty + i * 8;
        sm[ty + i * 8][tx] = x[((size_t)b * C_DIM + c) * N_TOK + nt + tx];
    }
    __syncthreads();
    const int kt = ct >> 5;
#pragma unroll
    for (int i = 0; i < 4; i++) {
        int n = nt + ty + i * 8;
        size_t dst = (size_t)(((b * 2) + (n >> 7)) * 48 + kt) * BLK_H
                   + (n & 127) * HTS + tx;
        g_xb[dst] = __float2half_rn(sm[tx][ty + i * 8]);
    }
}

// ==========================================================================
// Kernel 1 (fp16 mma.sync + bulk-copy pipeline): h[n][o] = relu(x^T W1^T + b1)
// ==========================================================================
__global__ __launch_bounds__(256, 2) void k1_mma(
    const float* __restrict__ bc1, const float* __restrict__ bs1)
{
    extern __shared__ __half smh[];
    const uint32_t sbase = (uint32_t)__cvta_generic_to_shared(smh);
    const uint32_t mb    = sbase;
    const uint32_t st0   = sbase + 1024;

    const int b  = blockIdx.z;
    const int mt = blockIdx.y;
    const int nt = blockIdx.x;

    const __half* Asrc = g_xb  + (size_t)((b * 2 + nt) * 48) * BLK_H;
    const __half* Bsrc = g_w1b + (size_t)(mt * 48) * BLK_H;
    const float*  bias = (mt < 4) ? (bc1 + mt * 128) : (bs1 + (mt - 4) * 128);

    const int tid  = threadIdx.x;
    const int warp = tid >> 5, lane = tid & 31;
    const int g = lane >> 2, t = lane & 3;
    const int wm = warp >> 2, wn = warp & 3;

    const int lrow = lane & 15;
    const int lcol = (lane >> 4) * 8;

    const uint32_t a_base = st0 + (uint32_t)((wm * 64 + lrow) * HTS + lcol) * 2u;
    const uint32_t b_base = st0 + BLK_B + (uint32_t)((wn * 32 + lrow) * HTS + lcol) * 2u;

    if (tid == 0) {
#pragma unroll
        for (int s = 0; s < NS; s++) MBAR_INIT(mb + 8 * s, 1);
    }
    __syncthreads();
    if (tid == 0) {
#pragma unroll
        for (int s = 0; s < NS; s++) {
            MBAR_EXPECT_TX(mb + 8 * s, STG_BYTES);
            BULK_G2S(st0 + s * STG_BYTES,         Asrc + (size_t)s * BLK_H, BLK_B, mb + 8 * s);
            BULK_G2S(st0 + s * STG_BYTES + BLK_B, Bsrc + (size_t)s * BLK_H, BLK_B, mb + 8 * s);
        }
    }

    float acc[4][4][4];
#pragma unroll
    for (int i = 0; i < 4; i++)
#pragma unroll
        for (int j = 0; j < 4; j++)
#pragma unroll
            for (int q = 0; q < 4; q++) acc[i][j][q] = 0.f;

    const int KT = C_DIM / 32;   // 48
    for (int kt = 0; kt < KT; kt++) {
        const int s = kt & (NS - 1);
        const uint32_t parity = (kt >> 2) & 1;
        mbar_wait(mb + 8 * s, parity);

        const uint32_t abuf = a_base + s * STG_BYTES;
        const uint32_t bbuf = b_base + s * STG_BYTES;

#pragma unroll
        for (int kk = 0; kk < 2; kk++) {
            uint32_t af[4][4];
#pragma unroll
            for (int mi = 0; mi < 4; mi++)
                ldsm_x4(af[mi][0], af[mi][1], af[mi][2], af[mi][3],
                        abuf + mi * (16 * HTS * 2) + kk * 32);
            uint32_t bf[4][2];
#pragma unroll
            for (int nip = 0; nip < 2; nip++) {
                uint32_t r0, r1, r2, r3;
                ldsm_x4(r0, r1, r2, r3, bbuf + nip * (16 * HTS * 2) + kk * 32);
                bf[2 * nip + 0][0] = r0; bf[2 * nip + 0][1] = r2;
                bf[2 * nip + 1][0] = r1; bf[2 * nip + 1][1] = r3;
            }
#pragma unroll
            for (int mi = 0; mi < 4; mi++)
#pragma unroll
                for (int ni = 0; ni < 4; ni++)
                    mma_f16(acc[mi][ni], af[mi], bf[ni]);
        }
        __syncthreads();
        if (tid == 0 && kt + NS < KT) {
            const int kn = kt + NS;
            MBAR_EXPECT_TX(mb + 8 * s, STG_BYTES);
            BULK_G2S(st0 + s * STG_BYTES,         Asrc + (size_t)kn * BLK_H, BLK_B, mb + 8 * s);
            BULK_G2S(st0 + s * STG_BYTES + BLK_B, Bsrc + (size_t)kn * BLK_H, BLK_B, mb + 8 * s);
        }
    }

    float bvv[4][2];
#pragma unroll
    for (int ni = 0; ni < 4; ni++) {
        int col = wn * 32 + ni * 8 + t * 2;
        bvv[ni][0] = __ldg(bias + col);
        bvv[ni][1] = __ldg(bias + col + 1);
    }
    __half* Ob = g_hb + (size_t)((b * 2 + nt) * 32 + mt * 4 + wn) * BLK_H;
#pragma unroll
    for (int mi = 0; mi < 4; mi++) {
#pragma unroll
        for (int q2 = 0; q2 < 2; q2++) {
            int row = wm * 64 + mi * 16 + q2 * 8 + g;
#pragma unroll
            for (int ni = 0; ni < 4; ni++) {
                int c = ni * 8 + t * 2;
                __half2 hv = __floats2half2_rn(
                    fmaxf(acc[mi][ni][q2 * 2 + 0] + bvv[ni][0], 0.f),
                    fmaxf(acc[mi][ni][q2 * 2 + 1] + bvv[ni][1], 0.f));
                *(__half2*)(Ob + row * HTS + c) = hv;
            }
        }
    }
}

// ==========================================================================
// Kernel 2 (fp16 mma.sync + bulk pipeline): f = Wc2 h1 + bc2 ; s = Ws2 h2 + bs2
// ==========================================================================
__global__ __launch_bounds__(256, 2) void k2_mma(
    const float* __restrict__ bc2, const float* __restrict__ bs2)
{
    extern __shared__ __half smh[];
    const uint32_t sbase = (uint32_t)__cvta_generic_to_shared(smh);
    const uint32_t mb    = sbase;
    const uint32_t st0   = sbase + 1024;

    const int b  = blockIdx.z;
    const int mt = blockIdx.y;
    const int nt = blockIdx.x;

    const __half* Asrc = g_w2b + (size_t)(mt * 16) * BLK_H;
    const __half* Bsrc = g_hb  + (size_t)((b * 2 + nt) * 32 + mt * 16) * BLK_H;

    const int tid  = threadIdx.x;
    const int warp = tid >> 5, lane = tid & 31;
    const int g = lane >> 2, t = lane & 3;
    const int wm = warp >> 2, wn = warp & 3;

    const int lrow = lane & 15;
    const int lcol = (lane >> 4) * 8;

    const uint32_t a_base = st0 + (uint32_t)((wm * 64 + lrow) * HTS + lcol) * 2u;
    const uint32_t b_base = st0 + BLK_B + (uint32_t)((wn * 32 + lrow) * HTS + lcol) * 2u;

    if (tid == 0) {
#pragma unroll
        for (int s = 0; s < NS; s++) MBAR_INIT(mb + 8 * s, 1);
    }
    __syncthreads();
    if (tid == 0) {
#pragma unroll
        for (int s = 0; s < NS; s++) {
            MBAR_EXPECT_TX(mb + 8 * s, STG_BYTES);
            BULK_G2S(st0 + s * STG_BYTES,         Asrc + (size_t)s * BLK_H, BLK_B, mb + 8 * s);
            BULK_G2S(st0 + s * STG_BYTES + BLK_B, Bsrc + (size_t)s * BLK_H, BLK_B, mb + 8 * s);
        }
    }

    float acc[4][4][4];
#pragma unroll
    for (int i = 0; i < 4; i++)
#pragma unroll
        for (int j = 0; j < 4; j++)
#pragma unroll
            for (int q = 0; q < 4; q++) acc[i][j][q] = 0.f;

    const int KT = HIDD / 32;   // 16
    for (int kt = 0; kt < KT; kt++) {
        const int s = kt & (NS - 1);
        const uint32_t parity = (kt >> 2) & 1;
        mbar_wait(mb + 8 * s, parity);

        const uint32_t abuf = a_base + s * STG_BYTES;
        const uint32_t bbuf = b_base + s * STG_BYTES;

#pragma unroll
        for (int kk = 0; kk < 2; kk++) {
            uint32_t af[4][4];
#pragma unroll
            for (int mi = 0; mi < 4; mi++)
                ldsm_x4(af[mi][0], af[mi][1], af[mi][2], af[mi][3],
                        abuf + mi * (16 * HTS * 2) + kk * 32);
            uint32_t bf[4][2];
#pragma unroll
            for (int nip = 0; nip < 2; nip++) {
                uint32_t r0, r1, r2, r3;
                ldsm_x4(r0, r1, r2, r3, bbuf + nip * (16 * HTS * 2) + kk * 32);
                bf[2 * nip + 0][0] = r0; bf[2 * nip + 0][1] = r2;
                bf[2 * nip + 1][0] = r1; bf[2 * nip + 1][1] = r3;
            }
#pragma unroll
            for (int mi = 0; mi < 4; mi++)
#pragma unroll
                for (int ni = 0; ni < 4; ni++)
                    mma_f16(acc[mi][ni], af[mi], bf[ni]);
        }
        __syncthreads();
        if (tid == 0 && kt + NS < KT) {
            const int kn = kt + NS;
            MBAR_EXPECT_TX(mb + 8 * s, STG_BYTES);
            BULK_G2S(st0 + s * STG_BYTES,         Asrc + (size_t)kn * BLK_H, BLK_B, mb + 8 * s);
            BULK_G2S(st0 + s * STG_BYTES + BLK_B, Bsrc + (size_t)kn * BLK_H, BLK_B, mb + 8 * s);
        }
    }

#pragma unroll
    for (int mi = 0; mi < 4; mi++) {
#pragma unroll
        for (int q2 = 0; q2 < 2; q2++) {
            int row = wm * 64 + mi * 16 + q2 * 8 + g;
            if (mt == 0) {
                float bv = __ldg(bc2 + row);
#pragma unroll
                for (int ni = 0; ni < 4; ni++) {
                    int col = nt * 128 + wn * 32 + ni * 8 + t * 2;
                    float2 v;
                    v.x = acc[mi][ni][q2 * 2 + 0] + bv;
                    v.y = acc[mi][ni][q2 * 2 + 1] + bv;
                    *(float2*)(g_f + ((size_t)b * L_DIM + row) * N_TOK + col) = v;
                }
            } else if (row < 64) {
                float bv = __ldg(bs2 + row);
#pragma unroll
                for (int ni = 0; ni < 4; ni++) {
                    int col = nt * 128 + wn * 32 + ni * 8 + t * 2;
                    float2 v;
                    v.x = acc[mi][ni][q2 * 2 + 0] + bv;
                    v.y = acc[mi][ni][q2 * 2 + 1] + bv;
                    *(float2*)(g_s + ((size_t)b * M_CL + row) * N_TOK + col) = v;
                }
            }
        }
    }
}

// ==========================================================================
// Kernel 3 (v3, 8-wide ILP): token MLP + L2 norm -> out[b][0:256]
// Warp-cooperative dots with 8 independent output accumulators per group ->
// 8 independent LDG.128 per k-step (MLP ~16 instead of ~2).
// ==========================================================================
__global__ __launch_bounds__(256) void k3_token(
    const float* __restrict__ t,
    const float* __restrict__ Wt1, const float* __restrict__ bt1,
    const float* __restrict__ Wt2, const float* __restrict__ bt2,
    float* __restrict__ out)
{
    __shared__ float ts[C_DIM];
    __shared__ float th[HIDD];
    __shared__ float tg[G_DIM];
    __shared__ float red[8];

    const int b    = blockIdx.x;
    const int tid  = threadIdx.x;
    const int warp = tid >> 5;
    const int lane = tid & 31;

    for (int i = tid; i < C_DIM / 4; i += 256)
        ((float4*)ts)[i] = ((const float4*)(t + (size_t)b * C_DIM))[i];
    __syncthreads();

    // layer 1: 512 outputs; warp computes 64, in 8 groups of 8
    const float4* tv4 = (const float4*)ts;
    for (int gq = 0; gq < 8; gq++) {
        const int o0 = warp * 64 + gq * 8;
        const float4* wbase = (const float4*)(Wt1 + (size_t)o0 * C_DIM);
        float a[8];
#pragma unroll
        for (int r = 0; r < 8; r++) a[r] = 0.f;
#pragma unroll
        for (int j = 0; j < C_DIM / 128; j++) {   // 12
            float4 tv = tv4[j * 32 + lane];
#pragma unroll
            for (int r = 0; r < 8; r++) {
                float4 v = __ldg(wbase + (size_t)r * (C_DIM / 4) + j * 32 + lane);
                a[r] += v.x * tv.x + v.y * tv.y + v.z * tv.z + v.w * tv.w;
            }
        }
#pragma unroll
        for (int r = 0; r < 8; r++)
#pragma unroll
            for (int off = 16; off; off >>= 1)
                a[r] += __shfl_xor_sync(0xffffffffu, a[r], off);
        if (lane == 0) {
#pragma unroll
            for (int r = 0; r < 8; r++)
                th[o0 + r] = fmaxf(a[r] + __ldg(bt1 + o0 + r), 0.f);
        }
    }
    __syncthreads();

    // layer 2: 256 outputs; warp computes 32, in 4 groups of 8
    const float4* hv4 = (const float4*)th;
    for (int gq = 0; gq < 4; gq++) {
        const int o0 = warp * 32 + gq * 8;
        const float4* wbase = (const float4*)(Wt2 + (size_t)o0 * HIDD);
        float a[8];
#pragma unroll
        for (int r = 0; r < 8; r++) a[r] = 0.f;
#pragma unroll
        for (int j = 0; j < HIDD / 128; j++) {    // 4
            float4 hv = hv4[j * 32 + lane];
#pragma unroll
            for (int r = 0; r < 8; r++) {
                float4 v = __ldg(wbase + (size_t)r * (HIDD / 4) + j * 32 + lane);
                a[r] += v.x * hv.x + v.y * hv.y + v.z * hv.z + v.w * hv.w;
            }
        }
#pragma unroll
        for (int r = 0; r < 8; r++)
#pragma unroll
            for (int off = 16; off; off >>= 1)
                a[r] += __shfl_xor_sync(0xffffffffu, a[r], off);
        if (lane == 0) {
#pragma unroll
            for (int r = 0; r < 8; r++)
                tg[o0 + r] = a[r] + __ldg(bt2 + o0 + r);
        }
    }
    __syncthreads();

    // L2 norm over the 256 token features
    float val = tg[tid];
    float ss = val * val;
#pragma unroll
    for (int off = 16; off; off >>= 1) ss += __shfl_xor_sync(0xffffffffu, ss, off);
    if (lane == 0) red[warp] = ss;
    __syncthreads();
    float tot = 0.f;
#pragma unroll
    for (int i = 0; i < 8; i++) tot += red[i];
    float sc = 1.f / fmaxf(sqrtf(tot), 1e-12f);
    out[(size_t)b * OUT_PER_B + tid] = val * sc;
}

// ==========================================================================
// Kernel 4 (v2): Sinkhorn -> g_p ; column LSE now two-pass, 4-way unrolled
// ==========================================================================
__global__ __launch_bounds__(256) void k4_sinkhorn(const float* __restrict__ dustp)
{
    extern __shared__ float sh[];
    float* Ms = sh;
    float* u  = sh + 65 * 256;
    float* v  = u + 72;

    const int b   = blockIdx.x;
    const int tid = threadIdx.x;
    const float dust = *dustp;
    const float* S = g_s + (size_t)b * M_CL * N_TOK;

    for (int i = tid; i < 64 * 256; i += 256) Ms[i] = S[i];
    Ms[64 * 256 + tid] = dust;
    v[tid] = 0.f;
    __syncthreads();

    const int w    = tid >> 5;
    const int lane = tid & 31;

    for (int it = 0; it < 3; it++) {
        // u[r] = log_a[r] - LSE_n(Ms[r][:] + v);  warp per row
        for (int r = w; r < 65; r += 8) {
            float vals[8];
            float mx = -INFINITY;
#pragma unroll
            for (int q = 0; q < 8; q++) {
                float vv = Ms[r * 256 + lane + 32 * q] + v[lane + 32 * q];
                vals[q] = vv;
                mx = fmaxf(mx, vv);
            }
#pragma unroll
            for (int off = 16; off; off >>= 1)
                mx = fmaxf(mx, __shfl_xor_sync(0xffffffffu, mx, off));
            float ssum = 0.f;
#pragma unroll
            for (int q = 0; q < 8; q++) ssum += expf(vals[q] - mx);
#pragma unroll
            for (int off = 16; off; off >>= 1)
                ssum += __shfl_xor_sync(0xffffffffu, ssum, off);
            if (lane == 0) {
                float la = (r == 64) ? LOGA_LAST : NEG_LOG320;
                u[r] = la - (mx + logf(ssum));
            }
        }
        __syncthreads();
        // v[j] = log_b - LSE_m(Ms[:,j] + u);  two-pass, 4-way unrolled
        {
            float m0 = -INFINITY, m1 = -INFINITY, m2 = -INFINITY, m3 = -INFINITY;
#pragma unroll
            for (int m = 0; m < 64; m += 4) {
                m0 = fmaxf(m0, Ms[(m + 0) * 256 + tid] + u[m + 0]);
                m1 = fmaxf(m1, Ms[(m + 1) * 256 + tid] + u[m + 1]);
                m2 = fmaxf(m2, Ms[(m + 2) * 256 + tid] + u[m + 2]);
                m3 = fmaxf(m3, Ms[(m + 3) * 256 + tid] + u[m + 3]);
            }
            float mx = fmaxf(fmaxf(m0, m1), fmaxf(m2, m3));
            mx = fmaxf(mx, Ms[64 * 256 + tid] + u[64]);
            float s0 = 0.f, s1 = 0.f, s2 = 0.f, s3 = 0.f;
#pragma unroll
            for (int m = 0; m < 64; m += 4) {
                s0 += expf(Ms[(m + 0) * 256 + tid] + u[m + 0] - mx);
                s1 += expf(Ms[(m + 1) * 256 + tid] + u[m + 1] - mx);
                s2 += expf(Ms[(m + 2) * 256 + tid] + u[m + 2] - mx);
                s3 += expf(Ms[(m + 3) * 256 + tid] + u[m + 3] - mx);
            }
            float s = (s0 + s1) + (s2 + s3) + expf(Ms[64 * 256 + tid] + u[64] - mx);
            v[tid] = NEG_LOG320 - (mx + logf(s));
        }
        __syncthreads();
    }

    float* P = g_p + (size_t)b * M_CL * N_TOK;
    for (int i = tid; i < 64 * 256; i += 256) {
        int m = i >> 8, j = i & 255;
        P[i] = expf(Ms[i] + u[m] + v[j] - NEG_LOG320);
    }
}

// ==========================================================================
// Kernel 5: VLAD + intra-norm
// ==========================================================================
#define PS_LD 260
__global__ __launch_bounds__(256) void k5_vlad(float* __restrict__ out)
{
    extern __shared__ float sh[];
    float* ps  = sh;
    float* vs  = sh + 64 * PS_LD;
    float* inv = vs + 128 * 64;

    const int b   = blockIdx.x;
    const int tid = threadIdx.x;
    const float* P = g_p + (size_t)b * M_CL * N_TOK;
    const float* F = g_f + (size_t)b * L_DIM * N_TOK;

    for (int i = tid; i < 64 * 256; i += 256) {
        int m = i >> 8, n = i & 255;
        ps[m * PS_LD + n] = P[i];
    }
    __syncthreads();

    const int m  = tid & 63;
    const int lg = tid >> 6;

    const float4* pr = (const float4*)(ps + m * PS_LD);

    float acc[32];
#pragma unroll
    for (int i = 0; i < 32; i++) acc[i] = 0.f;

    for (int nc = 0; nc < 64; nc += 4) {
        float4 pv0 = pr[nc + 0], pv1 = pr[nc + 1], pv2 = pr[nc + 2], pv3 = pr[nc + 3];
#pragma unroll
        for (int li = 0; li < 32; li++) {
            const float4* fr = (const float4*)(F + (size_t)(lg * 32 + li) * N_TOK);
            float4 f0 = fr[nc + 0], f1 = fr[nc + 1], f2 = fr[nc + 2], f3 = fr[nc + 3];
            float a = acc[li];
            a += f0.x * pv0.x + f0.y * pv0.y + f0.z * pv0.z + f0.w * pv0.w;
            a += f1.x * pv1.x + f1.y * pv1.y + f1.z * pv1.z + f1.w * pv1.w;
            a += f2.x * pv2.x + f2.y * pv2.y + f2.z * pv2.z + f2.w * pv2.w;
            a += f3.x * pv3.x + f3.y * pv3.y + f3.z * pv3.z + f3.w * pv3.w;
            acc[li] = a;
        }
    }
#pragma unroll
    for (int li = 0; li < 32; li++) vs[(lg * 32 + li) * 64 + m] = acc[li];
    __syncthreads();

    if (tid < 64) {
        float ss = 0.f;
        for (int l = 0; l < 128; l++) {
            float vv = vs[l * 64 + tid];
            ss += vv * vv;
        }
        inv[tid] = 1.f / fmaxf(sqrtf(ss), 1e-12f);
    }
    __syncthreads();

    float* Ob = out + (size_t)b * OUT_PER_B + G_DIM;
    for (int i = tid; i < L_DIM * M_CL; i += 256) Ob[i] = vs[i] * inv[i & 63];
}

// ==========================================================================
// Kernel 6: final L2 norm
// ==========================================================================
__global__ __launch_bounds__(256) void k6_norm(float* __restrict__ out)
{
    __shared__ float red[8];
    __shared__ float sc_s;
    const int b   = blockIdx.x;
    const int tid = threadIdx.x;
    float* O = out + (size_t)b * OUT_PER_B;

    float ss = 0.f;
    for (int i = tid; i < OUT_PER_B; i += 256) {
        float vv = O[i];
        ss += vv * vv;
    }
#pragma unroll
    for (int off = 16; off; off >>= 1) ss += __shfl_xor_sync(0xffffffffu, ss, off);
    if ((tid & 31) == 0) red[tid >> 5] = ss;
    __syncthreads();
    if (tid == 0) {
        float tot = 0.f;
#pragma unroll
        for (int i = 0; i < 8; i++) tot += red[i];
        sc_s = 1.f / fmaxf(sqrtf(tot), 1e-12f);
    }
    __syncthreads();
    float sc = sc_s;
    for (int i = tid; i < OUT_PER_B; i += 256) O[i] *= sc;
}

// ==========================================================================
// launch  (k3 at launch index 3 so ncu verifies the rewrite)
// ==========================================================================
extern "C" void kernel_launch(void* const* d_in, const int* in_sizes, int n_in,
                              void* d_out, int out_size)
{
    (void)in_sizes; (void)n_in; (void)out_size;
    const float* x    = (const float*)d_in[0];
    const float* t    = (const float*)d_in[1];
    const float* Wt1  = (const float*)d_in[2];
    const float* bt1  = (const float*)d_in[3];
    const float* Wt2  = (const float*)d_in[4];
    const float* bt2  = (const float*)d_in[5];
    const float* Wc1  = (const float*)d_in[6];
    const float* bc1  = (const float*)d_in[7];
    const float* Wc2  = (const float*)d_in[8];
    const float* bc2  = (const float*)d_in[9];
    const float* Ws1  = (const float*)d_in[10];
    const float* bs1  = (const float*)d_in[11];
    const float* Ws2  = (const float*)d_in[12];
    const float* bs2  = (const float*)d_in[13];
    const float* dust = (const float*)d_in[14];
    float* out = (float*)d_out;

    const int sink_smem = (65 * 256 + 72 + 256) * (int)sizeof(float);
    const int vlad_smem = (64 * PS_LD + 128 * 64 + 64) * (int)sizeof(float);
    cudaFuncSetAttribute(k1_mma,      cudaFuncAttributeMaxDynamicSharedMemorySize, GEMM_SMEM);
    cudaFuncSetAttribute(k2_mma,      cudaFuncAttributeMaxDynamicSharedMemorySize, GEMM_SMEM);
    cudaFuncSetAttribute(k4_sinkhorn, cudaFuncAttributeMaxDynamicSharedMemorySize, sink_smem);
    cudaFuncSetAttribute(k5_vlad,     cudaFuncAttributeMaxDynamicSharedMemorySize, vlad_smem);

    p_weights<<<512, 256>>>(Wc1, Ws1, Wc2, Ws2);                 // idx 0
    p_xt<<<dim3(48, 8, B_SZ), 256>>>(x);                         // idx 1
    k1_mma<<<dim3(2, 8, B_SZ), 256, GEMM_SMEM>>>(bc1, bs1);      // idx 2
    k3_token<<<B_SZ, 256>>>(t, Wt1, bt1, Wt2, bt2, out);         // idx 3 (ncu target)
    k2_mma<<<dim3(2, 2, B_SZ), 256, GEMM_SMEM>>>(bc2, bs2);      // idx 4
    k4_sinkhorn<<<B_SZ, 256, sink_smem>>>(dust);                 // idx 5
    k5_vlad<<<B_SZ, 256, vlad_smem>>>(out);                      // idx 6
    k6_norm<<<B_SZ, 256>>>(out);                                 // idx 7
}

// round 10
// speedup vs baseline: 6.2018x; 1.3946x over previous
#include <cuda_runtime.h>
#include <cuda_fp16.h>
#include <math.h>
#include <stdint.h>

// ---------------- problem constants ----------------
#define B_SZ   64
#define C_DIM  1536
#define N_TOK  256
#define HIDD   512
#define L_DIM  128
#define G_DIM  256
#define M_CL   64
#define OUT_PER_B (G_DIM + L_DIM * M_CL)   // 8448

#define NEG_LOG320 (-5.768320995793772f)
#define LOGA_LAST  (-0.510825623765991f)

// blocked tile: 128 rows x 40 halves (32 data + 8 pad) = 5120 halves = 10240 B
#define BLK_H   5120
#define BLK_B   10240

// ---------------- scratch (blocked, pre-padded layouts) ----------------
__device__ __half g_xb  [B_SZ * 2 * 48 * BLK_H];  // x^T blocked
__device__ __half g_hb  [B_SZ * 2 * 32 * BLK_H];  // hidden blocked
__device__ __half g_w1b [8 * 48 * BLK_H];         // [Wc1;Ws1] blocked
__device__ __half g_w2b [2 * 16 * BLK_H];         // [Wc2;Ws2pad] blocked
__device__ __half g_wt1b[4 * 48 * BLK_H];         // Wt1 blocked (4 tiles x 48 kt)
__device__ __half g_wt2b[2 * 16 * BLK_H];         // Wt2 blocked (2 tiles x 16 kt)
__device__ __half g_tb  [48 * BLK_H];             // tokens t blocked (rows 64-127 stay 0)
__device__ __half g_thb [16 * BLK_H];             // token hidden blocked (512 cols)
__device__ float  g_tg[B_SZ * G_DIM];             // token logits [tok][256]
__device__ float  g_f[B_SZ * L_DIM * N_TOK];
__device__ float  g_s[B_SZ * M_CL * N_TOK];
__device__ float  g_p[B_SZ * M_CL * N_TOK];

// ---------------- helpers ----------------
__device__ __forceinline__ void ldsm_x4(uint32_t& r0, uint32_t& r1, uint32_t& r2, uint32_t& r3,
                                        uint32_t addr) {
    asm volatile("ldmatrix.sync.aligned.m8n8.x4.shared.b16 {%0,%1,%2,%3}, [%4];"
        : "=r"(r0), "=r"(r1), "=r"(r2), "=r"(r3) : "r"(addr));
}

__device__ __forceinline__ void mma_f16(float* d, const uint32_t* a, const uint32_t* b) {
    asm volatile(
        "mma.sync.aligned.m16n8k16.row.col.f32.f16.f16.f32 "
        "{%0,%1,%2,%3}, {%4,%5,%6,%7}, {%8,%9}, {%0,%1,%2,%3};"
        : "+f"(d[0]), "+f"(d[1]), "+f"(d[2]), "+f"(d[3])
        : "r"(a[0]), "r"(a[1]), "r"(a[2]), "r"(a[3]), "r"(b[0]), "r"(b[1]));
}

#define MBAR_INIT(mbar, cnt) \
    asm volatile("mbarrier.init.shared.b64 [%0], %1;" :: "r"(mbar), "r"((uint32_t)(cnt)) : "memory")
#define MBAR_EXPECT_TX(mbar, bytes) \
    asm volatile("mbarrier.arrive.expect_tx.shared.b64 _, [%0], %1;" \
                 :: "r"(mbar), "r"((uint32_t)(bytes)) : "memory")
#define BULK_G2S(dst_smem, gsrc, bytes, mbar) \
    asm volatile("cp.async.bulk.shared::cta.global.mbarrier::complete_tx::bytes [%0], [%1], %2, [%3];" \
                 :: "r"(dst_smem), "l"(gsrc), "r"((uint32_t)(bytes)), "r"(mbar) : "memory")

__device__ __forceinline__ void mbar_wait(uint32_t mbar, uint32_t parity) {
    asm volatile(
        "{\n\t.reg .pred P1;\n\t"
        "WAIT_LOOP_%=:\n\t"
        "mbarrier.try_wait.parity.acquire.cta.shared::cta.b64 P1, [%0], %1, 0x989680;\n\t"
        "@P1 bra.uni WAIT_DONE_%=;\n\t"
        "bra.uni WAIT_LOOP_%=;\n\t"
        "WAIT_DONE_%=:\n\t}"
        :: "r"(mbar), "r"(parity) : "memory");
}

#define HTS       40
#define NS        4
#define STG_BYTES (2 * BLK_B)               // 20480
#define GEMM_SMEM (1024 + NS * STG_BYTES)   // 82944 B

// ==========================================================================
// Prepass A: all weights + token vector -> fp16 blocked layouts
// segments: W1(1024x1536) | W2pad(256x512) | Wt1(512x1536) | Wt2(256x512) | t(64x1536)
// ==========================================================================
__global__ __launch_bounds__(256) void p_weights(
    const float* __restrict__ Wc1, const float* __restrict__ Ws1,
    const float* __restrict__ Wc2, const float* __restrict__ Ws2,
    const float* __restrict__ Wt1, const float* __restrict__ Wt2,
    const float* __restrict__ t)
{
    const int n1 = 1024 * C_DIM;
    const int n2 = 256 * HIDD;
    const int n3 = 512 * C_DIM;
    const int n4 = 256 * HIDD;
    const int n5 = B_SZ * C_DIM;
    const int total = n1 + n2 + n3 + n4 + n5;
    for (int idx = blockIdx.x * 256 + threadIdx.x; idx < total; idx += gridDim.x * 256) {
        if (idx < n1) {
            int o = idx / C_DIM, k = idx - o * C_DIM;
            float v = (o < 512) ? Wc1[idx] : Ws1[idx - 512 * C_DIM];
            g_w1b[(size_t)((o >> 7) * 48 + (k >> 5)) * BLK_H + (o & 127) * HTS + (k & 31)]
                = __float2half_rn(v);
        } else if (idx < n1 + n2) {
            int j = idx - n1;
            int o = j >> 9, k = j & 511;
            float v = (o < 128) ? Wc2[j]
                    : (o < 192) ? Ws2[j - 128 * HIDD] : 0.f;
            g_w2b[(size_t)((o >> 7) * 16 + (k >> 5)) * BLK_H + (o & 127) * HTS + (k & 31)]
                = __float2half_rn(v);
        } else if (idx < n1 + n2 + n3) {
            int j = idx - n1 - n2;
            int o = j / C_DIM, k = j - o * C_DIM;
            g_wt1b[(size_t)((o >> 7) * 48 + (k >> 5)) * BLK_H + (o & 127) * HTS + (k & 31)]
                = __float2half_rn(Wt1[j]);
        } else if (idx < n1 + n2 + n3 + n4) {
            int j = idx - n1 - n2 - n3;
            int o = j >> 9, k = j & 511;
            g_wt2b[(size_t)((o >> 7) * 16 + (k >> 5)) * BLK_H + (o & 127) * HTS + (k & 31)]
                = __float2half_rn(Wt2[j]);
        } else {
            int j = idx - n1 - n2 - n3 - n4;
            int r = j / C_DIM, k = j - r * C_DIM;   // r < 64; rows 64-127 stay zero
            g_tb[(size_t)(k >> 5) * BLK_H + r * HTS + (k & 31)] = __float2half_rn(t[j]);
        }
    }
}

// ==========================================================================
// Prepass B: x[b][c][n] -> blocked g_xb (transpose + fp16)
// ==========================================================================
__global__ __launch_bounds__(256) void p_xt(const float* __restrict__ x)
{
    __shared__ float sm[32][33];
    const int b  = blockIdx.z;
    const int ct = blockIdx.x * 32;
    const int nt = blockIdx.y * 32;
    const int tx = threadIdx.x & 31;
    const int ty = threadIdx.x >> 5;

#pragma unroll
    for (int i = 0; i < 4; i++) {
        int c = ct + ty + i * 8;
        sm[ty + i * 8][tx] = x[((size_t)b * C_DIM + c) * N_TOK + nt + tx];
    }
    __syncthreads();
    const int kt = ct >> 5;
#pragma unroll
    for (int i = 0; i < 4; i++) {
        int n = nt + ty + i * 8;
        size_t dst = (size_t)(((b * 2) + (n >> 7)) * 48 + kt) * BLK_H
                   + (n & 127) * HTS + tx;
        g_xb[dst] = __float2half_rn(sm[tx][ty + i * 8]);
    }
}

// ==========================================================================
// Kernel 1: h = relu(x^T W1^T + b1) (mt 0..7) + token layer1 (mt==8, 4 CTAs)
// grid (2, 9, 64)
// ==========================================================================
__global__ __launch_bounds__(256, 2) void k1_mma(
    const float* __restrict__ bc1, const float* __restrict__ bs1,
    const float* __restrict__ bt1)
{
    const int b  = blockIdx.z;
    const int mt = blockIdx.y;
    const int nt = blockIdx.x;

    const bool token = (mt == 8);
    if (token && (nt != 0 || b >= 4)) return;

    extern __shared__ __half smh[];
    const uint32_t sbase = (uint32_t)__cvta_generic_to_shared(smh);
    const uint32_t mb    = sbase;
    const uint32_t st0   = sbase + 1024;

    const __half* Asrc;
    const __half* Bsrc;
    const float*  bias;
    __half*       Odst;
    if (token) {
        Asrc = g_tb;
        Bsrc = g_wt1b + (size_t)(b * 48) * BLK_H;
        bias = bt1 + b * 128;
        Odst = g_thb + (size_t)(b * 4) * BLK_H;
    } else {
        Asrc = g_xb  + (size_t)((b * 2 + nt) * 48) * BLK_H;
        Bsrc = g_w1b + (size_t)(mt * 48) * BLK_H;
        bias = (mt < 4) ? (bc1 + mt * 128) : (bs1 + (mt - 4) * 128);
        Odst = g_hb + (size_t)((b * 2 + nt) * 32 + mt * 4) * BLK_H;
    }

    const int tid  = threadIdx.x;
    const int warp = tid >> 5, lane = tid & 31;
    const int g = lane >> 2, t = lane & 3;
    const int wm = warp >> 2, wn = warp & 3;

    const int lrow = lane & 15;
    const int lcol = (lane >> 4) * 8;

    const uint32_t a_base = st0 + (uint32_t)((wm * 64 + lrow) * HTS + lcol) * 2u;
    const uint32_t b_base = st0 + BLK_B + (uint32_t)((wn * 32 + lrow) * HTS + lcol) * 2u;

    if (tid == 0) {
#pragma unroll
        for (int s = 0; s < NS; s++) MBAR_INIT(mb + 8 * s, 1);
    }
    __syncthreads();
    if (tid == 0) {
#pragma unroll
        for (int s = 0; s < NS; s++) {
            MBAR_EXPECT_TX(mb + 8 * s, STG_BYTES);
            BULK_G2S(st0 + s * STG_BYTES,         Asrc + (size_t)s * BLK_H, BLK_B, mb + 8 * s);
            BULK_G2S(st0 + s * STG_BYTES + BLK_B, Bsrc + (size_t)s * BLK_H, BLK_B, mb + 8 * s);
        }
    }

    float acc[4][4][4];
#pragma unroll
    for (int i = 0; i < 4; i++)
#pragma unroll
        for (int j = 0; j < 4; j++)
#pragma unroll
            for (int q = 0; q < 4; q++) acc[i][j][q] = 0.f;

    const int KT = C_DIM / 32;   // 48
    for (int kt = 0; kt < KT; kt++) {
        const int s = kt & (NS - 1);
        const uint32_t parity = (kt >> 2) & 1;
        mbar_wait(mb + 8 * s, parity);

        const uint32_t abuf = a_base + s * STG_BYTES;
        const uint32_t bbuf = b_base + s * STG_BYTES;

#pragma unroll
        for (int kk = 0; kk < 2; kk++) {
            uint32_t af[4][4];
#pragma unroll
            for (int mi = 0; mi < 4; mi++)
                ldsm_x4(af[mi][0], af[mi][1], af[mi][2], af[mi][3],
                        abuf + mi * (16 * HTS * 2) + kk * 32);
            uint32_t bf[4][2];
#pragma unroll
            for (int nip = 0; nip < 2; nip++) {
                uint32_t r0, r1, r2, r3;
                ldsm_x4(r0, r1, r2, r3, bbuf + nip * (16 * HTS * 2) + kk * 32);
                bf[2 * nip + 0][0] = r0; bf[2 * nip + 0][1] = r2;
                bf[2 * nip + 1][0] = r1; bf[2 * nip + 1][1] = r3;
            }
#pragma unroll
            for (int mi = 0; mi < 4; mi++)
#pragma unroll
                for (int ni = 0; ni < 4; ni++)
                    mma_f16(acc[mi][ni], af[mi], bf[ni]);
        }
        __syncthreads();
        if (tid == 0 && kt + NS < KT) {
            const int kn = kt + NS;
            MBAR_EXPECT_TX(mb + 8 * s, STG_BYTES);
            BULK_G2S(st0 + s * STG_BYTES,         Asrc + (size_t)kn * BLK_H, BLK_B, mb + 8 * s);
            BULK_G2S(st0 + s * STG_BYTES + BLK_B, Bsrc + (size_t)kn * BLK_H, BLK_B, mb + 8 * s);
        }
    }

    float bvv[4][2];
#pragma unroll
    for (int ni = 0; ni < 4; ni++) {
        int col = wn * 32 + ni * 8 + t * 2;
        bvv[ni][0] = __ldg(bias + col);
        bvv[ni][1] = __ldg(bias + col + 1);
    }
    __half* Ob = Odst + (size_t)wn * BLK_H;
#pragma unroll
    for (int mi = 0; mi < 4; mi++) {
#pragma unroll
        for (int q2 = 0; q2 < 2; q2++) {
            int row = wm * 64 + mi * 16 + q2 * 8 + g;
#pragma unroll
            for (int ni = 0; ni < 4; ni++) {
                int c = ni * 8 + t * 2;
                __half2 hv = __floats2half2_rn(
                    fmaxf(acc[mi][ni][q2 * 2 + 0] + bvv[ni][0], 0.f),
                    fmaxf(acc[mi][ni][q2 * 2 + 1] + bvv[ni][1], 0.f));
                *(__half2*)(Ob + row * HTS + c) = hv;
            }
        }
    }
}

// ==========================================================================
// Kernel 2: f/s second layers (mt 0..1) + token layer2 (mt==2, 2 CTAs)
// grid (2, 3, 64)
// ==========================================================================
__global__ __launch_bounds__(256, 2) void k2_mma(
    const float* __restrict__ bc2, const float* __restrict__ bs2,
    const float* __restrict__ bt2)
{
    const int b  = blockIdx.z;
    const int mt = blockIdx.y;
    const int nt = blockIdx.x;

    const bool token = (mt == 2);
    if (token && (nt != 0 || b >= 2)) return;

    extern __shared__ __half smh[];
    const uint32_t sbase = (uint32_t)__cvta_generic_to_shared(smh);
    const uint32_t mb    = sbase;
    const uint32_t st0   = sbase + 1024;

    const __half* Asrc;
    const __half* Bsrc;
    if (token) {
        Asrc = g_wt2b + (size_t)(b * 16) * BLK_H;
        Bsrc = g_thb;
    } else {
        Asrc = g_w2b + (size_t)(mt * 16) * BLK_H;
        Bsrc = g_hb  + (size_t)((b * 2 + nt) * 32 + mt * 16) * BLK_H;
    }

    const int tid  = threadIdx.x;
    const int warp = tid >> 5, lane = tid & 31;
    const int g = lane >> 2, t = lane & 3;
    const int wm = warp >> 2, wn = warp & 3;

    const int lrow = lane & 15;
    const int lcol = (lane >> 4) * 8;

    const uint32_t a_base = st0 + (uint32_t)((wm * 64 + lrow) * HTS + lcol) * 2u;
    const uint32_t b_base = st0 + BLK_B + (uint32_t)((wn * 32 + lrow) * HTS + lcol) * 2u;

    if (tid == 0) {
#pragma unroll
        for (int s = 0; s < NS; s++) MBAR_INIT(mb + 8 * s, 1);
    }
    __syncthreads();
    if (tid == 0) {
#pragma unroll
        for (int s = 0; s < NS; s++) {
            MBAR_EXPECT_TX(mb + 8 * s, STG_BYTES);
            BULK_G2S(st0 + s * STG_BYTES,         Asrc + (size_t)s * BLK_H, BLK_B, mb + 8 * s);
            BULK_G2S(st0 + s * STG_BYTES + BLK_B, Bsrc + (size_t)s * BLK_H, BLK_B, mb + 8 * s);
        }
    }

    float acc[4][4][4];
#pragma unroll
    for (int i = 0; i < 4; i++)
#pragma unroll
        for (int j = 0; j < 4; j++)
#pragma unroll
            for (int q = 0; q < 4; q++) acc[i][j][q] = 0.f;

    const int KT = HIDD / 32;   // 16
    for (int kt = 0; kt < KT; kt++) {
        const int s = kt & (NS - 1);
        const uint32_t parity = (kt >> 2) & 1;
        mbar_wait(mb + 8 * s, parity);

        const uint32_t abuf = a_base + s * STG_BYTES;
        const uint32_t bbuf = b_base + s * STG_BYTES;

#pragma unroll
        for (int kk = 0; kk < 2; kk++) {
            uint32_t af[4][4];
#pragma unroll
            for (int mi = 0; mi < 4; mi++)
                ldsm_x4(af[mi][0], af[mi][1], af[mi][2], af[mi][3],
                        abuf + mi * (16 * HTS * 2) + kk * 32);
            uint32_t bf[4][2];
#pragma unroll
            for (int nip = 0; nip < 2; nip++) {
                uint32_t r0, r1, r2, r3;
                ldsm_x4(r0, r1, r2, r3, bbuf + nip * (16 * HTS * 2) + kk * 32);
                bf[2 * nip + 0][0] = r0; bf[2 * nip + 0][1] = r2;
                bf[2 * nip + 1][0] = r1; bf[2 * nip + 1][1] = r3;
            }
#pragma unroll
            for (int mi = 0; mi < 4; mi++)
#pragma unroll
                for (int ni = 0; ni < 4; ni++)
                    mma_f16(acc[mi][ni], af[mi], bf[ni]);
        }
        __syncthreads();
        if (tid == 0 && kt + NS < KT) {
            const int kn = kt + NS;
            MBAR_EXPECT_TX(mb + 8 * s, STG_BYTES);
            BULK_G2S(st0 + s * STG_BYTES,         Asrc + (size_t)kn * BLK_H, BLK_B, mb + 8 * s);
            BULK_G2S(st0 + s * STG_BYTES + BLK_B, Bsrc + (size_t)kn * BLK_H, BLK_B, mb + 8 * s);
        }
    }

#pragma unroll
    for (int mi = 0; mi < 4; mi++) {
#pragma unroll
        for (int q2 = 0; q2 < 2; q2++) {
            int row = wm * 64 + mi * 16 + q2 * 8 + g;
            if (token) {
                float bv = __ldg(bt2 + b * 128 + row);
#pragma unroll
                for (int ni = 0; ni < 4; ni++) {
                    int col = wn * 32 + ni * 8 + t * 2;   // token index
                    if (col < 64) {
                        g_tg[(size_t)col * G_DIM + b * 128 + row]       = acc[mi][ni][q2 * 2 + 0] + bv;
                        g_tg[(size_t)(col + 1) * G_DIM + b * 128 + row] = acc[mi][ni][q2 * 2 + 1] + bv;
                    }
                }
            } else if (mt == 0) {
                float bv = __ldg(bc2 + row);
#pragma unroll
                for (int ni = 0; ni < 4; ni++) {
                    int col = nt * 128 + wn * 32 + ni * 8 + t * 2;
                    float2 v;
                    v.x = acc[mi][ni][q2 * 2 + 0] + bv;
                    v.y = acc[mi][ni][q2 * 2 + 1] + bv;
                    *(float2*)(g_f + ((size_t)b * L_DIM + row) * N_TOK + col) = v;
                }
            } else if (row < 64) {
                float bv = __ldg(bs2 + row);
#pragma unroll
                for (int ni = 0; ni < 4; ni++) {
                    int col = nt * 128 + wn * 32 + ni * 8 + t * 2;
                    float2 v;
                    v.x = acc[mi][ni][q2 * 2 + 0] + bv;
                    v.y = acc[mi][ni][q2 * 2 + 1] + bv;
                    *(float2*)(g_s + ((size_t)b * M_CL + row) * N_TOK + col) = v;
                }
            }
        }
    }
}

// ==========================================================================
// Kernel 3c: token L2 norm -> out[b][0:256]
// ==========================================================================
__global__ __launch_bounds__(256) void k3c_norm(float* __restrict__ out)
{
    __shared__ float red[8];
    const int b   = blockIdx.x;
    const int tid = threadIdx.x;
    float val = g_tg[(size_t)b * G_DIM + tid];
    float ss = val * val;
#pragma unroll
    for (int off = 16; off; off >>= 1) ss += __shfl_xor_sync(0xffffffffu, ss, off);
    if ((tid & 31) == 0) red[tid >> 5] = ss;
    __syncthreads();
    float tot = 0.f;
#pragma unroll
    for (int i = 0; i < 8; i++) tot += red[i];
    float sc = 1.f / fmaxf(sqrtf(tot), 1e-12f);
    out[(size_t)b * OUT_PER_B + tid] = val * sc;
}

// ==========================================================================
// Kernel 4 (v2): Sinkhorn -> g_p
// ==========================================================================
__global__ __launch_bounds__(256) void k4_sinkhorn(const float* __restrict__ dustp)
{
    extern __shared__ float sh[];
    float* Ms = sh;
    float* u  = sh + 65 * 256;
    float* v  = u + 72;

    const int b   = blockIdx.x;
    const int tid = threadIdx.x;
    const float dust = *dustp;
    const float* S = g_s + (size_t)b * M_CL * N_TOK;

    for (int i = tid; i < 64 * 256; i += 256) Ms[i] = S[i];
    Ms[64 * 256 + tid] = dust;
    v[tid] = 0.f;
    __syncthreads();

    const int w    = tid >> 5;
    const int lane = tid & 31;

    for (int it = 0; it < 3; it++) {
        for (int r = w; r < 65; r += 8) {
            float vals[8];
            float mx = -INFINITY;
#pragma unroll
            for (int q = 0; q < 8; q++) {
                float vv = Ms[r * 256 + lane + 32 * q] + v[lane + 32 * q];
                vals[q] = vv;
                mx = fmaxf(mx, vv);
            }
#pragma unroll
            for (int off = 16; off; off >>= 1)
                mx = fmaxf(mx, __shfl_xor_sync(0xffffffffu, mx, off));
            float ssum = 0.f;
#pragma unroll
            for (int q = 0; q < 8; q++) ssum += expf(vals[q] - mx);
#pragma unroll
            for (int off = 16; off; off >>= 1)
                ssum += __shfl_xor_sync(0xffffffffu, ssum, off);
            if (lane == 0) {
                float la = (r == 64) ? LOGA_LAST : NEG_LOG320;
                u[r] = la - (mx + logf(ssum));
            }
        }
        __syncthreads();
        {
            float m0 = -INFINITY, m1 = -INFINITY, m2 = -INFINITY, m3 = -INFINITY;
#pragma unroll
            for (int m = 0; m < 64; m += 4) {
                m0 = fmaxf(m0, Ms[(m + 0) * 256 + tid] + u[m + 0]);
                m1 = fmaxf(m1, Ms[(m + 1) * 256 + tid] + u[m + 1]);
                m2 = fmaxf(m2, Ms[(m + 2) * 256 + tid] + u[m + 2]);
                m3 = fmaxf(m3, Ms[(m + 3) * 256 + tid] + u[m + 3]);
            }
            float mx = fmaxf(fmaxf(m0, m1), fmaxf(m2, m3));
            mx = fmaxf(mx, Ms[64 * 256 + tid] + u[64]);
            float s0 = 0.f, s1 = 0.f, s2 = 0.f, s3 = 0.f;
#pragma unroll
            for (int m = 0; m < 64; m += 4) {
                s0 += expf(Ms[(m + 0) * 256 + tid] + u[m + 0] - mx);
                s1 += expf(Ms[(m + 1) * 256 + tid] + u[m + 1] - mx);
                s2 += expf(Ms[(m + 2) * 256 + tid] + u[m + 2] - mx);
                s3 += expf(Ms[(m + 3) * 256 + tid] + u[m + 3] - mx);
            }
            float s = (s0 + s1) + (s2 + s3) + expf(Ms[64 * 256 + tid] + u[64] - mx);
            v[tid] = NEG_LOG320 - (mx + logf(s));
        }
        __syncthreads();
    }

    float* P = g_p + (size_t)b * M_CL * N_TOK;
    for (int i = tid; i < 64 * 256; i += 256) {
        int m = i >> 8, j = i & 255;
        P[i] = expf(Ms[i] + u[m] + v[j] - NEG_LOG320);
    }
}

// ==========================================================================
// Kernel 5: VLAD + intra-norm
// ==========================================================================
#define PS_LD 260
__global__ __launch_bounds__(256) void k5_vlad(float* __restrict__ out)
{
    extern __shared__ float sh[];
    float* ps  = sh;
    float* vs  = sh + 64 * PS_LD;
    float* inv = vs + 128 * 64;

    const int b   = blockIdx.x;
    const int tid = threadIdx.x;
    const float* P = g_p + (size_t)b * M_CL * N_TOK;
    const float* F = g_f + (size_t)b * L_DIM * N_TOK;

    for (int i = tid; i < 64 * 256; i += 256) {
        int m = i >> 8, n = i & 255;
        ps[m * PS_LD + n] = P[i];
    }
    __syncthreads();

    const int m  = tid & 63;
    const int lg = tid >> 6;

    const float4* pr = (const float4*)(ps + m * PS_LD);

    float acc[32];
#pragma unroll
    for (int i = 0; i < 32; i++) acc[i] = 0.f;

    for (int nc = 0; nc < 64; nc += 4) {
        float4 pv0 = pr[nc + 0], pv1 = pr[nc + 1], pv2 = pr[nc + 2], pv3 = pr[nc + 3];
#pragma unroll
        for (int li = 0; li < 32; li++) {
            const float4* fr = (const float4*)(F + (size_t)(lg * 32 + li) * N_TOK);
            float4 f0 = fr[nc + 0], f1 = fr[nc + 1], f2 = fr[nc + 2], f3 = fr[nc + 3];
            float a = acc[li];
            a += f0.x * pv0.x + f0.y * pv0.y + f0.z * pv0.z + f0.w * pv0.w;
            a += f1.x * pv1.x + f1.y * pv1.y + f1.z * pv1.z + f1.w * pv1.w;
            a += f2.x * pv2.x + f2.y * pv2.y + f2.z * pv2.z + f2.w * pv2.w;
            a += f3.x * pv3.x + f3.y * pv3.y + f3.z * pv3.z + f3.w * pv3.w;
            acc[li] = a;
        }
    }
#pragma unroll
    for (int li = 0; li < 32; li++) vs[(lg * 32 + li) * 64 + m] = acc[li];
    __syncthreads();

    if (tid < 64) {
        float ss = 0.f;
        for (int l = 0; l < 128; l++) {
            float vv = vs[l * 64 + tid];
            ss += vv * vv;
        }
        inv[tid] = 1.f / fmaxf(sqrtf(ss), 1e-12f);
    }
    __syncthreads();

    float* Ob = out + (size_t)b * OUT_PER_B + G_DIM;
    for (int i = tid; i < L_DIM * M_CL; i += 256) Ob[i] = vs[i] * inv[i & 63];
}

// ==========================================================================
// Kernel 6: final L2 norm
// ==========================================================================
__global__ __launch_bounds__(256) void k6_norm(float* __restrict__ out)
{
    __shared__ float red[8];
    __shared__ float sc_s;
    const int b   = blockIdx.x;
    const int tid = threadIdx.x;
    float* O = out + (size_t)b * OUT_PER_B;

    float ss = 0.f;
    for (int i = tid; i < OUT_PER_B; i += 256) {
        float vv = O[i];
        ss += vv * vv;
    }
#pragma unroll
    for (int off = 16; off; off >>= 1) ss += __shfl_xor_sync(0xffffffffu, ss, off);
    if ((tid & 31) == 0) red[tid >> 5] = ss;
    __syncthreads();
    if (tid == 0) {
        float tot = 0.f;
#pragma unroll
        for (int i = 0; i < 8; i++) tot += red[i];
        sc_s = 1.f / fmaxf(sqrtf(tot), 1e-12f);
    }
    __syncthreads();
    float sc = sc_s;
    for (int i = tid; i < OUT_PER_B; i += 256) O[i] *= sc;
}

// ==========================================================================
// launch
// ==========================================================================
extern "C" void kernel_launch(void* const* d_in, const int* in_sizes, int n_in,
                              void* d_out, int out_size)
{
    (void)in_sizes; (void)n_in; (void)out_size;
    const float* x    = (const float*)d_in[0];
    const float* t    = (const float*)d_in[1];
    const float* Wt1  = (const float*)d_in[2];
    const float* bt1  = (const float*)d_in[3];
    const float* Wt2  = (const float*)d_in[4];
    const float* bt2  = (const float*)d_in[5];
    const float* Wc1  = (const float*)d_in[6];
    const float* bc1  = (const float*)d_in[7];
    const float* Wc2  = (const float*)d_in[8];
    const float* bc2  = (const float*)d_in[9];
    const float* Ws1  = (const float*)d_in[10];
    const float* bs1  = (const float*)d_in[11];
    const float* Ws2  = (const float*)d_in[12];
    const float* bs2  = (const float*)d_in[13];
    const float* dust = (const float*)d_in[14];
    float* out = (float*)d_out;

    const int sink_smem = (65 * 256 + 72 + 256) * (int)sizeof(float);
    const int vlad_smem = (64 * PS_LD + 128 * 64 + 64) * (int)sizeof(float);
    cudaFuncSetAttribute(k1_mma,      cudaFuncAttributeMaxDynamicSharedMemorySize, GEMM_SMEM);
    cudaFuncSetAttribute(k2_mma,      cudaFuncAttributeMaxDynamicSharedMemorySize, GEMM_SMEM);
    cudaFuncSetAttribute(k4_sinkhorn, cudaFuncAttributeMaxDynamicSharedMemorySize, sink_smem);
    cudaFuncSetAttribute(k5_vlad,     cudaFuncAttributeMaxDynamicSharedMemorySize, vlad_smem);

    p_weights<<<512, 256>>>(Wc1, Ws1, Wc2, Ws2, Wt1, Wt2, t);        // idx 0
    p_xt<<<dim3(48, 8, B_SZ), 256>>>(x);                             // idx 1
    k1_mma<<<dim3(2, 9, B_SZ), 256, GEMM_SMEM>>>(bc1, bs1, bt1);     // idx 2
    k2_mma<<<dim3(2, 3, B_SZ), 256, GEMM_SMEM>>>(bc2, bs2, bt2);     // idx 3 (ncu)
    k4_sinkhorn<<<B_SZ, 256, sink_smem>>>(dust);                     // idx 4
    k5_vlad<<<B_SZ, 256, vlad_smem>>>(out);                          // idx 5
    k3c_norm<<<B_SZ, 256>>>(out);                                    // idx 6
    k6_norm<<<B_SZ, 256>>>(out);                                     // idx 7
}

// round 11
// speedup vs baseline: 6.9405x; 1.1191x over previous
#include <cuda_runtime.h>
#include <cuda_fp16.h>
#include <math.h>
#include <stdint.h>

// ---------------- problem constants ----------------
#define B_SZ   64
#define C_DIM  1536
#define N_TOK  256
#define HIDD   512
#define L_DIM  128
#define G_DIM  256
#define M_CL   64
#define OUT_PER_B (G_DIM + L_DIM * M_CL)   // 8448

#define NEG_LOG320 (-5.768320995793772f)
#define LOGA_LAST  (-0.510825623765991f)

// blocked tile: 128 rows x 40 halves (32 data + 8 pad) = 5120 halves = 10240 B
#define BLK_H   5120
#define BLK_B   10240

// ---------------- scratch (blocked, pre-padded layouts) ----------------
__device__ __half g_xb  [B_SZ * 2 * 48 * BLK_H];  // x^T blocked
__device__ __half g_hb  [B_SZ * 2 * 32 * BLK_H];  // hidden blocked
__device__ __half g_w1b [8 * 48 * BLK_H];         // [Wc1;Ws1] blocked
__device__ __half g_w2b [2 * 16 * BLK_H];         // [Wc2;Ws2pad] blocked
__device__ __half g_wt1b[4 * 48 * BLK_H];         // Wt1 blocked
__device__ __half g_wt2b[2 * 16 * BLK_H];         // Wt2 blocked
__device__ __half g_tb  [48 * BLK_H];             // tokens t blocked (rows 64-127 zero)
__device__ __half g_thb [16 * BLK_H];             // token hidden blocked
__device__ float  g_tg[B_SZ * G_DIM];             // token logits [tok][256]
__device__ float  g_f[B_SZ * L_DIM * N_TOK];
__device__ float  g_s[B_SZ * M_CL * N_TOK];

// ---------------- helpers ----------------
__device__ __forceinline__ void ldsm_x4(uint32_t& r0, uint32_t& r1, uint32_t& r2, uint32_t& r3,
                                        uint32_t addr) {
    asm volatile("ldmatrix.sync.aligned.m8n8.x4.shared.b16 {%0,%1,%2,%3}, [%4];"
        : "=r"(r0), "=r"(r1), "=r"(r2), "=r"(r3) : "r"(addr));
}

__device__ __forceinline__ void mma_f16(float* d, const uint32_t* a, const uint32_t* b) {
    asm volatile(
        "mma.sync.aligned.m16n8k16.row.col.f32.f16.f16.f32 "
        "{%0,%1,%2,%3}, {%4,%5,%6,%7}, {%8,%9}, {%0,%1,%2,%3};"
        : "+f"(d[0]), "+f"(d[1]), "+f"(d[2]), "+f"(d[3])
        : "r"(a[0]), "r"(a[1]), "r"(a[2]), "r"(a[3]), "r"(b[0]), "r"(b[1]));
}

#define MBAR_INIT(mbar, cnt) \
    asm volatile("mbarrier.init.shared.b64 [%0], %1;" :: "r"(mbar), "r"((uint32_t)(cnt)) : "memory")
#define MBAR_EXPECT_TX(mbar, bytes) \
    asm volatile("mbarrier.arrive.expect_tx.shared.b64 _, [%0], %1;" \
                 :: "r"(mbar), "r"((uint32_t)(bytes)) : "memory")
#define BULK_G2S(dst_smem, gsrc, bytes, mbar) \
    asm volatile("cp.async.bulk.shared::cta.global.mbarrier::complete_tx::bytes [%0], [%1], %2, [%3];" \
                 :: "r"(dst_smem), "l"(gsrc), "r"((uint32_t)(bytes)), "r"(mbar) : "memory")

__device__ __forceinline__ void mbar_wait(uint32_t mbar, uint32_t parity) {
    asm volatile(
        "{\n\t.reg .pred P1;\n\t"
        "WAIT_LOOP_%=:\n\t"
        "mbarrier.try_wait.parity.acquire.cta.shared::cta.b64 P1, [%0], %1, 0x989680;\n\t"
        "@P1 bra.uni WAIT_DONE_%=;\n\t"
        "bra.uni WAIT_LOOP_%=;\n\t"
        "WAIT_DONE_%=:\n\t}"
        :: "r"(mbar), "r"(parity) : "memory");
}

#define HTS       40
#define NS        4
#define STG_BYTES (2 * BLK_B)               // 20480
#define GEMM_SMEM (1024 + NS * STG_BYTES)   // 82944 B

// ==========================================================================
// Merged prepass: blocks [0, 24576) transpose x; blocks [24576, 25088)
// blockify all weights + token vector (grid-stride).
// ==========================================================================
#define XT_BLOCKS (48 * 8 * B_SZ)   // 24576
#define PW_BLOCKS 512

__global__ __launch_bounds__(256) void p_prep(
    const float* __restrict__ x,
    const float* __restrict__ Wc1, const float* __restrict__ Ws1,
    const float* __restrict__ Wc2, const float* __restrict__ Ws2,
    const float* __restrict__ Wt1, const float* __restrict__ Wt2,
    const float* __restrict__ t)
{
    __shared__ float sm[32][33];
    const int blk = blockIdx.x;
    const int tid = threadIdx.x;

    if (blk < XT_BLOCKS) {
        // ---- x transpose tile ----
        const int b   = blk / 384;
        const int rem = blk - b * 384;
        const int ct  = (rem >> 3) * 32;   // 48 c-tiles
        const int nt  = (rem & 7) * 32;    // 8 n-tiles
        const int tx = tid & 31;
        const int ty = tid >> 5;

#pragma unroll
        for (int i = 0; i < 4; i++) {
            int c = ct + ty + i * 8;
            sm[ty + i * 8][tx] = x[((size_t)b * C_DIM + c) * N_TOK + nt + tx];
        }
        __syncthreads();
        const int kt = ct >> 5;
#pragma unroll
        for (int i = 0; i < 4; i++) {
            int n = nt + ty + i * 8;
            size_t dst = (size_t)(((b * 2) + (n >> 7)) * 48 + kt) * BLK_H
                       + (n & 127) * HTS + tx;
            g_xb[dst] = __float2half_rn(sm[tx][ty + i * 8]);
        }
    } else {
        // ---- weights + token blockify ----
        const int n1 = 1024 * C_DIM;
        const int n2 = 256 * HIDD;
        const int n3 = 512 * C_DIM;
        const int n4 = 256 * HIDD;
        const int n5 = B_SZ * C_DIM;
        const int total = n1 + n2 + n3 + n4 + n5;
        const int wb = blk - XT_BLOCKS;
        for (int idx = wb * 256 + tid; idx < total; idx += PW_BLOCKS * 256) {
            if (idx < n1) {
                int o = idx / C_DIM, k = idx - o * C_DIM;
                float v = (o < 512) ? Wc1[idx] : Ws1[idx - 512 * C_DIM];
                g_w1b[(size_t)((o >> 7) * 48 + (k >> 5)) * BLK_H + (o & 127) * HTS + (k & 31)]
                    = __float2half_rn(v);
            } else if (idx < n1 + n2) {
                int j = idx - n1;
                int o = j >> 9, k = j & 511;
                float v = (o < 128) ? Wc2[j]
                        : (o < 192) ? Ws2[j - 128 * HIDD] : 0.f;
                g_w2b[(size_t)((o >> 7) * 16 + (k >> 5)) * BLK_H + (o & 127) * HTS + (k & 31)]
                    = __float2half_rn(v);
            } else if (idx < n1 + n2 + n3) {
                int j = idx - n1 - n2;
                int o = j / C_DIM, k = j - o * C_DIM;
                g_wt1b[(size_t)((o >> 7) * 48 + (k >> 5)) * BLK_H + (o & 127) * HTS + (k & 31)]
                    = __float2half_rn(Wt1[j]);
            } else if (idx < n1 + n2 + n3 + n4) {
                int j = idx - n1 - n2 - n3;
                int o = j >> 9, k = j & 511;
                g_wt2b[(size_t)((o >> 7) * 16 + (k >> 5)) * BLK_H + (o & 127) * HTS + (k & 31)]
                    = __float2half_rn(Wt2[j]);
            } else {
                int j = idx - n1 - n2 - n3 - n4;
                int r = j / C_DIM, k = j - r * C_DIM;   // r < 64
                g_tb[(size_t)(k >> 5) * BLK_H + r * HTS + (k & 31)] = __float2half_rn(t[j]);
            }
        }
    }
}

// ==========================================================================
// Kernel 1: h = relu(x^T W1^T + b1) (mt 0..7) + token layer1 (mt==8, 4 CTAs)
// grid (2, 9, 64)
// ==========================================================================
__global__ __launch_bounds__(256, 2) void k1_mma(
    const float* __restrict__ bc1, const float* __restrict__ bs1,
    const float* __restrict__ bt1)
{
    const int b  = blockIdx.z;
    const int mt = blockIdx.y;
    const int nt = blockIdx.x;

    const bool token = (mt == 8);
    if (token && (nt != 0 || b >= 4)) return;

    extern __shared__ __half smh[];
    const uint32_t sbase = (uint32_t)__cvta_generic_to_shared(smh);
    const uint32_t mb    = sbase;
    const uint32_t st0   = sbase + 1024;

    const __half* Asrc;
    const __half* Bsrc;
    const float*  bias;
    __half*       Odst;
    if (token) {
        Asrc = g_tb;
        Bsrc = g_wt1b + (size_t)(b * 48) * BLK_H;
        bias = bt1 + b * 128;
        Odst = g_thb + (size_t)(b * 4) * BLK_H;
    } else {
        Asrc = g_xb  + (size_t)((b * 2 + nt) * 48) * BLK_H;
        Bsrc = g_w1b + (size_t)(mt * 48) * BLK_H;
        bias = (mt < 4) ? (bc1 + mt * 128) : (bs1 + (mt - 4) * 128);
        Odst = g_hb + (size_t)((b * 2 + nt) * 32 + mt * 4) * BLK_H;
    }

    const int tid  = threadIdx.x;
    const int warp = tid >> 5, lane = tid & 31;
    const int g = lane >> 2, t = lane & 3;
    const int wm = warp >> 2, wn = warp & 3;

    const int lrow = lane & 15;
    const int lcol = (lane >> 4) * 8;

    const uint32_t a_base = st0 + (uint32_t)((wm * 64 + lrow) * HTS + lcol) * 2u;
    const uint32_t b_base = st0 + BLK_B + (uint32_t)((wn * 32 + lrow) * HTS + lcol) * 2u;

    if (tid == 0) {
#pragma unroll
        for (int s = 0; s < NS; s++) MBAR_INIT(mb + 8 * s, 1);
    }
    __syncthreads();
    if (tid == 0) {
#pragma unroll
        for (int s = 0; s < NS; s++) {
            MBAR_EXPECT_TX(mb + 8 * s, STG_BYTES);
            BULK_G2S(st0 + s * STG_BYTES,         Asrc + (size_t)s * BLK_H, BLK_B, mb + 8 * s);
            BULK_G2S(st0 + s * STG_BYTES + BLK_B, Bsrc + (size_t)s * BLK_H, BLK_B, mb + 8 * s);
        }
    }

    float acc[4][4][4];
#pragma unroll
    for (int i = 0; i < 4; i++)
#pragma unroll
        for (int j = 0; j < 4; j++)
#pragma unroll
            for (int q = 0; q < 4; q++) acc[i][j][q] = 0.f;

    const int KT = C_DIM / 32;   // 48
    for (int kt = 0; kt < KT; kt++) {
        const int s = kt & (NS - 1);
        const uint32_t parity = (kt >> 2) & 1;
        mbar_wait(mb + 8 * s, parity);

        const uint32_t abuf = a_base + s * STG_BYTES;
        const uint32_t bbuf = b_base + s * STG_BYTES;

#pragma unroll
        for (int kk = 0; kk < 2; kk++) {
            uint32_t af[4][4];
#pragma unroll
            for (int mi = 0; mi < 4; mi++)
                ldsm_x4(af[mi][0], af[mi][1], af[mi][2], af[mi][3],
                        abuf + mi * (16 * HTS * 2) + kk * 32);
            uint32_t bf[4][2];
#pragma unroll
            for (int nip = 0; nip < 2; nip++) {
                uint32_t r0, r1, r2, r3;
                ldsm_x4(r0, r1, r2, r3, bbuf + nip * (16 * HTS * 2) + kk * 32);
                bf[2 * nip + 0][0] = r0; bf[2 * nip + 0][1] = r2;
                bf[2 * nip + 1][0] = r1; bf[2 * nip + 1][1] = r3;
            }
#pragma unroll
            for (int mi = 0; mi < 4; mi++)
#pragma unroll
                for (int ni = 0; ni < 4; ni++)
                    mma_f16(acc[mi][ni], af[mi], bf[ni]);
        }
        __syncthreads();
        if (tid == 0 && kt + NS < KT) {
            const int kn = kt + NS;
            MBAR_EXPECT_TX(mb + 8 * s, STG_BYTES);
            BULK_G2S(st0 + s * STG_BYTES,         Asrc + (size_t)kn * BLK_H, BLK_B, mb + 8 * s);
            BULK_G2S(st0 + s * STG_BYTES + BLK_B, Bsrc + (size_t)kn * BLK_H, BLK_B, mb + 8 * s);
        }
    }

    float bvv[4][2];
#pragma unroll
    for (int ni = 0; ni < 4; ni++) {
        int col = wn * 32 + ni * 8 + t * 2;
        bvv[ni][0] = __ldg(bias + col);
        bvv[ni][1] = __ldg(bias + col + 1);
    }
    __half* Ob = Odst + (size_t)wn * BLK_H;
#pragma unroll
    for (int mi = 0; mi < 4; mi++) {
#pragma unroll
        for (int q2 = 0; q2 < 2; q2++) {
            int row = wm * 64 + mi * 16 + q2 * 8 + g;
#pragma unroll
            for (int ni = 0; ni < 4; ni++) {
                int c = ni * 8 + t * 2;
                __half2 hv = __floats2half2_rn(
                    fmaxf(acc[mi][ni][q2 * 2 + 0] + bvv[ni][0], 0.f),
                    fmaxf(acc[mi][ni][q2 * 2 + 1] + bvv[ni][1], 0.f));
                *(__half2*)(Ob + row * HTS + c) = hv;
            }
        }
    }
}

// ==========================================================================
// Kernel 2: f/s second layers (mt 0..1) + token layer2 (mt==2, 2 CTAs)
// grid (2, 3, 64)
// ==========================================================================
__global__ __launch_bounds__(256, 2) void k2_mma(
    const float* __restrict__ bc2, const float* __restrict__ bs2,
    const float* __restrict__ bt2)
{
    const int b  = blockIdx.z;
    const int mt = blockIdx.y;
    const int nt = blockIdx.x;

    const bool token = (mt == 2);
    if (token && (nt != 0 || b >= 2)) return;

    extern __shared__ __half smh[];
    const uint32_t sbase = (uint32_t)__cvta_generic_to_shared(smh);
    const uint32_t mb    = sbase;
    const uint32_t st0   = sbase + 1024;

    const __half* Asrc;
    const __half* Bsrc;
    if (token) {
        Asrc = g_wt2b + (size_t)(b * 16) * BLK_H;
        Bsrc = g_thb;
    } else {
        Asrc = g_w2b + (size_t)(mt * 16) * BLK_H;
        Bsrc = g_hb  + (size_t)((b * 2 + nt) * 32 + mt * 16) * BLK_H;
    }

    const int tid  = threadIdx.x;
    const int warp = tid >> 5, lane = tid & 31;
    const int g = lane >> 2, t = lane & 3;
    const int wm = warp >> 2, wn = warp & 3;

    const int lrow = lane & 15;
    const int lcol = (lane >> 4) * 8;

    const uint32_t a_base = st0 + (uint32_t)((wm * 64 + lrow) * HTS + lcol) * 2u;
    const uint32_t b_base = st0 + BLK_B + (uint32_t)((wn * 32 + lrow) * HTS + lcol) * 2u;

    if (tid == 0) {
#pragma unroll
        for (int s = 0; s < NS; s++) MBAR_INIT(mb + 8 * s, 1);
    }
    __syncthreads();
    if (tid == 0) {
#pragma unroll
        for (int s = 0; s < NS; s++) {
            MBAR_EXPECT_TX(mb + 8 * s, STG_BYTES);
            BULK_G2S(st0 + s * STG_BYTES,         Asrc + (size_t)s * BLK_H, BLK_B, mb + 8 * s);
            BULK_G2S(st0 + s * STG_BYTES + BLK_B, Bsrc + (size_t)s * BLK_H, BLK_B, mb + 8 * s);
        }
    }

    float acc[4][4][4];
#pragma unroll
    for (int i = 0; i < 4; i++)
#pragma unroll
        for (int j = 0; j < 4; j++)
#pragma unroll
            for (int q = 0; q < 4; q++) acc[i][j][q] = 0.f;

    const int KT = HIDD / 32;   // 16
    for (int kt = 0; kt < KT; kt++) {
        const int s = kt & (NS - 1);
        const uint32_t parity = (kt >> 2) & 1;
        mbar_wait(mb + 8 * s, parity);

        const uint32_t abuf = a_base + s * STG_BYTES;
        const uint32_t bbuf = b_base + s * STG_BYTES;

#pragma unroll
        for (int kk = 0; kk < 2; kk++) {
            uint32_t af[4][4];
#pragma unroll
            for (int mi = 0; mi < 4; mi++)
                ldsm_x4(af[mi][0], af[mi][1], af[mi][2], af[mi][3],
                        abuf + mi * (16 * HTS * 2) + kk * 32);
            uint32_t bf[4][2];
#pragma unroll
            for (int nip = 0; nip < 2; nip++) {
                uint32_t r0, r1, r2, r3;
                ldsm_x4(r0, r1, r2, r3, bbuf + nip * (16 * HTS * 2) + kk * 32);
                bf[2 * nip + 0][0] = r0; bf[2 * nip + 0][1] = r2;
                bf[2 * nip + 1][0] = r1; bf[2 * nip + 1][1] = r3;
            }
#pragma unroll
            for (int mi = 0; mi < 4; mi++)
#pragma unroll
                for (int ni = 0; ni < 4; ni++)
                    mma_f16(acc[mi][ni], af[mi], bf[ni]);
        }
        __syncthreads();
        if (tid == 0 && kt + NS < KT) {
            const int kn = kt + NS;
            MBAR_EXPECT_TX(mb + 8 * s, STG_BYTES);
            BULK_G2S(st0 + s * STG_BYTES,         Asrc + (size_t)kn * BLK_H, BLK_B, mb + 8 * s);
            BULK_G2S(st0 + s * STG_BYTES + BLK_B, Bsrc + (size_t)kn * BLK_H, BLK_B, mb + 8 * s);
        }
    }

#pragma unroll
    for (int mi = 0; mi < 4; mi++) {
#pragma unroll
        for (int q2 = 0; q2 < 2; q2++) {
            int row = wm * 64 + mi * 16 + q2 * 8 + g;
            if (token) {
                float bv = __ldg(bt2 + b * 128 + row);
#pragma unroll
                for (int ni = 0; ni < 4; ni++) {
                    int col = wn * 32 + ni * 8 + t * 2;   // token index
                    if (col < 64) {
                        g_tg[(size_t)col * G_DIM + b * 128 + row]       = acc[mi][ni][q2 * 2 + 0] + bv;
                        g_tg[(size_t)(col + 1) * G_DIM + b * 128 + row] = acc[mi][ni][q2 * 2 + 1] + bv;
                    }
                }
            } else if (mt == 0) {
                float bv = __ldg(bc2 + row);
#pragma unroll
                for (int ni = 0; ni < 4; ni++) {
                    int col = nt * 128 + wn * 32 + ni * 8 + t * 2;
                    float2 v;
                    v.x = acc[mi][ni][q2 * 2 + 0] + bv;
                    v.y = acc[mi][ni][q2 * 2 + 1] + bv;
                    *(float2*)(g_f + ((size_t)b * L_DIM + row) * N_TOK + col) = v;
                }
            } else if (row < 64) {
                float bv = __ldg(bs2 + row);
#pragma unroll
                for (int ni = 0; ni < 4; ni++) {
                    int col = nt * 128 + wn * 32 + ni * 8 + t * 2;
                    float2 v;
                    v.x = acc[mi][ni][q2 * 2 + 0] + bv;
                    v.y = acc[mi][ni][q2 * 2 + 1] + bv;
                    *(float2*)(g_s + ((size_t)b * M_CL + row) * N_TOK + col) = v;
                }
            }
        }
    }
}

// ==========================================================================
// Fused tail: Sinkhorn + VLAD + intra-norm + token-norm + final norm.
// One block per batch; P never leaves smem. smem ~167 KB.
// ==========================================================================
#define PS_LD 260
#define TAIL_SMEM ((65 * 256 + 72 + 256 + 64 * PS_LD + 128 * 64 + 64 + 8) * 4)

__global__ __launch_bounds__(256) void k_tail(const float* __restrict__ dustp,
                                              float* __restrict__ out)
{
    extern __shared__ float sh[];
    float* Ms  = sh;                       // 65*256
    float* u   = Ms + 65 * 256;            // 72
    float* v   = u + 72;                   // 256
    float* ps  = v + 256;                  // 64*PS_LD
    float* vs  = ps + 64 * PS_LD;          // 128*64
    float* inv = vs + 128 * 64;            // 64
    float* red = inv + 64;                 // 8

    const int b   = blockIdx.x;
    const int tid = threadIdx.x;
    const int w    = tid >> 5;
    const int lane = tid & 31;
    const float dust = *dustp;
    const float* S = g_s + (size_t)b * M_CL * N_TOK;

    // ---- Sinkhorn (log domain, 3 iters) ----
    for (int i = tid; i < 64 * 256; i += 256) Ms[i] = S[i];
    Ms[64 * 256 + tid] = dust;
    v[tid] = 0.f;
    __syncthreads();

    for (int it = 0; it < 3; it++) {
        for (int r = w; r < 65; r += 8) {
            float vals[8];
            float mx = -INFINITY;
#pragma unroll
            for (int q = 0; q < 8; q++) {
                float vv = Ms[r * 256 + lane + 32 * q] + v[lane + 32 * q];
                vals[q] = vv;
                mx = fmaxf(mx, vv);
            }
#pragma unroll
            for (int off = 16; off; off >>= 1)
                mx = fmaxf(mx, __shfl_xor_sync(0xffffffffu, mx, off));
            float ssum = 0.f;
#pragma unroll
            for (int q = 0; q < 8; q++) ssum += expf(vals[q] - mx);
#pragma unroll
            for (int off = 16; off; off >>= 1)
                ssum += __shfl_xor_sync(0xffffffffu, ssum, off);
            if (lane == 0) {
                float la = (r == 64) ? LOGA_LAST : NEG_LOG320;
                u[r] = la - (mx + logf(ssum));
            }
        }
        __syncthreads();
        {
            float m0 = -INFINITY, m1 = -INFINITY, m2 = -INFINITY, m3 = -INFINITY;
#pragma unroll
            for (int m = 0; m < 64; m += 4) {
                m0 = fmaxf(m0, Ms[(m + 0) * 256 + tid] + u[m + 0]);
                m1 = fmaxf(m1, Ms[(m + 1) * 256 + tid] + u[m + 1]);
                m2 = fmaxf(m2, Ms[(m + 2) * 256 + tid] + u[m + 2]);
                m3 = fmaxf(m3, Ms[(m + 3) * 256 + tid] + u[m + 3]);
            }
            float mx = fmaxf(fmaxf(m0, m1), fmaxf(m2, m3));
            mx = fmaxf(mx, Ms[64 * 256 + tid] + u[64]);
            float s0 = 0.f, s1 = 0.f, s2 = 0.f, s3 = 0.f;
#pragma unroll
            for (int m = 0; m < 64; m += 4) {
                s0 += expf(Ms[(m + 0) * 256 + tid] + u[m + 0] - mx);
                s1 += expf(Ms[(m + 1) * 256 + tid] + u[m + 1] - mx);
                s2 += expf(Ms[(m + 2) * 256 + tid] + u[m + 2] - mx);
                s3 += expf(Ms[(m + 3) * 256 + tid] + u[m + 3] - mx);
            }
            float s = (s0 + s1) + (s2 + s3) + expf(Ms[64 * 256 + tid] + u[64] - mx);
            v[tid] = NEG_LOG320 - (mx + logf(s));
        }
        __syncthreads();
    }

    // ---- P (drop dustbin) straight into padded smem ----
    for (int i = tid; i < 64 * 256; i += 256) {
        int m = i >> 8, n = i & 255;
        ps[m * PS_LD + n] = expf(Ms[i] + u[m] + v[n] - NEG_LOG320);
    }
    __syncthreads();

    // ---- VLAD: vlad[l][m] = sum_n f[l][n] * p[m][n] ----
    const float* F = g_f + (size_t)b * L_DIM * N_TOK;
    const int m  = tid & 63;
    const int lg = tid >> 6;
    const float4* pr = (const float4*)(ps + m * PS_LD);

    float acc[32];
#pragma unroll
    for (int i = 0; i < 32; i++) acc[i] = 0.f;

    for (int nc = 0; nc < 64; nc += 4) {
        float4 pv0 = pr[nc + 0], pv1 = pr[nc + 1], pv2 = pr[nc + 2], pv3 = pr[nc + 3];
#pragma unroll
        for (int li = 0; li < 32; li++) {
            const float4* fr = (const float4*)(F + (size_t)(lg * 32 + li) * N_TOK);
            float4 f0 = fr[nc + 0], f1 = fr[nc + 1], f2 = fr[nc + 2], f3 = fr[nc + 3];
            float a = acc[li];
            a += f0.x * pv0.x + f0.y * pv0.y + f0.z * pv0.z + f0.w * pv0.w;
            a += f1.x * pv1.x + f1.y * pv1.y + f1.z * pv1.z + f1.w * pv1.w;
            a += f2.x * pv2.x + f2.y * pv2.y + f2.z * pv2.z + f2.w * pv2.w;
            a += f3.x * pv3.x + f3.y * pv3.y + f3.z * pv3.z + f3.w * pv3.w;
            acc[li] = a;
        }
    }
#pragma unroll
    for (int li = 0; li < 32; li++) vs[(lg * 32 + li) * 64 + m] = acc[li];
    __syncthreads();

    // intra-norm over l per cluster m
    if (tid < 64) {
        float ss = 0.f;
        for (int l = 0; l < 128; l++) {
            float vv = vs[l * 64 + tid];
            ss += vv * vv;
        }
        inv[tid] = 1.f / fmaxf(sqrtf(ss), 1e-12f);
    }
    __syncthreads();

    // ---- token L2 norm ----
    float tval = g_tg[(size_t)b * G_DIM + tid];
    float sst = tval * tval;
#pragma unroll
    for (int off = 16; off; off >>= 1) sst += __shfl_xor_sync(0xffffffffu, sst, off);
    if (lane == 0) red[w] = sst;
    __syncthreads();
    float ttot = 0.f;
#pragma unroll
    for (int i = 0; i < 8; i++) ttot += red[i];
    float tnorm = tval * (1.f / fmaxf(sqrtf(ttot), 1e-12f));
    __syncthreads();   // red reuse

    // ---- final whole-vector norm ----
    float ssf = tnorm * tnorm;   // each thread holds exactly one token element
    for (int i = tid; i < L_DIM * M_CL; i += 256) {
        float vv = vs[i] * inv[i & 63];
        ssf += vv * vv;
    }
#pragma unroll
    for (int off = 16; off; off >>= 1) ssf += __shfl_xor_sync(0xffffffffu, ssf, off);
    if (lane == 0) red[w] = ssf;
    __syncthreads();
    float tot = 0.f;
#pragma unroll
    for (int i = 0; i < 8; i++) tot += red[i];
    float sc = 1.f / fmaxf(sqrtf(tot), 1e-12f);

    // ---- write out ----
    float* O = out + (size_t)b * OUT_PER_B;
    O[tid] = tnorm * sc;
    for (int i = tid; i < L_DIM * M_CL; i += 256)
        O[G_DIM + i] = vs[i] * inv[i & 63] * sc;
}

// ==========================================================================
// launch — 4 kernels total
// ==========================================================================
extern "C" void kernel_launch(void* const* d_in, const int* in_sizes, int n_in,
                              void* d_out, int out_size)
{
    (void)in_sizes; (void)n_in; (void)out_size;
    const float* x    = (const float*)d_in[0];
    const float* t    = (const float*)d_in[1];
    const float* Wt1  = (const float*)d_in[2];
    const float* bt1  = (const float*)d_in[3];
    const float* Wt2  = (const float*)d_in[4];
    const float* bt2  = (const float*)d_in[5];
    const float* Wc1  = (const float*)d_in[6];
    const float* bc1  = (const float*)d_in[7];
    const float* Wc2  = (const float*)d_in[8];
    const float* bc2  = (const float*)d_in[9];
    const float* Ws1  = (const float*)d_in[10];
    const float* bs1  = (const float*)d_in[11];
    const float* Ws2  = (const float*)d_in[12];
    const float* bs2  = (const float*)d_in[13];
    const float* dust = (const float*)d_in[14];
    float* out = (float*)d_out;

    cudaFuncSetAttribute(k1_mma, cudaFuncAttributeMaxDynamicSharedMemorySize, GEMM_SMEM);
    cudaFuncSetAttribute(k2_mma, cudaFuncAttributeMaxDynamicSharedMemorySize, GEMM_SMEM);
    cudaFuncSetAttribute(k_tail, cudaFuncAttributeMaxDynamicSharedMemorySize, TAIL_SMEM);

    p_prep<<<XT_BLOCKS + PW_BLOCKS, 256>>>(x, Wc1, Ws1, Wc2, Ws2, Wt1, Wt2, t);  // idx 0
    k1_mma<<<dim3(2, 9, B_SZ), 256, GEMM_SMEM>>>(bc1, bs1, bt1);                  // idx 1
    k2_mma<<<dim3(2, 3, B_SZ), 256, GEMM_SMEM>>>(bc2, bs2, bt2);                  // idx 2
    k_tail<<<B_SZ, 256, TAIL_SMEM>>>(dust, out);                                  // idx 3 (ncu)
}